// round 1
// baseline (speedup 1.0000x reference)
#include <cuda_runtime.h>
#include <math.h>

#define SEQ 4096
#define DM  768
#define NH  12
#define DK  64
#define PAD 68                       // smem row pad (words) for attention tiles

// Scratch (allocation-free rule: __device__ globals)
__device__ float g_q[SEQ * DM];
__device__ float g_k[SEQ * DM];
__device__ float g_v[SEQ * DM];
__device__ float g_ctx[SEQ * DM];

// ---------------------------------------------------------------------------
// Tiled GEMM body: C[m][n] = (sum_k A[m][k] * W[n][k] + bias[n]) * scale
// Tile 64x64, BK=16, 256 threads, 4x4 micro-tile per thread.
// blockIdx.x -> n tile, blockIdx.y -> m tile. K = DM = 768.
// ---------------------------------------------------------------------------
__device__ __forceinline__ void gemm64(const float* __restrict__ A,
                                       const float* __restrict__ W,
                                       const float* __restrict__ bias,
                                       float* __restrict__ C,
                                       float scale)
{
    __shared__ float As[16][64];   // [k][m]
    __shared__ float Bs[16][64];   // [k][n]

    const int t  = threadIdx.x;
    const int tx = t & 15, ty = t >> 4;
    const int m0 = blockIdx.y * 64, n0 = blockIdx.x * 64;

    const int lrow = t >> 2;            // 0..63
    const int lk   = (t & 3) << 2;      // 0,4,8,12

    float acc[4][4] = {};

    for (int k0 = 0; k0 < DM; k0 += 16) {
        __syncthreads();
        {
            float4 av = *(const float4*)&A[(m0 + lrow) * DM + k0 + lk];
            float4 wv = *(const float4*)&W[(n0 + lrow) * DM + k0 + lk];
            As[lk + 0][lrow] = av.x; As[lk + 1][lrow] = av.y;
            As[lk + 2][lrow] = av.z; As[lk + 3][lrow] = av.w;
            Bs[lk + 0][lrow] = wv.x; Bs[lk + 1][lrow] = wv.y;
            Bs[lk + 2][lrow] = wv.z; Bs[lk + 3][lrow] = wv.w;
        }
        __syncthreads();

#pragma unroll
        for (int k = 0; k < 16; k++) {
            float4 a4 = *(const float4*)&As[k][ty << 2];
            float4 b4 = *(const float4*)&Bs[k][tx << 2];
            float a_[4] = {a4.x, a4.y, a4.z, a4.w};
            float b_[4] = {b4.x, b4.y, b4.z, b4.w};
#pragma unroll
            for (int i = 0; i < 4; i++)
#pragma unroll
                for (int j = 0; j < 4; j++)
                    acc[i][j] += a_[i] * b_[j];
        }
    }

    float4 bias4 = *(const float4*)&bias[n0 + (tx << 2)];
    float b_[4] = {bias4.x, bias4.y, bias4.z, bias4.w};
#pragma unroll
    for (int i = 0; i < 4; i++) {
        int m = m0 + (ty << 2) + i;
        float4 outv;
        outv.x = (acc[i][0] + b_[0]) * scale;
        outv.y = (acc[i][1] + b_[1]) * scale;
        outv.z = (acc[i][2] + b_[2]) * scale;
        outv.w = (acc[i][3] + b_[3]) * scale;
        *(float4*)&C[m * DM + n0 + (tx << 2)] = outv;
    }
}

// Fused QKV projection. grid = (12, 64, 3). 1/sqrt(d_k)=0.125 folded into Q.
__global__ __launch_bounds__(256) void qkv_proj(
    const float* __restrict__ x,
    const float* __restrict__ Wq, const float* __restrict__ bq,
    const float* __restrict__ Wk, const float* __restrict__ bk,
    const float* __restrict__ Wv, const float* __restrict__ bv)
{
    int w = blockIdx.z;
    if (w == 0)      gemm64(x, Wq, bq, g_q, 0.125f);
    else if (w == 1) gemm64(x, Wk, bk, g_k, 1.0f);
    else             gemm64(x, Wv, bv, g_v, 1.0f);
}

// Output projection. grid = (12, 64).
__global__ __launch_bounds__(256) void out_proj(
    const float* __restrict__ Wo, const float* __restrict__ bo,
    float* __restrict__ out)
{
    gemm64(g_ctx, Wo, bo, out, 1.0f);
}

// ---------------------------------------------------------------------------
// Flash attention (fp32, causal). One block per (q-tile of 64, head).
// Tiles: Qs[r][d], Kt[d][c] (transposed), Vs[c][dv], Ps[r][c]; all [64][PAD].
// 256 threads = 16x16, each thread owns a 4x4 micro-tile (rows ty*4+, cols tx*4+).
// Online softmax state (m, l) replicated across the 16 lanes sharing a row.
// ---------------------------------------------------------------------------
#define ATTN_SMEM (4 * 64 * PAD * 4)

__global__ __launch_bounds__(256) void attn_kernel()
{
    extern __shared__ float sm[];
    float* Qs = sm;                 // [64][PAD]   (r, d)
    float* Kt = sm + 64 * PAD;      // [64][PAD]   (d, c)
    float* Vs = sm + 2 * 64 * PAD;  // [64][PAD]   (c, dv)
    float* Ps = sm + 3 * 64 * PAD;  // [64][PAD]   (r, c)

    const int t  = threadIdx.x;
    const int tx = t & 15, ty = t >> 4;
    const int qb = blockIdx.x;      // query tile (0..63)
    const int h  = blockIdx.y;      // head (0..11)
    const int r0 = ty << 2;         // local rows r0..r0+3
    const int c0 = tx << 2;         // local cols c0..c0+3 (also dv for PV/out)

    // Load Q tile (already pre-scaled by 0.125)
    for (int idx = t; idx < 64 * 64; idx += 256) {
        int rr = idx >> 6, dd = idx & 63;
        Qs[rr * PAD + dd] = g_q[(qb * 64 + rr) * DM + h * DK + dd];
    }

    float o[4][4] = {};
    float m_[4] = {-1e30f, -1e30f, -1e30f, -1e30f};
    float l_[4] = {};

    for (int kb = 0; kb <= qb; kb++) {
        __syncthreads();   // protect Kt/Vs/Ps from previous iteration's readers
        for (int idx = t; idx < 64 * 64; idx += 256) {
            int cc = idx >> 6, dd = idx & 63;
            Kt[dd * PAD + cc] = g_k[(kb * 64 + cc) * DM + h * DK + dd];
            Vs[cc * PAD + dd] = g_v[(kb * 64 + cc) * DM + h * DK + dd];
        }
        __syncthreads();

        // S = Q * K^T   (scaled already via Q)
        float s_[4][4] = {};
#pragma unroll 8
        for (int d = 0; d < 64; d++) {
            float a0 = Qs[(r0 + 0) * PAD + d];
            float a1 = Qs[(r0 + 1) * PAD + d];
            float a2 = Qs[(r0 + 2) * PAD + d];
            float a3 = Qs[(r0 + 3) * PAD + d];
            float4 b4 = *(const float4*)&Kt[d * PAD + c0];
            s_[0][0] += a0 * b4.x; s_[0][1] += a0 * b4.y; s_[0][2] += a0 * b4.z; s_[0][3] += a0 * b4.w;
            s_[1][0] += a1 * b4.x; s_[1][1] += a1 * b4.y; s_[1][2] += a1 * b4.z; s_[1][3] += a1 * b4.w;
            s_[2][0] += a2 * b4.x; s_[2][1] += a2 * b4.y; s_[2][2] += a2 * b4.z; s_[2][3] += a2 * b4.w;
            s_[3][0] += a3 * b4.x; s_[3][1] += a3 * b4.y; s_[3][2] += a3 * b4.z; s_[3][3] += a3 * b4.w;
        }

        // causal mask on the diagonal tile
        if (kb == qb) {
#pragma unroll
            for (int i = 0; i < 4; i++)
#pragma unroll
                for (int j = 0; j < 4; j++)
                    if (c0 + j > r0 + i) s_[i][j] = -1e30f;
        }

        // online softmax (rows span 16 lanes; shfl within aligned 16-lane groups)
#pragma unroll
        for (int i = 0; i < 4; i++) {
            float rm = fmaxf(fmaxf(s_[i][0], s_[i][1]), fmaxf(s_[i][2], s_[i][3]));
            rm = fmaxf(rm, __shfl_xor_sync(0xffffffffu, rm, 1));
            rm = fmaxf(rm, __shfl_xor_sync(0xffffffffu, rm, 2));
            rm = fmaxf(rm, __shfl_xor_sync(0xffffffffu, rm, 4));
            rm = fmaxf(rm, __shfl_xor_sync(0xffffffffu, rm, 8));

            float mnew = fmaxf(m_[i], rm);
            float corr = __expf(m_[i] - mnew);   // first iter: exp(-huge) -> 0

            float p0 = __expf(s_[i][0] - mnew);
            float p1 = __expf(s_[i][1] - mnew);
            float p2 = __expf(s_[i][2] - mnew);
            float p3 = __expf(s_[i][3] - mnew);
            *(float4*)&Ps[(r0 + i) * PAD + c0] = make_float4(p0, p1, p2, p3);

            float rs = p0 + p1 + p2 + p3;
            rs += __shfl_xor_sync(0xffffffffu, rs, 1);
            rs += __shfl_xor_sync(0xffffffffu, rs, 2);
            rs += __shfl_xor_sync(0xffffffffu, rs, 4);
            rs += __shfl_xor_sync(0xffffffffu, rs, 8);

            l_[i] = l_[i] * corr + rs;
            m_[i] = mnew;
#pragma unroll
            for (int j = 0; j < 4; j++) o[i][j] *= corr;
        }

        __syncthreads();  // Ps visible to all before PV

        // O += P * V
#pragma unroll 8
        for (int c = 0; c < 64; c++) {
            float a0 = Ps[(r0 + 0) * PAD + c];
            float a1 = Ps[(r0 + 1) * PAD + c];
            float a2 = Ps[(r0 + 2) * PAD + c];
            float a3 = Ps[(r0 + 3) * PAD + c];
            float4 b4 = *(const float4*)&Vs[c * PAD + c0];
            o[0][0] += a0 * b4.x; o[0][1] += a0 * b4.y; o[0][2] += a0 * b4.z; o[0][3] += a0 * b4.w;
            o[1][0] += a1 * b4.x; o[1][1] += a1 * b4.y; o[1][2] += a1 * b4.z; o[1][3] += a1 * b4.w;
            o[2][0] += a2 * b4.x; o[2][1] += a2 * b4.y; o[2][2] += a2 * b4.z; o[2][3] += a2 * b4.w;
            o[3][0] += a3 * b4.x; o[3][1] += a3 * b4.y; o[3][2] += a3 * b4.z; o[3][3] += a3 * b4.w;
        }
    }

    // normalize and write ctx (layout [S, DM], head slice at columns h*64)
#pragma unroll
    for (int i = 0; i < 4; i++) {
        float inv = 1.0f / l_[i];
        float4 outv = make_float4(o[i][0] * inv, o[i][1] * inv,
                                  o[i][2] * inv, o[i][3] * inv);
        *(float4*)&g_ctx[(qb * 64 + r0 + i) * DM + h * DK + c0] = outv;
    }
}

// ---------------------------------------------------------------------------
extern "C" void kernel_launch(void* const* d_in, const int* in_sizes, int n_in,
                              void* d_out, int out_size)
{
    const float* x  = (const float*)d_in[0];
    const float* Wq = (const float*)d_in[1];
    const float* bq = (const float*)d_in[2];
    const float* Wk = (const float*)d_in[3];
    const float* bk = (const float*)d_in[4];
    const float* Wv = (const float*)d_in[5];
    const float* bv = (const float*)d_in[6];
    const float* Wo = (const float*)d_in[7];
    const float* bo = (const float*)d_in[8];
    float* out = (float*)d_out;

    cudaFuncSetAttribute(attn_kernel,
                         cudaFuncAttributeMaxDynamicSharedMemorySize, ATTN_SMEM);

    qkv_proj<<<dim3(DM / 64, SEQ / 64, 3), 256>>>(x, Wq, bq, Wk, bk, Wv, bv);
    attn_kernel<<<dim3(SEQ / 64, NH), 256, ATTN_SMEM>>>();
    out_proj<<<dim3(DM / 64, SEQ / 64), 256>>>(Wo, bo, out);
}

// round 3
// speedup vs baseline: 1.3062x; 1.3062x over previous
#include <cuda_runtime.h>
#include <math.h>
#include <stdint.h>

#define SEQ 4096
#define DM  768
#define NH  12
#define DK  64
#define PAD 68

#if defined(__CUDA_ARCH__) && (__CUDA_ARCH__ == 1030) && defined(__CUDA_ARCH_FEAT_SM103_ALL)
#define HAS_TC 1
#else
#define HAS_TC 0
#endif

// Scratch (allocation-free rule: __device__ globals)
__device__ float g_q[SEQ * DM];
__device__ float g_k[SEQ * DM];
__device__ float g_v[SEQ * DM];
__device__ float g_ctx[SEQ * DM];

// ============================================================================
// GEMM tile geometry (shared by TC path and fallback)
// ============================================================================
#define GTM 128
#define GTN 128
#define GKC 32
#define NCHUNK (DM / GKC)                 // 24
#define TILE_B (GTM * 128)                // 16384 B (128 rows x 128 B)
#define STAGE_B (4 * TILE_B)              // Ahi, Alo, Bhi, Blo
#define GEMM_SMEM (1024 + 1024 + 2 * STAGE_B)

#if HAS_TC
// ============================================================================
// PTX helpers (only compiled for sm_103a feature target)
// ============================================================================
__device__ __forceinline__ uint32_t smem_u32(const void* p) {
    uint32_t a;
    asm("{ .reg .u64 t; cvta.to.shared.u64 t, %1; cvt.u32.u64 %0, t; }"
        : "=r"(a) : "l"(p));
    return a;
}
__device__ __forceinline__ uint32_t elect_one() {
    uint32_t p;
    asm volatile("{ .reg .pred p; elect.sync _|p, 0xFFFFFFFF; selp.b32 %0, 1, 0, p; }" : "=r"(p));
    return p;
}
#define SW128(off) ((off) ^ (((off) >> 3) & 0x70))

#define MBAR_INIT(addr, cnt) \
    asm volatile("mbarrier.init.shared.b64 [%0], %1;" :: "r"(addr), "r"(cnt) : "memory")

#define MBAR_WAIT(addr, parity) do {                                           \
    asm volatile(                                                              \
        "{\n\t.reg .pred P1;\n\t"                                              \
        "WL_%=:\n\t"                                                           \
        "mbarrier.try_wait.parity.acquire.cta.shared::cta.b64 P1, [%0], %1, 0x989680;\n\t" \
        "@P1 bra.uni WD_%=;\n\t"                                               \
        "bra.uni WL_%=;\n\t"                                                   \
        "WD_%=:\n\t}"                                                          \
        :: "r"(addr), "r"(parity) : "memory");                                 \
} while (0)

#define TC_ALLOC(smem_addr, ncols) \
    asm volatile("tcgen05.alloc.cta_group::1.sync.aligned.shared::cta.b32 [%0], %1;" \
                 :: "r"(smem_addr), "r"(ncols) : "memory")
#define TC_DEALLOC(tmem, ncols) \
    asm volatile("tcgen05.dealloc.cta_group::1.sync.aligned.b32 %0, %1;" :: "r"(tmem), "r"(ncols))
#define TC_RELINQ() \
    asm volatile("tcgen05.relinquish_alloc_permit.cta_group::1.sync.aligned;")
#define TC_COMMIT(mbar) \
    asm volatile("tcgen05.commit.cta_group::1.mbarrier::arrive::one.shared::cluster.b64 [%0];" \
                 :: "r"(mbar) : "memory")
#define TC_FENCE_AFTER()  asm volatile("tcgen05.fence::after_thread_sync;" ::: "memory")
#define TC_FENCE_BEFORE() asm volatile("tcgen05.fence::before_thread_sync;" ::: "memory")
#define TC_WAIT_LD()      asm volatile("tcgen05.wait::ld.sync.aligned;" ::: "memory")
#define FENCE_ASYNC_SHARED() asm volatile("fence.proxy.async.shared::cta;" ::: "memory")

#define TC_LD_X32(r, tmem)                                                     \
    asm volatile(                                                              \
        "tcgen05.ld.sync.aligned.32x32b.x32.b32 "                              \
        "{%0, %1, %2, %3, %4, %5, %6, %7, "                                    \
        " %8, %9, %10, %11, %12, %13, %14, %15, "                              \
        " %16, %17, %18, %19, %20, %21, %22, %23, "                            \
        " %24, %25, %26, %27, %28, %29, %30, %31}, [%32];"                     \
        : "=r"((r)[0]),  "=r"((r)[1]),  "=r"((r)[2]),  "=r"((r)[3]),           \
          "=r"((r)[4]),  "=r"((r)[5]),  "=r"((r)[6]),  "=r"((r)[7]),           \
          "=r"((r)[8]),  "=r"((r)[9]),  "=r"((r)[10]), "=r"((r)[11]),          \
          "=r"((r)[12]), "=r"((r)[13]), "=r"((r)[14]), "=r"((r)[15]),          \
          "=r"((r)[16]), "=r"((r)[17]), "=r"((r)[18]), "=r"((r)[19]),          \
          "=r"((r)[20]), "=r"((r)[21]), "=r"((r)[22]), "=r"((r)[23]),          \
          "=r"((r)[24]), "=r"((r)[25]), "=r"((r)[26]), "=r"((r)[27]),          \
          "=r"((r)[28]), "=r"((r)[29]), "=r"((r)[30]), "=r"((r)[31])           \
        : "r"(tmem))

__device__ __forceinline__ uint64_t make_desc_sw128(uint32_t addr) {
    return ((uint64_t)2 << 61) | ((uint64_t)1 << 46) | ((uint64_t)64 << 32)
         | ((uint64_t)1 << 16) | (((uint64_t)(addr >> 4)) & 0x3FFF);
}

__device__ __forceinline__ void mma_tf32_ss(uint32_t d, uint64_t ad, uint64_t bd,
                                            uint32_t idesc, uint32_t en) {
    asm volatile(
        "{\n\t.reg .pred p;\n\tsetp.ne.u32 p, %4, 0;\n\t"
        "tcgen05.mma.cta_group::1.kind::tf32 [%0], %1, %2, %3, p;\n\t}"
        :: "r"(d), "l"(ad), "l"(bd), "r"(idesc), "r"(en) : "memory");
}

__device__ __forceinline__ float tf32_hi(float x) {
    uint32_t u;
    asm("cvt.rna.tf32.f32 %0, %1;" : "=r"(u) : "f"(x));
    return __uint_as_float(u);
}

// idesc: dtype F32=1 [4:5], atype TF32=2 [7:9], btype TF32=2 [10:12],
//        N>>3 [17:22], M>>4 [24:28]
#define IDESC_TF32 ((1u << 4) | (2u << 7) | (2u << 10) | ((GTN / 8) << 17) | ((GTM / 16) << 24))

__device__ __forceinline__ void load_split(const float* __restrict__ src,
                                           int row0, int k0,
                                           uint32_t hi_t, uint32_t lo_t, int t)
{
#pragma unroll
    for (int i = 0; i < 8; i++) {
        int idx = i * 128 + t;
        int r = idx >> 3, c4 = idx & 7;
        float4 v = *(const float4*)&src[(row0 + r) * DM + k0 + c4 * 4];
        float4 h, l;
        h.x = tf32_hi(v.x); l.x = v.x - h.x;
        h.y = tf32_hi(v.y); l.y = v.y - h.y;
        h.z = tf32_hi(v.z); l.z = v.z - h.z;
        h.w = tf32_hi(v.w); l.w = v.w - h.w;
        uint32_t off = SW128((uint32_t)(r * 128 + c4 * 16));
        asm volatile("st.shared.v4.b32 [%0], {%1,%2,%3,%4};" ::
            "r"(hi_t + off), "r"(__float_as_uint(h.x)), "r"(__float_as_uint(h.y)),
            "r"(__float_as_uint(h.z)), "r"(__float_as_uint(h.w)) : "memory");
        asm volatile("st.shared.v4.b32 [%0], {%1,%2,%3,%4};" ::
            "r"(lo_t + off), "r"(__float_as_uint(l.x)), "r"(__float_as_uint(l.y)),
            "r"(__float_as_uint(l.z)), "r"(__float_as_uint(l.w)) : "memory");
    }
}

__device__ __forceinline__ void gemm_body(const float* __restrict__ A,
                                          const float* __restrict__ W,
                                          const float* __restrict__ bias,
                                          float* __restrict__ C,
                                          float scale)
{
    extern __shared__ char smraw[];
    const uint32_t base = (smem_u32(smraw) + 1023) & ~1023u;
    const uint32_t mbar0 = base + 8, mbar1 = base + 16;
    const uint32_t tiles = base + 1024;

    const int t   = threadIdx.x;
    const int wid = t >> 5, lid = t & 31;
    const int m0  = blockIdx.y * GTM;
    const int n0  = blockIdx.x * GTN;

    if (wid == 0) {
        TC_ALLOC(base, 128);
        TC_RELINQ();
    }
    if (t == 0) {
        MBAR_INIT(mbar0, 1);
        MBAR_INIT(mbar1, 1);
    }
    __syncthreads();
    uint32_t tmem;
    asm volatile("ld.shared.b32 %0, [%1];" : "=r"(tmem) : "r"(base));

    int ph0 = 0, ph1 = 0;

    for (int c = 0; c < NCHUNK; c++) {
        const int s = c & 1;
        const uint32_t st = tiles + s * STAGE_B;
        const uint32_t aHi = st, aLo = st + TILE_B, bHi = st + 2 * TILE_B, bLo = st + 3 * TILE_B;

        if (c >= 2) {
            if (s == 0) { MBAR_WAIT(mbar0, ph0); ph0 ^= 1; }
            else        { MBAR_WAIT(mbar1, ph1); ph1 ^= 1; }
        }

        load_split(A, m0, c * GKC, aHi, aLo, t);
        load_split(W, n0, c * GKC, bHi, bLo, t);

        FENCE_ASYNC_SHARED();
        __syncthreads();

        if (wid == 0 && elect_one()) {
            uint64_t dA[2] = { make_desc_sw128(aHi), make_desc_sw128(aLo) };
            uint64_t dB[2] = { make_desc_sw128(bHi), make_desc_sw128(bLo) };
#pragma unroll
            for (int cb = 0; cb < 3; cb++) {
                uint64_t ad = dA[cb == 2 ? 1 : 0];
                uint64_t bd = dB[cb == 1 ? 1 : 0];
#pragma unroll
                for (int ks = 0; ks < 4; ks++) {
                    uint32_t en = !(c == 0 && cb == 0 && ks == 0);
                    mma_tf32_ss(tmem, ad + ks * 2, bd + ks * 2, IDESC_TF32, en);
                }
            }
            TC_COMMIT(s == 0 ? mbar0 : mbar1);
        }
    }

    MBAR_WAIT(mbar0, ph0);
    MBAR_WAIT(mbar1, ph1);
    TC_FENCE_AFTER();

    uint32_t dr[128];
    TC_LD_X32(dr +  0, tmem +  0);
    TC_LD_X32(dr + 32, tmem + 32);
    TC_LD_X32(dr + 64, tmem + 64);
    TC_LD_X32(dr + 96, tmem + 96);
    TC_WAIT_LD();
    TC_FENCE_BEFORE();

    const int m = m0 + wid * 32 + lid;
#pragma unroll
    for (int c4 = 0; c4 < 32; c4++) {
        int n = n0 + c4 * 4;
        float4 o;
        o.x = (__uint_as_float(dr[c4 * 4 + 0]) + bias[n + 0]) * scale;
        o.y = (__uint_as_float(dr[c4 * 4 + 1]) + bias[n + 1]) * scale;
        o.z = (__uint_as_float(dr[c4 * 4 + 2]) + bias[n + 2]) * scale;
        o.w = (__uint_as_float(dr[c4 * 4 + 3]) + bias[n + 3]) * scale;
        *(float4*)&C[m * DM + n] = o;
    }

    __syncthreads();
    if (wid == 0) TC_DEALLOC(tmem, 128);
}

#else  // !HAS_TC ------------------------------------------------------------
// Fallback SIMT body with identical launch geometry (128 threads, 128x128 tile).
// Correctness-preserving; only used if the non-feature cubin is ever selected.
__device__ __forceinline__ void gemm_body(const float* __restrict__ A,
                                          const float* __restrict__ W,
                                          const float* __restrict__ bias,
                                          float* __restrict__ C,
                                          float scale)
{
    extern __shared__ char smraw[];
    float* Ws = (float*)smraw;          // [GKC][128] chunk of W, k-major
    float* As = (float*)smraw + GKC * 128;  // [GKC][128]

    const int t  = threadIdx.x;
    const int m0 = blockIdx.y * GTM;
    const int n0 = blockIdx.x * GTN;

    // thread t: rows m0 + (t>>4)*16 + 0..15? Simpler: 8 rows x 16 cols micro.
    const int tr = (t >> 4) << 4;   // row group of 16 (8 groups)
    const int tc = (t & 15) << 3;   // col group of 8  (16 groups)

    float acc[16][8] = {};

    for (int k0 = 0; k0 < DM; k0 += GKC) {
        __syncthreads();
        for (int idx = t; idx < GKC * 128 / 4; idx += 128) {
            int r = (idx * 4) >> 5, k4 = (idx * 4) & 31;   // r: 0..127, k4 step 4
            float4 wv = *(const float4*)&W[(n0 + r) * DM + k0 + k4];
            Ws[(k4 + 0) * 128 + r] = wv.x; Ws[(k4 + 1) * 128 + r] = wv.y;
            Ws[(k4 + 2) * 128 + r] = wv.z; Ws[(k4 + 3) * 128 + r] = wv.w;
            float4 av = *(const float4*)&A[(m0 + r) * DM + k0 + k4];
            As[(k4 + 0) * 128 + r] = av.x; As[(k4 + 1) * 128 + r] = av.y;
            As[(k4 + 2) * 128 + r] = av.z; As[(k4 + 3) * 128 + r] = av.w;
        }
        __syncthreads();
        for (int k = 0; k < GKC; k++) {
            float a_[16], b_[8];
#pragma unroll
            for (int i = 0; i < 16; i++) a_[i] = As[k * 128 + tr + i];
#pragma unroll
            for (int j = 0; j < 8; j++)  b_[j] = Ws[k * 128 + tc + j];
#pragma unroll
            for (int i = 0; i < 16; i++)
#pragma unroll
                for (int j = 0; j < 8; j++) acc[i][j] += a_[i] * b_[j];
        }
    }
#pragma unroll
    for (int i = 0; i < 16; i++)
#pragma unroll
        for (int j = 0; j < 8; j++)
            C[(m0 + tr + i) * DM + n0 + tc + j] = (acc[i][j] + bias[n0 + tc + j]) * scale;
}
#endif  // HAS_TC

// Fused QKV projection: grid (6, 32, 3)
__global__ __launch_bounds__(128) void qkv_tc(
    const float* __restrict__ x,
    const float* __restrict__ Wq, const float* __restrict__ bq,
    const float* __restrict__ Wk, const float* __restrict__ bk,
    const float* __restrict__ Wv, const float* __restrict__ bv)
{
    int w = blockIdx.z;
    if (w == 0)      gemm_body(x, Wq, bq, g_q, 0.125f);
    else if (w == 1) gemm_body(x, Wk, bk, g_k, 1.0f);
    else             gemm_body(x, Wv, bv, g_v, 1.0f);
}

// Output projection: grid (6, 32)
__global__ __launch_bounds__(128) void out_tc(
    const float* __restrict__ Wo, const float* __restrict__ bo,
    float* __restrict__ out)
{
    gemm_body(g_ctx, Wo, bo, out, 1.0f);
}

// ============================================================================
// Flash attention (fp32 SIMT, causal) — unchanged from R1 (passing, 1e-6)
// ============================================================================
#define ATTN_SMEM (4 * 64 * PAD * 4)

__global__ __launch_bounds__(256) void attn_kernel()
{
    extern __shared__ float sm[];
    float* Qs = sm;
    float* Kt = sm + 64 * PAD;
    float* Vs = sm + 2 * 64 * PAD;
    float* Ps = sm + 3 * 64 * PAD;

    const int t  = threadIdx.x;
    const int tx = t & 15, ty = t >> 4;
    const int qb = blockIdx.x;
    const int h  = blockIdx.y;
    const int r0 = ty << 2;
    const int c0 = tx << 2;

    for (int idx = t; idx < 64 * 64; idx += 256) {
        int rr = idx >> 6, dd = idx & 63;
        Qs[rr * PAD + dd] = g_q[(qb * 64 + rr) * DM + h * DK + dd];
    }

    float o[4][4] = {};
    float m_[4] = {-1e30f, -1e30f, -1e30f, -1e30f};
    float l_[4] = {};

    for (int kb = 0; kb <= qb; kb++) {
        __syncthreads();
        for (int idx = t; idx < 64 * 64; idx += 256) {
            int cc = idx >> 6, dd = idx & 63;
            Kt[dd * PAD + cc] = g_k[(kb * 64 + cc) * DM + h * DK + dd];
            Vs[cc * PAD + dd] = g_v[(kb * 64 + cc) * DM + h * DK + dd];
        }
        __syncthreads();

        float s_[4][4] = {};
#pragma unroll 8
        for (int d = 0; d < 64; d++) {
            float a0 = Qs[(r0 + 0) * PAD + d];
            float a1 = Qs[(r0 + 1) * PAD + d];
            float a2 = Qs[(r0 + 2) * PAD + d];
            float a3 = Qs[(r0 + 3) * PAD + d];
            float4 b4 = *(const float4*)&Kt[d * PAD + c0];
            s_[0][0] += a0 * b4.x; s_[0][1] += a0 * b4.y; s_[0][2] += a0 * b4.z; s_[0][3] += a0 * b4.w;
            s_[1][0] += a1 * b4.x; s_[1][1] += a1 * b4.y; s_[1][2] += a1 * b4.z; s_[1][3] += a1 * b4.w;
            s_[2][0] += a2 * b4.x; s_[2][1] += a2 * b4.y; s_[2][2] += a2 * b4.z; s_[2][3] += a2 * b4.w;
            s_[3][0] += a3 * b4.x; s_[3][1] += a3 * b4.y; s_[3][2] += a3 * b4.z; s_[3][3] += a3 * b4.w;
        }

        if (kb == qb) {
#pragma unroll
            for (int i = 0; i < 4; i++)
#pragma unroll
                for (int j = 0; j < 4; j++)
                    if (c0 + j > r0 + i) s_[i][j] = -1e30f;
        }

#pragma unroll
        for (int i = 0; i < 4; i++) {
            float rm = fmaxf(fmaxf(s_[i][0], s_[i][1]), fmaxf(s_[i][2], s_[i][3]));
            rm = fmaxf(rm, __shfl_xor_sync(0xffffffffu, rm, 1));
            rm = fmaxf(rm, __shfl_xor_sync(0xffffffffu, rm, 2));
            rm = fmaxf(rm, __shfl_xor_sync(0xffffffffu, rm, 4));
            rm = fmaxf(rm, __shfl_xor_sync(0xffffffffu, rm, 8));

            float mnew = fmaxf(m_[i], rm);
            float corr = __expf(m_[i] - mnew);

            float p0 = __expf(s_[i][0] - mnew);
            float p1 = __expf(s_[i][1] - mnew);
            float p2 = __expf(s_[i][2] - mnew);
            float p3 = __expf(s_[i][3] - mnew);
            *(float4*)&Ps[(r0 + i) * PAD + c0] = make_float4(p0, p1, p2, p3);

            float rs = p0 + p1 + p2 + p3;
            rs += __shfl_xor_sync(0xffffffffu, rs, 1);
            rs += __shfl_xor_sync(0xffffffffu, rs, 2);
            rs += __shfl_xor_sync(0xffffffffu, rs, 4);
            rs += __shfl_xor_sync(0xffffffffu, rs, 8);

            l_[i] = l_[i] * corr + rs;
            m_[i] = mnew;
#pragma unroll
            for (int j = 0; j < 4; j++) o[i][j] *= corr;
        }

        __syncthreads();

#pragma unroll 8
        for (int c = 0; c < 64; c++) {
            float a0 = Ps[(r0 + 0) * PAD + c];
            float a1 = Ps[(r0 + 1) * PAD + c];
            float a2 = Ps[(r0 + 2) * PAD + c];
            float a3 = Ps[(r0 + 3) * PAD + c];
            float4 b4 = *(const float4*)&Vs[c * PAD + c0];
            o[0][0] += a0 * b4.x; o[0][1] += a0 * b4.y; o[0][2] += a0 * b4.z; o[0][3] += a0 * b4.w;
            o[1][0] += a1 * b4.x; o[1][1] += a1 * b4.y; o[1][2] += a1 * b4.z; o[1][3] += a1 * b4.w;
            o[2][0] += a2 * b4.x; o[2][1] += a2 * b4.y; o[2][2] += a2 * b4.z; o[2][3] += a2 * b4.w;
            o[3][0] += a3 * b4.x; o[3][1] += a3 * b4.y; o[3][2] += a3 * b4.z; o[3][3] += a3 * b4.w;
        }
    }

#pragma unroll
    for (int i = 0; i < 4; i++) {
        float inv = 1.0f / l_[i];
        float4 outv = make_float4(o[i][0] * inv, o[i][1] * inv,
                                  o[i][2] * inv, o[i][3] * inv);
        *(float4*)&g_ctx[(qb * 64 + r0 + i) * DM + h * DK + c0] = outv;
    }
}

// ---------------------------------------------------------------------------
extern "C" void kernel_launch(void* const* d_in, const int* in_sizes, int n_in,
                              void* d_out, int out_size)
{
    const float* x  = (const float*)d_in[0];
    const float* Wq = (const float*)d_in[1];
    const float* bq = (const float*)d_in[2];
    const float* Wk = (const float*)d_in[3];
    const float* bk = (const float*)d_in[4];
    const float* Wv = (const float*)d_in[5];
    const float* bv = (const float*)d_in[6];
    const float* Wo = (const float*)d_in[7];
    const float* bo = (const float*)d_in[8];
    float* out = (float*)d_out;

    cudaFuncSetAttribute(qkv_tc, cudaFuncAttributeMaxDynamicSharedMemorySize, GEMM_SMEM);
    cudaFuncSetAttribute(out_tc, cudaFuncAttributeMaxDynamicSharedMemorySize, GEMM_SMEM);
    cudaFuncSetAttribute(attn_kernel, cudaFuncAttributeMaxDynamicSharedMemorySize, ATTN_SMEM);

    qkv_tc<<<dim3(DM / GTN, SEQ / GTM, 3), 128, GEMM_SMEM>>>(x, Wq, bq, Wk, bk, Wv, bv);
    attn_kernel<<<dim3(SEQ / 64, NH), 256, ATTN_SMEM>>>();
    out_tc<<<dim3(DM / GTN, SEQ / GTM), 128, GEMM_SMEM>>>(Wo, bo, out);
}

// round 4
// speedup vs baseline: 2.2123x; 1.6937x over previous
#include <cuda_runtime.h>
#include <math.h>
#include <stdint.h>

#define SEQ 4096
#define DM  768
#define NH  12
#define DK  64

#if defined(__CUDA_ARCH__) && (__CUDA_ARCH__ == 1030) && defined(__CUDA_ARCH_FEAT_SM103_ALL)
#define HAS_TC 1
#else
#define HAS_TC 0
#endif

// Scratch (allocation-free rule: __device__ globals)
__device__ float g_q[SEQ * DM];
__device__ float g_k[SEQ * DM];
__device__ float g_v[SEQ * DM];
__device__ float g_ctx[SEQ * DM];

// ============================================================================
// GEMM tile geometry
// ============================================================================
#define GTM 128
#define GTN 128
#define GKC 32
#define NCHUNK (DM / GKC)                 // 24
#define TILE_B (GTM * 128)                // 16384 B
#define STAGE_B (4 * TILE_B)
#define GEMM_SMEM (1024 + 1024 + 2 * STAGE_B)

// Attention smem: slack + Q(64K) + K(64K) + Vt(64K)
#define ATT_SMEM (1024 + 3 * 65536)
// TMEM columns
#define TM_O  0
#define TM_S  64
#define TM_PH 192
#define TM_PL 320

#if HAS_TC
// ============================================================================
// PTX helpers (sm_103a feature target only)
// ============================================================================
__device__ __forceinline__ uint32_t smem_u32(const void* p) {
    uint32_t a;
    asm("{ .reg .u64 t; cvta.to.shared.u64 t, %1; cvt.u32.u64 %0, t; }"
        : "=r"(a) : "l"(p));
    return a;
}
__device__ __forceinline__ uint32_t elect_one() {
    uint32_t p;
    asm volatile("{ .reg .pred p; elect.sync _|p, 0xFFFFFFFF; selp.b32 %0, 1, 0, p; }" : "=r"(p));
    return p;
}
#define SW128(off) ((off) ^ (((off) >> 3) & 0x70))

#define MBAR_INIT(addr, cnt) \
    asm volatile("mbarrier.init.shared.b64 [%0], %1;" :: "r"(addr), "r"(cnt) : "memory")

#define MBAR_WAIT(addr, parity) do {                                           \
    asm volatile(                                                              \
        "{\n\t.reg .pred P1;\n\t"                                              \
        "WL_%=:\n\t"                                                           \
        "mbarrier.try_wait.parity.acquire.cta.shared::cta.b64 P1, [%0], %1, 0x989680;\n\t" \
        "@P1 bra.uni WD_%=;\n\t"                                               \
        "bra.uni WL_%=;\n\t"                                                   \
        "WD_%=:\n\t}"                                                          \
        :: "r"(addr), "r"(parity) : "memory");                                 \
} while (0)

#define TC_ALLOC(smem_addr, ncols) \
    asm volatile("tcgen05.alloc.cta_group::1.sync.aligned.shared::cta.b32 [%0], %1;" \
                 :: "r"(smem_addr), "r"(ncols) : "memory")
#define TC_DEALLOC(tmem, ncols) \
    asm volatile("tcgen05.dealloc.cta_group::1.sync.aligned.b32 %0, %1;" :: "r"(tmem), "r"(ncols))
#define TC_RELINQ() \
    asm volatile("tcgen05.relinquish_alloc_permit.cta_group::1.sync.aligned;")
#define TC_COMMIT(mbar) \
    asm volatile("tcgen05.commit.cta_group::1.mbarrier::arrive::one.shared::cluster.b64 [%0];" \
                 :: "r"(mbar) : "memory")
#define TC_FENCE_AFTER()  asm volatile("tcgen05.fence::after_thread_sync;" ::: "memory")
#define TC_FENCE_BEFORE() asm volatile("tcgen05.fence::before_thread_sync;" ::: "memory")
#define TC_WAIT_LD()      asm volatile("tcgen05.wait::ld.sync.aligned;" ::: "memory")
#define TC_WAIT_ST()      asm volatile("tcgen05.wait::st.sync.aligned;" ::: "memory")
#define FENCE_ASYNC_SHARED() asm volatile("fence.proxy.async.shared::cta;" ::: "memory")

#define TC_LD_X32(r, tmem)                                                     \
    asm volatile(                                                              \
        "tcgen05.ld.sync.aligned.32x32b.x32.b32 "                              \
        "{%0, %1, %2, %3, %4, %5, %6, %7, "                                    \
        " %8, %9, %10, %11, %12, %13, %14, %15, "                              \
        " %16, %17, %18, %19, %20, %21, %22, %23, "                            \
        " %24, %25, %26, %27, %28, %29, %30, %31}, [%32];"                     \
        : "=r"((r)[0]),  "=r"((r)[1]),  "=r"((r)[2]),  "=r"((r)[3]),           \
          "=r"((r)[4]),  "=r"((r)[5]),  "=r"((r)[6]),  "=r"((r)[7]),           \
          "=r"((r)[8]),  "=r"((r)[9]),  "=r"((r)[10]), "=r"((r)[11]),          \
          "=r"((r)[12]), "=r"((r)[13]), "=r"((r)[14]), "=r"((r)[15]),          \
          "=r"((r)[16]), "=r"((r)[17]), "=r"((r)[18]), "=r"((r)[19]),          \
          "=r"((r)[20]), "=r"((r)[21]), "=r"((r)[22]), "=r"((r)[23]),          \
          "=r"((r)[24]), "=r"((r)[25]), "=r"((r)[26]), "=r"((r)[27]),          \
          "=r"((r)[28]), "=r"((r)[29]), "=r"((r)[30]), "=r"((r)[31])           \
        : "r"(tmem))

#define TC_ST_X32(tmem, r)                                                     \
    asm volatile(                                                              \
        "tcgen05.st.sync.aligned.32x32b.x32.b32 [%0], "                        \
        "{%1, %2, %3, %4, %5, %6, %7, %8, "                                    \
        " %9, %10, %11, %12, %13, %14, %15, %16, "                             \
        " %17, %18, %19, %20, %21, %22, %23, %24, "                            \
        " %25, %26, %27, %28, %29, %30, %31, %32};"                            \
        :: "r"(tmem),                                                          \
           "r"((r)[0]),  "r"((r)[1]),  "r"((r)[2]),  "r"((r)[3]),              \
           "r"((r)[4]),  "r"((r)[5]),  "r"((r)[6]),  "r"((r)[7]),              \
           "r"((r)[8]),  "r"((r)[9]),  "r"((r)[10]), "r"((r)[11]),             \
           "r"((r)[12]), "r"((r)[13]), "r"((r)[14]), "r"((r)[15]),             \
           "r"((r)[16]), "r"((r)[17]), "r"((r)[18]), "r"((r)[19]),             \
           "r"((r)[20]), "r"((r)[21]), "r"((r)[22]), "r"((r)[23]),             \
           "r"((r)[24]), "r"((r)[25]), "r"((r)[26]), "r"((r)[27]),             \
           "r"((r)[28]), "r"((r)[29]), "r"((r)[30]), "r"((r)[31])              \
        : "memory")

__device__ __forceinline__ uint64_t make_desc_sw128(uint32_t addr) {
    return ((uint64_t)2 << 61) | ((uint64_t)1 << 46) | ((uint64_t)64 << 32)
         | ((uint64_t)1 << 16) | (((uint64_t)(addr >> 4)) & 0x3FFF);
}

__device__ __forceinline__ void mma_tf32_ss(uint32_t d, uint64_t ad, uint64_t bd,
                                            uint32_t idesc, uint32_t en) {
    asm volatile(
        "{\n\t.reg .pred p;\n\tsetp.ne.u32 p, %4, 0;\n\t"
        "tcgen05.mma.cta_group::1.kind::tf32 [%0], %1, %2, %3, p;\n\t}"
        :: "r"(d), "l"(ad), "l"(bd), "r"(idesc), "r"(en) : "memory");
}
__device__ __forceinline__ void mma_tf32_ts(uint32_t d, uint32_t a, uint64_t bd,
                                            uint32_t idesc, uint32_t en) {
    asm volatile(
        "{\n\t.reg .pred p;\n\tsetp.ne.u32 p, %4, 0;\n\t"
        "tcgen05.mma.cta_group::1.kind::tf32 [%0], [%1], %2, %3, p;\n\t}"
        :: "r"(d), "r"(a), "l"(bd), "r"(idesc), "r"(en) : "memory");
}

__device__ __forceinline__ float tf32_hi(float x) {
    uint32_t u;
    asm("cvt.rna.tf32.f32 %0, %1;" : "=r"(u) : "f"(x));
    return __uint_as_float(u);
}

#define IDESC_TF32 ((1u << 4) | (2u << 7) | (2u << 10) | ((GTN / 8) << 17) | ((GTM / 16) << 24))
#define IDESC_S    ((1u << 4) | (2u << 7) | (2u << 10) | (16u << 17) | (8u << 24))   /* N=128 M=128 */
#define IDESC_PV   ((1u << 4) | (2u << 7) | (2u << 10) | (8u << 17)  | (8u << 24))   /* N=64  M=128 */

// ============================================================================
// Projection GEMM (unchanged from R3, passing)
// ============================================================================
__device__ __forceinline__ void load_split(const float* __restrict__ src,
                                           int row0, int k0,
                                           uint32_t hi_t, uint32_t lo_t, int t)
{
#pragma unroll
    for (int i = 0; i < 8; i++) {
        int idx = i * 128 + t;
        int r = idx >> 3, c4 = idx & 7;
        float4 v = *(const float4*)&src[(row0 + r) * DM + k0 + c4 * 4];
        float4 h, l;
        h.x = tf32_hi(v.x); l.x = v.x - h.x;
        h.y = tf32_hi(v.y); l.y = v.y - h.y;
        h.z = tf32_hi(v.z); l.z = v.z - h.z;
        h.w = tf32_hi(v.w); l.w = v.w - h.w;
        uint32_t off = SW128((uint32_t)(r * 128 + c4 * 16));
        asm volatile("st.shared.v4.b32 [%0], {%1,%2,%3,%4};" ::
            "r"(hi_t + off), "r"(__float_as_uint(h.x)), "r"(__float_as_uint(h.y)),
            "r"(__float_as_uint(h.z)), "r"(__float_as_uint(h.w)) : "memory");
        asm volatile("st.shared.v4.b32 [%0], {%1,%2,%3,%4};" ::
            "r"(lo_t + off), "r"(__float_as_uint(l.x)), "r"(__float_as_uint(l.y)),
            "r"(__float_as_uint(l.z)), "r"(__float_as_uint(l.w)) : "memory");
    }
}

__device__ __forceinline__ void gemm_body(const float* __restrict__ A,
                                          const float* __restrict__ W,
                                          const float* __restrict__ bias,
                                          float* __restrict__ C,
                                          float scale)
{
    extern __shared__ char smraw[];
    const uint32_t base = (smem_u32(smraw) + 1023) & ~1023u;
    const uint32_t mbar0 = base + 8, mbar1 = base + 16;
    const uint32_t tiles = base + 1024;

    const int t   = threadIdx.x;
    const int wid = t >> 5, lid = t & 31;
    const int m0  = blockIdx.y * GTM;
    const int n0  = blockIdx.x * GTN;

    if (wid == 0) { TC_ALLOC(base, 128); TC_RELINQ(); }
    if (t == 0) { MBAR_INIT(mbar0, 1); MBAR_INIT(mbar1, 1); }
    __syncthreads();
    uint32_t tmem;
    asm volatile("ld.shared.b32 %0, [%1];" : "=r"(tmem) : "r"(base));

    int ph0 = 0, ph1 = 0;

    for (int c = 0; c < NCHUNK; c++) {
        const int s = c & 1;
        const uint32_t st = tiles + s * STAGE_B;
        const uint32_t aHi = st, aLo = st + TILE_B, bHi = st + 2 * TILE_B, bLo = st + 3 * TILE_B;

        if (c >= 2) {
            if (s == 0) { MBAR_WAIT(mbar0, ph0); ph0 ^= 1; }
            else        { MBAR_WAIT(mbar1, ph1); ph1 ^= 1; }
        }

        load_split(A, m0, c * GKC, aHi, aLo, t);
        load_split(W, n0, c * GKC, bHi, bLo, t);

        FENCE_ASYNC_SHARED();
        __syncthreads();

        if (wid == 0 && elect_one()) {
            uint64_t dA[2] = { make_desc_sw128(aHi), make_desc_sw128(aLo) };
            uint64_t dB[2] = { make_desc_sw128(bHi), make_desc_sw128(bLo) };
#pragma unroll
            for (int cb = 0; cb < 3; cb++) {
                uint64_t ad = dA[cb == 2 ? 1 : 0];
                uint64_t bd = dB[cb == 1 ? 1 : 0];
#pragma unroll
                for (int ks = 0; ks < 4; ks++) {
                    uint32_t en = !(c == 0 && cb == 0 && ks == 0);
                    mma_tf32_ss(tmem, ad + ks * 2, bd + ks * 2, IDESC_TF32, en);
                }
            }
            TC_COMMIT(s == 0 ? mbar0 : mbar1);
        }
    }

    MBAR_WAIT(mbar0, ph0);
    MBAR_WAIT(mbar1, ph1);
    TC_FENCE_AFTER();

    uint32_t dr[128];
    TC_LD_X32(dr +  0, tmem +  0);
    TC_LD_X32(dr + 32, tmem + 32);
    TC_LD_X32(dr + 64, tmem + 64);
    TC_LD_X32(dr + 96, tmem + 96);
    TC_WAIT_LD();
    TC_FENCE_BEFORE();

    const int m = m0 + wid * 32 + lid;
#pragma unroll
    for (int c4 = 0; c4 < 32; c4++) {
        int n = n0 + c4 * 4;
        float4 o;
        o.x = (__uint_as_float(dr[c4 * 4 + 0]) + bias[n + 0]) * scale;
        o.y = (__uint_as_float(dr[c4 * 4 + 1]) + bias[n + 1]) * scale;
        o.z = (__uint_as_float(dr[c4 * 4 + 2]) + bias[n + 2]) * scale;
        o.w = (__uint_as_float(dr[c4 * 4 + 3]) + bias[n + 3]) * scale;
        *(float4*)&C[m * DM + n] = o;
    }

    __syncthreads();
    if (wid == 0) TC_DEALLOC(tmem, 128);
}

#else  // !HAS_TC fallback GEMM (dead code on GB300)
__device__ __forceinline__ void gemm_body(const float* __restrict__ A,
                                          const float* __restrict__ W,
                                          const float* __restrict__ bias,
                                          float* __restrict__ C,
                                          float scale)
{
    extern __shared__ char smraw[];
    float* Ws = (float*)smraw;
    float* As = (float*)smraw + GKC * 128;

    const int t  = threadIdx.x;
    const int m0 = blockIdx.y * GTM;
    const int n0 = blockIdx.x * GTN;
    const int tr = (t >> 4) << 4;
    const int tc = (t & 15) << 3;

    float acc[16][8] = {};
    for (int k0 = 0; k0 < DM; k0 += GKC) {
        __syncthreads();
        for (int idx = t; idx < GKC * 128 / 4; idx += 128) {
            int r = (idx * 4) >> 5, k4 = (idx * 4) & 31;
            float4 wv = *(const float4*)&W[(n0 + r) * DM + k0 + k4];
            Ws[(k4 + 0) * 128 + r] = wv.x; Ws[(k4 + 1) * 128 + r] = wv.y;
            Ws[(k4 + 2) * 128 + r] = wv.z; Ws[(k4 + 3) * 128 + r] = wv.w;
            float4 av = *(const float4*)&A[(m0 + r) * DM + k0 + k4];
            As[(k4 + 0) * 128 + r] = av.x; As[(k4 + 1) * 128 + r] = av.y;
            As[(k4 + 2) * 128 + r] = av.z; As[(k4 + 3) * 128 + r] = av.w;
        }
        __syncthreads();
        for (int k = 0; k < GKC; k++) {
            float a_[16], b_[8];
#pragma unroll
            for (int i = 0; i < 16; i++) a_[i] = As[k * 128 + tr + i];
#pragma unroll
            for (int j = 0; j < 8; j++)  b_[j] = Ws[k * 128 + tc + j];
#pragma unroll
            for (int i = 0; i < 16; i++)
#pragma unroll
                for (int j = 0; j < 8; j++) acc[i][j] += a_[i] * b_[j];
        }
    }
#pragma unroll
    for (int i = 0; i < 16; i++)
#pragma unroll
        for (int j = 0; j < 8; j++)
            C[(m0 + tr + i) * DM + n0 + tc + j] = (acc[i][j] + bias[n0 + tc + j]) * scale;
}
#endif  // HAS_TC

__global__ __launch_bounds__(128) void qkv_tc(
    const float* __restrict__ x,
    const float* __restrict__ Wq, const float* __restrict__ bq,
    const float* __restrict__ Wk, const float* __restrict__ bk,
    const float* __restrict__ Wv, const float* __restrict__ bv)
{
    int w = blockIdx.z;
    if (w == 0)      gemm_body(x, Wq, bq, g_q, 0.125f);
    else if (w == 1) gemm_body(x, Wk, bk, g_k, 1.0f);
    else             gemm_body(x, Wv, bv, g_v, 1.0f);
}

__global__ __launch_bounds__(128) void out_tc(
    const float* __restrict__ Wo, const float* __restrict__ bo,
    float* __restrict__ out)
{
    gemm_body(g_ctx, Wo, bo, out, 1.0f);
}

// ============================================================================
// tcgen05 flash attention, fixed-max softmax (m = 16).
// One CTA per (q-tile 128, head). 256 threads = 2 "column groups" of 4 warps.
// Per 128-key tile:
//   S = Q K^T   (split-tf32 SS, D_S in TMEM cols 64..191)
//   P = exp(S-16) masked, split hi/lo, stored to TMEM (cols 192.. / 320..)
//   O += P V    (split-tf32 TS: A = P in TMEM, B = V^T chunks in SMEM)
// l = row-sum of P accumulated in registers; final O/l written to g_ctx.
// ============================================================================
__global__ __launch_bounds__(256) void attn_tc()
{
#if HAS_TC
    extern __shared__ char smraw[];
    __shared__ uint64_t s_bar[2];
    __shared__ uint32_t s_tptr;
    __shared__ float s_l[256];

    const uint32_t tiles = (smem_u32(smraw) + 1023) & ~1023u;
    const uint32_t QO = tiles;              // 4 tiles: hi c0, hi c1 | lo c0, lo c1 (16KB each)
    const uint32_t KO = tiles + 65536;
    const uint32_t VO = tiles + 131072;     // 8 tiles: hi kc0..3 | lo kc0..3 (8KB each)
    const uint32_t mbar_s  = smem_u32(&s_bar[0]);
    const uint32_t mbar_pv = smem_u32(&s_bar[1]);
    const uint32_t tptr_a  = smem_u32(&s_tptr);

    const int t    = threadIdx.x;
    const int wid  = t >> 5, lane = t & 31;
    const int sub  = wid & 3, wg = wid >> 2;
    const int qb   = (SEQ / 128 - 1) - blockIdx.x;   // longest tiles first
    const int h    = blockIdx.y;
    const int row  = sub * 32 + lane;                // local q row 0..127
    const int qglob = qb * 128 + row;

    if (wid == 0) { TC_ALLOC(tptr_a, 512); TC_RELINQ(); }
    if (t == 0) { MBAR_INIT(mbar_s, 1); MBAR_INIT(mbar_pv, 1); }
    __syncthreads();
    uint32_t tmem;
    asm volatile("ld.shared.b32 %0, [%1];" : "=r"(tmem) : "r"(tptr_a));

    // ---- load Q tile (persistent), split hi/lo, 2 K-chunks of 32 dims ----
    for (int idx = t; idx < 2048; idx += 256) {
        int c = idx >> 10, rr = (idx & 1023) >> 3, c4 = idx & 7;
        float4 v = *(const float4*)&g_q[(qb * 128 + rr) * DM + h * DK + c * 32 + c4 * 4];
        float4 hh, ll;
        hh.x = tf32_hi(v.x); ll.x = v.x - hh.x;
        hh.y = tf32_hi(v.y); ll.y = v.y - hh.y;
        hh.z = tf32_hi(v.z); ll.z = v.z - hh.z;
        hh.w = tf32_hi(v.w); ll.w = v.w - hh.w;
        uint32_t off = SW128((uint32_t)(rr * 128 + c4 * 16));
        uint32_t hi_t = QO + c * 16384, lo_t = QO + 32768 + c * 16384;
        asm volatile("st.shared.v4.b32 [%0], {%1,%2,%3,%4};" ::
            "r"(hi_t + off), "r"(__float_as_uint(hh.x)), "r"(__float_as_uint(hh.y)),
            "r"(__float_as_uint(hh.z)), "r"(__float_as_uint(hh.w)) : "memory");
        asm volatile("st.shared.v4.b32 [%0], {%1,%2,%3,%4};" ::
            "r"(lo_t + off), "r"(__float_as_uint(ll.x)), "r"(__float_as_uint(ll.y)),
            "r"(__float_as_uint(ll.z)), "r"(__float_as_uint(ll.w)) : "memory");
    }

    float lpart = 0.f;
    int ph_s = 0, ph_pv = 0;

    for (int kb = 0; kb <= qb; kb++) {
        if (kb > 0) { MBAR_WAIT(mbar_pv, ph_pv); ph_pv ^= 1; }

        // ---- load K tile [128 keys x 64 d] split, 2 chunks ----
        for (int idx = t; idx < 2048; idx += 256) {
            int c = idx >> 10, rr = (idx & 1023) >> 3, c4 = idx & 7;
            float4 v = *(const float4*)&g_k[(kb * 128 + rr) * DM + h * DK + c * 32 + c4 * 4];
            float4 hh, ll;
            hh.x = tf32_hi(v.x); ll.x = v.x - hh.x;
            hh.y = tf32_hi(v.y); ll.y = v.y - hh.y;
            hh.z = tf32_hi(v.z); ll.z = v.z - hh.z;
            hh.w = tf32_hi(v.w); ll.w = v.w - hh.w;
            uint32_t off = SW128((uint32_t)(rr * 128 + c4 * 16));
            uint32_t hi_t = KO + c * 16384, lo_t = KO + 32768 + c * 16384;
            asm volatile("st.shared.v4.b32 [%0], {%1,%2,%3,%4};" ::
                "r"(hi_t + off), "r"(__float_as_uint(hh.x)), "r"(__float_as_uint(hh.y)),
                "r"(__float_as_uint(hh.z)), "r"(__float_as_uint(hh.w)) : "memory");
            asm volatile("st.shared.v4.b32 [%0], {%1,%2,%3,%4};" ::
                "r"(lo_t + off), "r"(__float_as_uint(ll.x)), "r"(__float_as_uint(ll.y)),
                "r"(__float_as_uint(ll.z)), "r"(__float_as_uint(ll.w)) : "memory");
        }

        // ---- load V tile transposed: Vt chunk kc = [64 dv rows x 32 keys] ----
        for (int idx4 = t; idx4 < 2048; idx4 += 256) {
            int key_local = idx4 >> 4;
            int dv4 = (idx4 & 15) * 4;
            float4 v = *(const float4*)&g_v[(kb * 128 + key_local) * DM + h * DK + dv4];
            int kc = key_local >> 5, kk = key_local & 31;
            uint32_t hi_t = VO + kc * 8192, lo_t = VO + 32768 + kc * 8192;
            float vv[4] = {v.x, v.y, v.z, v.w};
#pragma unroll
            for (int i = 0; i < 4; i++) {
                float hv = tf32_hi(vv[i]);
                float lv = vv[i] - hv;
                uint32_t off = SW128((uint32_t)((dv4 + i) * 128 + kk * 4));
                asm volatile("st.shared.b32 [%0], %1;" :: "r"(hi_t + off), "r"(__float_as_uint(hv)) : "memory");
                asm volatile("st.shared.b32 [%0], %1;" :: "r"(lo_t + off), "r"(__float_as_uint(lv)) : "memory");
            }
        }

        FENCE_ASYNC_SHARED();
        __syncthreads();

        // ---- S = Q K^T (split 3 combos) ----
        if (wid == 0 && elect_one()) {
#pragma unroll
            for (int cb = 0; cb < 3; cb++) {
                uint32_t aoff = (cb == 2) ? 32768u : 0u;
                uint32_t boff = (cb == 1) ? 32768u : 0u;
#pragma unroll
                for (int c = 0; c < 2; c++) {
                    uint64_t ad = make_desc_sw128(QO + aoff + c * 16384);
                    uint64_t bd = make_desc_sw128(KO + boff + c * 16384);
#pragma unroll
                    for (int ks = 0; ks < 4; ks++) {
                        uint32_t en = !(cb == 0 && c == 0 && ks == 0);
                        mma_tf32_ss(tmem + TM_S, ad + ks * 2, bd + ks * 2, IDESC_S, en);
                    }
                }
            }
            TC_COMMIT(mbar_s);
        }
        MBAR_WAIT(mbar_s, ph_s); ph_s ^= 1;
        TC_FENCE_AFTER();

        // ---- exp + mask + split, this wg's 64 columns ----
        const int colbase = wg * 64;
#pragma unroll
        for (int blk = 0; blk < 2; blk++) {
            uint32_t sr[32], hr[32], lr[32];
            TC_LD_X32(sr, tmem + TM_S + colbase + blk * 32);
            TC_WAIT_LD();
#pragma unroll
            for (int c = 0; c < 32; c++) {
                int key = kb * 128 + colbase + blk * 32 + c;
                float s = __uint_as_float(sr[c]);
                float p = (key <= qglob) ? __expf(s - 16.f) : 0.f;
                lpart += p;
                float hv = tf32_hi(p);
                hr[c] = __float_as_uint(hv);
                lr[c] = __float_as_uint(p - hv);
            }
            TC_ST_X32(tmem + TM_PH + colbase + blk * 32 + (sub << 21), hr);
            TC_ST_X32(tmem + TM_PL + colbase + blk * 32 + (sub << 21), lr);
        }
        TC_WAIT_ST();
        TC_FENCE_BEFORE();
        __syncthreads();

        // ---- O += P V (TS mode: A = P in TMEM; combos PhVh, PhVl, PlVh) ----
        if (wid == 0 && elect_one()) {
            TC_FENCE_AFTER();
#pragma unroll
            for (int cb = 0; cb < 3; cb++) {
                uint32_t pa = tmem + ((cb == 2) ? TM_PL : TM_PH);
                uint32_t vsel = (cb == 1) ? 32768u : 0u;
#pragma unroll
                for (int kc = 0; kc < 4; kc++) {
                    uint64_t bd = make_desc_sw128(VO + vsel + kc * 8192);
#pragma unroll
                    for (int ks = 0; ks < 4; ks++) {
                        uint32_t en = !(kb == 0 && cb == 0 && kc == 0 && ks == 0);
                        mma_tf32_ts(tmem + TM_O, pa + kc * 32 + ks * 8, bd + ks * 2, IDESC_PV, en);
                    }
                }
            }
            TC_COMMIT(mbar_pv);
        }
    }

    MBAR_WAIT(mbar_pv, ph_pv);
    TC_FENCE_AFTER();

    s_l[wg * 128 + row] = lpart;
    __syncthreads();

    if (wid < 4) {
        uint32_t orr[64];
        TC_LD_X32(orr, tmem + TM_O);
        TC_LD_X32(orr + 32, tmem + TM_O + 32);
        TC_WAIT_LD();
        TC_FENCE_BEFORE();
        float inv = 1.f / (s_l[row] + s_l[128 + row]);
#pragma unroll
        for (int c4 = 0; c4 < 16; c4++) {
            float4 o;
            o.x = __uint_as_float(orr[c4 * 4 + 0]) * inv;
            o.y = __uint_as_float(orr[c4 * 4 + 1]) * inv;
            o.z = __uint_as_float(orr[c4 * 4 + 2]) * inv;
            o.w = __uint_as_float(orr[c4 * 4 + 3]) * inv;
            *(float4*)&g_ctx[(qb * 128 + row) * DM + h * DK + c4 * 4] = o;
        }
    }
    __syncthreads();
    if (wid == 0) TC_DEALLOC(tmem, 512);

#else  // naive fallback (dead code on GB300; correctness only)
    const int t = threadIdx.x;
    const int qb = (SEQ / 128 - 1) - blockIdx.x;
    const int h = blockIdx.y;
    if (t < 128) {
        int row = qb * 128 + t;
        float l = 0.f, o[DK];
        for (int d = 0; d < DK; d++) o[d] = 0.f;
        for (int key = 0; key <= row; key++) {
            float s = 0.f;
            for (int d = 0; d < DK; d++)
                s += g_q[row * DM + h * DK + d] * g_k[key * DM + h * DK + d];
            float p = __expf(s - 16.f);
            l += p;
            for (int d = 0; d < DK; d++) o[d] += p * g_v[key * DM + h * DK + d];
        }
        for (int d = 0; d < DK; d++) g_ctx[row * DM + h * DK + d] = o[d] / l;
    }
#endif
}

// ---------------------------------------------------------------------------
extern "C" void kernel_launch(void* const* d_in, const int* in_sizes, int n_in,
                              void* d_out, int out_size)
{
    const float* x  = (const float*)d_in[0];
    const float* Wq = (const float*)d_in[1];
    const float* bq = (const float*)d_in[2];
    const float* Wk = (const float*)d_in[3];
    const float* bk = (const float*)d_in[4];
    const float* Wv = (const float*)d_in[5];
    const float* bv = (const float*)d_in[6];
    const float* Wo = (const float*)d_in[7];
    const float* bo = (const float*)d_in[8];
    float* out = (float*)d_out;

    cudaFuncSetAttribute(qkv_tc, cudaFuncAttributeMaxDynamicSharedMemorySize, GEMM_SMEM);
    cudaFuncSetAttribute(out_tc, cudaFuncAttributeMaxDynamicSharedMemorySize, GEMM_SMEM);
    cudaFuncSetAttribute(attn_tc, cudaFuncAttributeMaxDynamicSharedMemorySize, ATT_SMEM);

    qkv_tc<<<dim3(DM / GTN, SEQ / GTM, 3), 128, GEMM_SMEM>>>(x, Wq, bq, Wk, bk, Wv, bv);
    attn_tc<<<dim3(SEQ / 128, NH), 256, ATT_SMEM>>>();
    out_tc<<<dim3(DM / GTN, SEQ / GTM), 128, GEMM_SMEM>>>(Wo, bo, out);
}

// round 5
// speedup vs baseline: 2.9718x; 1.3433x over previous
#include <cuda_runtime.h>
#include <cuda_bf16.h>
#include <math.h>
#include <stdint.h>

#define SEQ 4096
#define DM  768
#define NH  12
#define DK  64

#if defined(__CUDA_ARCH__) && (__CUDA_ARCH__ == 1030) && defined(__CUDA_ARCH_FEAT_SM103_ALL)
#define HAS_TC 1
#else
#define HAS_TC 0
#endif

// Scratch (allocation-free rule: __device__ globals)
__device__ float g_q[SEQ * DM];
__device__ float g_k[SEQ * DM];
__device__ float g_v[SEQ * DM];
__device__ float g_ctx[SEQ * DM];

// ============================================================================
// Projection GEMM geometry (unchanged, passing)
// ============================================================================
#define GTM 128
#define GTN 128
#define GKC 32
#define NCHUNK (DM / GKC)
#define TILE_B (GTM * 128)
#define STAGE_B (4 * TILE_B)
#define GEMM_SMEM (1024 + 1024 + 2 * STAGE_B)

// Attention smem: slack + Q(32K) + K(2 stages x 32K) + V(2 stages x 32K)
#define ATT_SMEM (1024 + 32768 + 65536 + 65536)
// TMEM columns
#define TM_O  0     /* 64 cols fp32 */
#define TM_S  64    /* 128 cols fp32 */
#define TM_PH 192   /* 64 cols bf16x2 */
#define TM_PL 256   /* 64 cols bf16x2 */

#if HAS_TC
// ============================================================================
// PTX helpers (sm_103a feature target only)
// ============================================================================
__device__ __forceinline__ uint32_t smem_u32(const void* p) {
    uint32_t a;
    asm("{ .reg .u64 t; cvta.to.shared.u64 t, %1; cvt.u32.u64 %0, t; }"
        : "=r"(a) : "l"(p));
    return a;
}
__device__ __forceinline__ uint32_t elect_one() {
    uint32_t p;
    asm volatile("{ .reg .pred p; elect.sync _|p, 0xFFFFFFFF; selp.b32 %0, 1, 0, p; }" : "=r"(p));
    return p;
}
#define SW128(off) ((off) ^ (((off) >> 3) & 0x70))

#define MBAR_INIT(addr, cnt) \
    asm volatile("mbarrier.init.shared.b64 [%0], %1;" :: "r"(addr), "r"(cnt) : "memory")

#define MBAR_WAIT(addr, parity) do {                                           \
    asm volatile(                                                              \
        "{\n\t.reg .pred P1;\n\t"                                              \
        "WL_%=:\n\t"                                                           \
        "mbarrier.try_wait.parity.acquire.cta.shared::cta.b64 P1, [%0], %1, 0x989680;\n\t" \
        "@P1 bra.uni WD_%=;\n\t"                                               \
        "bra.uni WL_%=;\n\t"                                                   \
        "WD_%=:\n\t}"                                                          \
        :: "r"(addr), "r"(parity) : "memory");                                 \
} while (0)

#define TC_ALLOC(smem_addr, ncols) \
    asm volatile("tcgen05.alloc.cta_group::1.sync.aligned.shared::cta.b32 [%0], %1;" \
                 :: "r"(smem_addr), "r"(ncols) : "memory")
#define TC_DEALLOC(tmem, ncols) \
    asm volatile("tcgen05.dealloc.cta_group::1.sync.aligned.b32 %0, %1;" :: "r"(tmem), "r"(ncols))
#define TC_RELINQ() \
    asm volatile("tcgen05.relinquish_alloc_permit.cta_group::1.sync.aligned;")
#define TC_COMMIT(mbar) \
    asm volatile("tcgen05.commit.cta_group::1.mbarrier::arrive::one.shared::cluster.b64 [%0];" \
                 :: "r"(mbar) : "memory")
#define TC_FENCE_AFTER()  asm volatile("tcgen05.fence::after_thread_sync;" ::: "memory")
#define TC_FENCE_BEFORE() asm volatile("tcgen05.fence::before_thread_sync;" ::: "memory")
#define TC_WAIT_LD()      asm volatile("tcgen05.wait::ld.sync.aligned;" ::: "memory")
#define TC_WAIT_ST()      asm volatile("tcgen05.wait::st.sync.aligned;" ::: "memory")
#define FENCE_ASYNC_SHARED() asm volatile("fence.proxy.async.shared::cta;" ::: "memory")

#define TC_LD_X32(r, tmem)                                                     \
    asm volatile(                                                              \
        "tcgen05.ld.sync.aligned.32x32b.x32.b32 "                              \
        "{%0, %1, %2, %3, %4, %5, %6, %7, "                                    \
        " %8, %9, %10, %11, %12, %13, %14, %15, "                              \
        " %16, %17, %18, %19, %20, %21, %22, %23, "                            \
        " %24, %25, %26, %27, %28, %29, %30, %31}, [%32];"                     \
        : "=r"((r)[0]),  "=r"((r)[1]),  "=r"((r)[2]),  "=r"((r)[3]),           \
          "=r"((r)[4]),  "=r"((r)[5]),  "=r"((r)[6]),  "=r"((r)[7]),           \
          "=r"((r)[8]),  "=r"((r)[9]),  "=r"((r)[10]), "=r"((r)[11]),          \
          "=r"((r)[12]), "=r"((r)[13]), "=r"((r)[14]), "=r"((r)[15]),          \
          "=r"((r)[16]), "=r"((r)[17]), "=r"((r)[18]), "=r"((r)[19]),          \
          "=r"((r)[20]), "=r"((r)[21]), "=r"((r)[22]), "=r"((r)[23]),          \
          "=r"((r)[24]), "=r"((r)[25]), "=r"((r)[26]), "=r"((r)[27]),          \
          "=r"((r)[28]), "=r"((r)[29]), "=r"((r)[30]), "=r"((r)[31])           \
        : "r"(tmem))

#define TC_ST_X32(tmem, r)                                                     \
    asm volatile(                                                              \
        "tcgen05.st.sync.aligned.32x32b.x32.b32 [%0], "                        \
        "{%1, %2, %3, %4, %5, %6, %7, %8, "                                    \
        " %9, %10, %11, %12, %13, %14, %15, %16, "                             \
        " %17, %18, %19, %20, %21, %22, %23, %24, "                            \
        " %25, %26, %27, %28, %29, %30, %31, %32};"                            \
        :: "r"(tmem),                                                          \
           "r"((r)[0]),  "r"((r)[1]),  "r"((r)[2]),  "r"((r)[3]),              \
           "r"((r)[4]),  "r"((r)[5]),  "r"((r)[6]),  "r"((r)[7]),              \
           "r"((r)[8]),  "r"((r)[9]),  "r"((r)[10]), "r"((r)[11]),             \
           "r"((r)[12]), "r"((r)[13]), "r"((r)[14]), "r"((r)[15]),             \
           "r"((r)[16]), "r"((r)[17]), "r"((r)[18]), "r"((r)[19]),             \
           "r"((r)[20]), "r"((r)[21]), "r"((r)[22]), "r"((r)[23]),             \
           "r"((r)[24]), "r"((r)[25]), "r"((r)[26]), "r"((r)[27]),             \
           "r"((r)[28]), "r"((r)[29]), "r"((r)[30]), "r"((r)[31])              \
        : "memory")

__device__ __forceinline__ uint64_t make_desc_sw128(uint32_t addr) {
    return ((uint64_t)2 << 61) | ((uint64_t)1 << 46) | ((uint64_t)64 << 32)
         | ((uint64_t)1 << 16) | (((uint64_t)(addr >> 4)) & 0x3FFF);
}

__device__ __forceinline__ void mma_tf32_ss(uint32_t d, uint64_t ad, uint64_t bd,
                                            uint32_t idesc, uint32_t en) {
    asm volatile(
        "{\n\t.reg .pred p;\n\tsetp.ne.u32 p, %4, 0;\n\t"
        "tcgen05.mma.cta_group::1.kind::tf32 [%0], %1, %2, %3, p;\n\t}"
        :: "r"(d), "l"(ad), "l"(bd), "r"(idesc), "r"(en) : "memory");
}
__device__ __forceinline__ void mma_f16_ss(uint32_t d, uint64_t ad, uint64_t bd,
                                           uint32_t idesc, uint32_t en) {
    asm volatile(
        "{\n\t.reg .pred p;\n\tsetp.ne.u32 p, %4, 0;\n\t"
        "tcgen05.mma.cta_group::1.kind::f16 [%0], %1, %2, %3, p;\n\t}"
        :: "r"(d), "l"(ad), "l"(bd), "r"(idesc), "r"(en) : "memory");
}
__device__ __forceinline__ void mma_f16_ts(uint32_t d, uint32_t a, uint64_t bd,
                                           uint32_t idesc, uint32_t en) {
    asm volatile(
        "{\n\t.reg .pred p;\n\tsetp.ne.u32 p, %4, 0;\n\t"
        "tcgen05.mma.cta_group::1.kind::f16 [%0], [%1], %2, %3, p;\n\t}"
        :: "r"(d), "r"(a), "l"(bd), "r"(idesc), "r"(en) : "memory");
}

__device__ __forceinline__ float tf32_hi(float x) {
    uint32_t u;
    asm("cvt.rna.tf32.f32 %0, %1;" : "=r"(u) : "f"(x));
    return __uint_as_float(u);
}
__device__ __forceinline__ uint32_t bf16x2_of(float lo, float hi) {
    uint32_t r;
    asm("cvt.rn.bf16x2.f32 %0, %1, %2;" : "=r"(r) : "f"(hi), "f"(lo));
    return r;
}
__device__ __forceinline__ float bf16f(float x) {
    return __bfloat162float(__float2bfloat16(x));
}

#define IDESC_TF32  ((1u << 4) | (2u << 7) | (2u << 10) | ((GTN / 8) << 17) | ((GTM / 16) << 24))
#define IDESC_S16   ((1u << 4) | (1u << 7) | (1u << 10) | (16u << 17) | (8u << 24))  /* M=128 N=128 */
#define IDESC_PV16  ((1u << 4) | (1u << 7) | (1u << 10) | (8u << 17)  | (8u << 24))  /* M=128 N=64 */

// ============================================================================
// Projection GEMM (split-tf32, unchanged from R3/R4 — passing)
// ============================================================================
__device__ __forceinline__ void load_split(const float* __restrict__ src,
                                           int row0, int k0,
                                           uint32_t hi_t, uint32_t lo_t, int t)
{
#pragma unroll
    for (int i = 0; i < 8; i++) {
        int idx = i * 128 + t;
        int r = idx >> 3, c4 = idx & 7;
        float4 v = *(const float4*)&src[(row0 + r) * DM + k0 + c4 * 4];
        float4 h, l;
        h.x = tf32_hi(v.x); l.x = v.x - h.x;
        h.y = tf32_hi(v.y); l.y = v.y - h.y;
        h.z = tf32_hi(v.z); l.z = v.z - h.z;
        h.w = tf32_hi(v.w); l.w = v.w - h.w;
        uint32_t off = SW128((uint32_t)(r * 128 + c4 * 16));
        asm volatile("st.shared.v4.b32 [%0], {%1,%2,%3,%4};" ::
            "r"(hi_t + off), "r"(__float_as_uint(h.x)), "r"(__float_as_uint(h.y)),
            "r"(__float_as_uint(h.z)), "r"(__float_as_uint(h.w)) : "memory");
        asm volatile("st.shared.v4.b32 [%0], {%1,%2,%3,%4};" ::
            "r"(lo_t + off), "r"(__float_as_uint(l.x)), "r"(__float_as_uint(l.y)),
            "r"(__float_as_uint(l.z)), "r"(__float_as_uint(l.w)) : "memory");
    }
}

__device__ __forceinline__ void gemm_body(const float* __restrict__ A,
                                          const float* __restrict__ W,
                                          const float* __restrict__ bias,
                                          float* __restrict__ C,
                                          float scale)
{
    extern __shared__ char smraw[];
    const uint32_t base = (smem_u32(smraw) + 1023) & ~1023u;
    const uint32_t mbar0 = base + 8, mbar1 = base + 16;
    const uint32_t tiles = base + 1024;

    const int t   = threadIdx.x;
    const int wid = t >> 5, lid = t & 31;
    const int m0  = blockIdx.y * GTM;
    const int n0  = blockIdx.x * GTN;

    if (wid == 0) { TC_ALLOC(base, 128); TC_RELINQ(); }
    if (t == 0) { MBAR_INIT(mbar0, 1); MBAR_INIT(mbar1, 1); }
    __syncthreads();
    uint32_t tmem;
    asm volatile("ld.shared.b32 %0, [%1];" : "=r"(tmem) : "r"(base));

    int ph0 = 0, ph1 = 0;

    for (int c = 0; c < NCHUNK; c++) {
        const int s = c & 1;
        const uint32_t st = tiles + s * STAGE_B;
        const uint32_t aHi = st, aLo = st + TILE_B, bHi = st + 2 * TILE_B, bLo = st + 3 * TILE_B;

        if (c >= 2) {
            if (s == 0) { MBAR_WAIT(mbar0, ph0); ph0 ^= 1; }
            else        { MBAR_WAIT(mbar1, ph1); ph1 ^= 1; }
        }

        load_split(A, m0, c * GKC, aHi, aLo, t);
        load_split(W, n0, c * GKC, bHi, bLo, t);

        FENCE_ASYNC_SHARED();
        __syncthreads();

        if (wid == 0 && elect_one()) {
            uint64_t dA[2] = { make_desc_sw128(aHi), make_desc_sw128(aLo) };
            uint64_t dB[2] = { make_desc_sw128(bHi), make_desc_sw128(bLo) };
#pragma unroll
            for (int cb = 0; cb < 3; cb++) {
                uint64_t ad = dA[cb == 2 ? 1 : 0];
                uint64_t bd = dB[cb == 1 ? 1 : 0];
#pragma unroll
                for (int ks = 0; ks < 4; ks++) {
                    uint32_t en = !(c == 0 && cb == 0 && ks == 0);
                    mma_tf32_ss(tmem, ad + ks * 2, bd + ks * 2, IDESC_TF32, en);
                }
            }
            TC_COMMIT(s == 0 ? mbar0 : mbar1);
        }
    }

    MBAR_WAIT(mbar0, ph0);
    MBAR_WAIT(mbar1, ph1);
    TC_FENCE_AFTER();

    uint32_t dr[128];
    TC_LD_X32(dr +  0, tmem +  0);
    TC_LD_X32(dr + 32, tmem + 32);
    TC_LD_X32(dr + 64, tmem + 64);
    TC_LD_X32(dr + 96, tmem + 96);
    TC_WAIT_LD();
    TC_FENCE_BEFORE();

    const int m = m0 + wid * 32 + lid;
#pragma unroll
    for (int c4 = 0; c4 < 32; c4++) {
        int n = n0 + c4 * 4;
        float4 o;
        o.x = (__uint_as_float(dr[c4 * 4 + 0]) + bias[n + 0]) * scale;
        o.y = (__uint_as_float(dr[c4 * 4 + 1]) + bias[n + 1]) * scale;
        o.z = (__uint_as_float(dr[c4 * 4 + 2]) + bias[n + 2]) * scale;
        o.w = (__uint_as_float(dr[c4 * 4 + 3]) + bias[n + 3]) * scale;
        *(float4*)&C[m * DM + n] = o;
    }

    __syncthreads();
    if (wid == 0) TC_DEALLOC(tmem, 128);
}

// ---- attention bf16 tile loaders ----
// Q/K tile: [128 rows (q or key)][64 d] -> hi/lo bf16, 128B rows, SW128
__device__ __forceinline__ void load_qk_bf16(const float* __restrict__ src,
                                             int row0, int h,
                                             uint32_t hiT, uint32_t loT, int t)
{
#pragma unroll
    for (int i = 0; i < 8; i++) {
        int idx = i * 256 + t;
        int r = idx >> 4, c4 = idx & 15;
        float4 v = *(const float4*)&src[(row0 + r) * DM + h * DK + c4 * 4];
        uint32_t h0 = bf16x2_of(v.x, v.y);
        uint32_t h1 = bf16x2_of(v.z, v.w);
        uint32_t l0 = bf16x2_of(v.x - bf16f(v.x), v.y - bf16f(v.y));
        uint32_t l1 = bf16x2_of(v.z - bf16f(v.z), v.w - bf16f(v.w));
        uint32_t off = SW128((uint32_t)(r * 128 + c4 * 8));
        asm volatile("st.shared.v2.b32 [%0], {%1,%2};" :: "r"(hiT + off), "r"(h0), "r"(h1) : "memory");
        asm volatile("st.shared.v2.b32 [%0], {%1,%2};" :: "r"(loT + off), "r"(l0), "r"(l1) : "memory");
    }
}

// V tile transposed: 2 chunks [64 dv][64 keys] bf16, keys packed in pairs
__device__ __forceinline__ void load_v_bf16(const float* __restrict__ gv,
                                            int kb, int h,
                                            uint32_t hiT, uint32_t loT, int t)
{
#pragma unroll
    for (int i = 0; i < 4; i++) {
        int idx = i * 256 + t;
        int u   = idx & 63;     // key pair index (keys 2u, 2u+1)
        int dvg = idx >> 6;     // 0..15, dv group of 4
        const float* p0 = &gv[(kb * 128 + 2 * u) * DM + h * DK + dvg * 4];
        float4 a = *(const float4*)p0;
        float4 b = *(const float4*)(p0 + DM);
        int kc = u >> 5, up = u & 31;
        uint32_t hbase = hiT + kc * 8192, lbase = loT + kc * 8192;
        float av[4] = {a.x, a.y, a.z, a.w}, bv[4] = {b.x, b.y, b.z, b.w};
#pragma unroll
        for (int j = 0; j < 4; j++) {
            uint32_t hw = bf16x2_of(av[j], bv[j]);
            uint32_t lw = bf16x2_of(av[j] - bf16f(av[j]), bv[j] - bf16f(bv[j]));
            uint32_t off = SW128((uint32_t)((dvg * 4 + j) * 128 + up * 4));
            asm volatile("st.shared.b32 [%0], %1;" :: "r"(hbase + off), "r"(hw) : "memory");
            asm volatile("st.shared.b32 [%0], %1;" :: "r"(lbase + off), "r"(lw) : "memory");
        }
    }
}
#else  // !HAS_TC fallback GEMM (dead code on GB300)
__device__ __forceinline__ void gemm_body(const float* __restrict__ A,
                                          const float* __restrict__ W,
                                          const float* __restrict__ bias,
                                          float* __restrict__ C,
                                          float scale)
{
    extern __shared__ char smraw[];
    float* Ws = (float*)smraw;
    float* As = (float*)smraw + GKC * 128;

    const int t  = threadIdx.x;
    const int m0 = blockIdx.y * GTM;
    const int n0 = blockIdx.x * GTN;
    const int tr = (t >> 4) << 4;
    const int tc = (t & 15) << 3;

    float acc[16][8] = {};
    for (int k0 = 0; k0 < DM; k0 += GKC) {
        __syncthreads();
        for (int idx = t; idx < GKC * 128 / 4; idx += 128) {
            int r = (idx * 4) >> 5, k4 = (idx * 4) & 31;
            float4 wv = *(const float4*)&W[(n0 + r) * DM + k0 + k4];
            Ws[(k4 + 0) * 128 + r] = wv.x; Ws[(k4 + 1) * 128 + r] = wv.y;
            Ws[(k4 + 2) * 128 + r] = wv.z; Ws[(k4 + 3) * 128 + r] = wv.w;
            float4 av = *(const float4*)&A[(m0 + r) * DM + k0 + k4];
            As[(k4 + 0) * 128 + r] = av.x; As[(k4 + 1) * 128 + r] = av.y;
            As[(k4 + 2) * 128 + r] = av.z; As[(k4 + 3) * 128 + r] = av.w;
        }
        __syncthreads();
        for (int k = 0; k < GKC; k++) {
            float a_[16], b_[8];
#pragma unroll
            for (int i = 0; i < 16; i++) a_[i] = As[k * 128 + tr + i];
#pragma unroll
            for (int j = 0; j < 8; j++)  b_[j] = Ws[k * 128 + tc + j];
#pragma unroll
            for (int i = 0; i < 16; i++)
#pragma unroll
                for (int j = 0; j < 8; j++) acc[i][j] += a_[i] * b_[j];
        }
    }
#pragma unroll
    for (int i = 0; i < 16; i++)
#pragma unroll
        for (int j = 0; j < 8; j++)
            C[(m0 + tr + i) * DM + n0 + tc + j] = (acc[i][j] + bias[n0 + tc + j]) * scale;
}
#endif  // HAS_TC

__global__ __launch_bounds__(128) void qkv_tc(
    const float* __restrict__ x,
    const float* __restrict__ Wq, const float* __restrict__ bq,
    const float* __restrict__ Wk, const float* __restrict__ bk,
    const float* __restrict__ Wv, const float* __restrict__ bv)
{
    int w = blockIdx.z;
    if (w == 0)      gemm_body(x, Wq, bq, g_q, 0.125f);
    else if (w == 1) gemm_body(x, Wk, bk, g_k, 1.0f);
    else             gemm_body(x, Wv, bv, g_v, 1.0f);
}

__global__ __launch_bounds__(128) void out_tc(
    const float* __restrict__ Wo, const float* __restrict__ bo,
    float* __restrict__ out)
{
    gemm_body(g_ctx, Wo, bo, out, 1.0f);
}

// ============================================================================
// tcgen05 flash attention, bf16 hi/lo split, fixed-max softmax, double-buffered
// ============================================================================
__global__ __launch_bounds__(256) void attn_tc()
{
#if HAS_TC
    extern __shared__ char smraw[];
    __shared__ uint64_t s_bar[2];
    __shared__ uint32_t s_tptr;
    __shared__ float s_l[256];

    const uint32_t base = (smem_u32(smraw) + 1023) & ~1023u;
    const uint32_t QO = base;               // QH 16K | QL 16K
    const uint32_t KO = base + 32768;       // stage s at +s*32768: KH 16K | KL 16K
    const uint32_t VO = base + 98304;       // stage s at +s*32768: VH 16K (2x8K) | VL 16K
    const uint32_t mbar_s  = smem_u32(&s_bar[0]);
    const uint32_t mbar_pv = smem_u32(&s_bar[1]);
    const uint32_t tptr_a  = smem_u32(&s_tptr);

    const int t     = threadIdx.x;
    const int wid   = t >> 5, lane = t & 31;
    const int sub   = wid & 3, wg = wid >> 2;
    const int qb    = (SEQ / 128 - 1) - blockIdx.x;  // longest first
    const int h     = blockIdx.y;
    const int row   = sub * 32 + lane;
    const int qglob = qb * 128 + row;

    if (wid == 0) { TC_ALLOC(tptr_a, 512); TC_RELINQ(); }
    if (t == 0) { MBAR_INIT(mbar_s, 1); MBAR_INIT(mbar_pv, 1); }
    __syncthreads();
    uint32_t tmem;
    asm volatile("ld.shared.b32 %0, [%1];" : "=r"(tmem) : "r"(tptr_a));

    // preload Q (persistent) + K/V stage 0
    load_qk_bf16(g_q, qb * 128, h, QO, QO + 16384, t);
    load_qk_bf16(g_k, 0,        h, KO, KO + 16384, t);
    load_v_bf16(g_v, 0, h, VO, VO + 16384, t);
    FENCE_ASYNC_SHARED();

    float lpart = 0.f;
    int ph_s = 0, ph_pv = 0;

    for (int kb = 0; kb <= qb; kb++) {
        const int s = kb & 1;
        const uint32_t Kst = KO + s * 32768;
        const uint32_t Vst = VO + s * 32768;

        __syncthreads();   // stage-s loads visible; prev exp done with TM_S

        // ---- issue S = Q K^T (bf16 3-combo) ----
        if (wid == 0 && elect_one()) {
#pragma unroll
            for (int cb = 0; cb < 3; cb++) {
                uint64_t ad = make_desc_sw128(QO  + (cb == 2 ? 16384u : 0u));
                uint64_t bd = make_desc_sw128(Kst + (cb == 1 ? 16384u : 0u));
#pragma unroll
                for (int ks = 0; ks < 4; ks++)
                    mma_f16_ss(tmem + TM_S, ad + ks * 2, bd + ks * 2,
                               IDESC_S16, !(cb == 0 && ks == 0));
            }
            TC_COMMIT(mbar_s);
        }

        // ---- PV(kb-1) must finish before we overwrite stage s^1 ----
        if (kb > 0) { MBAR_WAIT(mbar_pv, ph_pv); ph_pv ^= 1; }

        // ---- prefetch next K/V tile (overlaps S MMA) ----
        if (kb < qb) {
            const uint32_t Kn = KO + (s ^ 1) * 32768;
            const uint32_t Vn = VO + (s ^ 1) * 32768;
            load_qk_bf16(g_k, (kb + 1) * 128, h, Kn, Kn + 16384, t);
            load_v_bf16(g_v, kb + 1, h, Vn, Vn + 16384, t);
            FENCE_ASYNC_SHARED();
        }

        MBAR_WAIT(mbar_s, ph_s); ph_s ^= 1;
        TC_FENCE_AFTER();

        // ---- exp + mask + bf16 split; P packed as bf16x2 along keys ----
        {
            const int colbase = wg * 64;
            uint32_t sr0[32], sr1[32];
            TC_LD_X32(sr0, tmem + TM_S + colbase);
            TC_LD_X32(sr1, tmem + TM_S + colbase + 32);
            TC_WAIT_LD();
            uint32_t hr[32], lr[32];
#pragma unroll
            for (int j = 0; j < 16; j++) {
                int key0 = kb * 128 + colbase + 2 * j;
                float p0 = (key0     <= qglob) ? __expf(__uint_as_float(sr0[2*j])   - 16.f) : 0.f;
                float p1 = (key0 + 1 <= qglob) ? __expf(__uint_as_float(sr0[2*j+1]) - 16.f) : 0.f;
                lpart += p0 + p1;
                hr[j] = bf16x2_of(p0, p1);
                lr[j] = bf16x2_of(p0 - bf16f(p0), p1 - bf16f(p1));
                int key2 = key0 + 32;
                float q0 = (key2     <= qglob) ? __expf(__uint_as_float(sr1[2*j])   - 16.f) : 0.f;
                float q1 = (key2 + 1 <= qglob) ? __expf(__uint_as_float(sr1[2*j+1]) - 16.f) : 0.f;
                lpart += q0 + q1;
                hr[16 + j] = bf16x2_of(q0, q1);
                lr[16 + j] = bf16x2_of(q0 - bf16f(q0), q1 - bf16f(q1));
            }
            TC_ST_X32(tmem + TM_PH + wg * 32 + (sub << 21), hr);
            TC_ST_X32(tmem + TM_PL + wg * 32 + (sub << 21), lr);
            TC_WAIT_ST();
        }
        TC_FENCE_BEFORE();
        __syncthreads();

        // ---- issue O += P V (TS, bf16 3-combo) ----
        if (wid == 0 && elect_one()) {
            TC_FENCE_AFTER();
#pragma unroll
            for (int cb = 0; cb < 3; cb++) {
                uint32_t pa = tmem + ((cb == 2) ? TM_PL : TM_PH);
                uint32_t vsel = Vst + (cb == 1 ? 16384u : 0u);
#pragma unroll
                for (int kc = 0; kc < 2; kc++) {
                    uint64_t bd = make_desc_sw128(vsel + kc * 8192);
#pragma unroll
                    for (int ks = 0; ks < 4; ks++) {
                        uint32_t en = !(kb == 0 && cb == 0 && kc == 0 && ks == 0);
                        mma_f16_ts(tmem + TM_O, pa + kc * 32 + ks * 8, bd + ks * 2,
                                   IDESC_PV16, en);
                    }
                }
            }
            TC_COMMIT(mbar_pv);
        }
    }

    MBAR_WAIT(mbar_pv, ph_pv);
    TC_FENCE_AFTER();

    s_l[wg * 128 + row] = lpart;
    __syncthreads();

    if (wid < 4) {
        uint32_t orr[64];
        TC_LD_X32(orr, tmem + TM_O);
        TC_LD_X32(orr + 32, tmem + TM_O + 32);
        TC_WAIT_LD();
        TC_FENCE_BEFORE();
        float inv = 1.f / (s_l[row] + s_l[128 + row]);
#pragma unroll
        for (int c4 = 0; c4 < 16; c4++) {
            float4 o;
            o.x = __uint_as_float(orr[c4 * 4 + 0]) * inv;
            o.y = __uint_as_float(orr[c4 * 4 + 1]) * inv;
            o.z = __uint_as_float(orr[c4 * 4 + 2]) * inv;
            o.w = __uint_as_float(orr[c4 * 4 + 3]) * inv;
            *(float4*)&g_ctx[(qb * 128 + row) * DM + h * DK + c4 * 4] = o;
        }
    }
    __syncthreads();
    if (wid == 0) TC_DEALLOC(tmem, 512);

#else  // naive fallback (dead code on GB300; correctness only)
    const int t = threadIdx.x;
    const int qb = (SEQ / 128 - 1) - blockIdx.x;
    const int h = blockIdx.y;
    if (t < 128) {
        int row = qb * 128 + t;
        float l = 0.f, o[DK];
        for (int d = 0; d < DK; d++) o[d] = 0.f;
        for (int key = 0; key <= row; key++) {
            float s = 0.f;
            for (int d = 0; d < DK; d++)
                s += g_q[row * DM + h * DK + d] * g_k[key * DM + h * DK + d];
            float p = __expf(s - 16.f);
            l += p;
            for (int d = 0; d < DK; d++) o[d] += p * g_v[key * DM + h * DK + d];
        }
        for (int d = 0; d < DK; d++) g_ctx[row * DM + h * DK + d] = o[d] / l;
    }
#endif
}

// ---------------------------------------------------------------------------
extern "C" void kernel_launch(void* const* d_in, const int* in_sizes, int n_in,
                              void* d_out, int out_size)
{
    const float* x  = (const float*)d_in[0];
    const float* Wq = (const float*)d_in[1];
    const float* bq = (const float*)d_in[2];
    const float* Wk = (const float*)d_in[3];
    const float* bk = (const float*)d_in[4];
    const float* Wv = (const float*)d_in[5];
    const float* bv = (const float*)d_in[6];
    const float* Wo = (const float*)d_in[7];
    const float* bo = (const float*)d_in[8];
    float* out = (float*)d_out;

    cudaFuncSetAttribute(qkv_tc, cudaFuncAttributeMaxDynamicSharedMemorySize, GEMM_SMEM);
    cudaFuncSetAttribute(out_tc, cudaFuncAttributeMaxDynamicSharedMemorySize, GEMM_SMEM);
    cudaFuncSetAttribute(attn_tc, cudaFuncAttributeMaxDynamicSharedMemorySize, ATT_SMEM);

    qkv_tc<<<dim3(DM / GTN, SEQ / GTM, 3), 128, GEMM_SMEM>>>(x, Wq, bq, Wk, bk, Wv, bv);
    attn_tc<<<dim3(SEQ / 128, NH), 256, ATT_SMEM>>>();
    out_tc<<<dim3(DM / GTN, SEQ / GTM), 128, GEMM_SMEM>>>(Wo, bo, out);
}

// round 6
// speedup vs baseline: 2.9814x; 1.0032x over previous
#include <cuda_runtime.h>
#include <cuda_bf16.h>
#include <math.h>
#include <stdint.h>

#define SEQ 4096
#define DM  768
#define NH  12
#define DK  64

#if defined(__CUDA_ARCH__) && (__CUDA_ARCH__ == 1030) && defined(__CUDA_ARCH_FEAT_SM103_ALL)
#define HAS_TC 1
#else
#define HAS_TC 0
#endif

// q scaled by 0.125*log2(e); softmax p = 2^(s' - EXPC), EXPC = 16*log2(e)
#define QSCALE 0.18033688011112042f
#define EXPC   23.083120654223414f

// Scratch (allocation-free rule: __device__ globals)
__device__ uint16_t g_qh[SEQ * DM], g_ql[SEQ * DM];
__device__ uint16_t g_kh[SEQ * DM], g_kl[SEQ * DM];
__device__ uint16_t g_vh[SEQ * DM], g_vl[SEQ * DM];
__device__ float    g_ctx[SEQ * DM];

// ============================================================================
// Projection GEMM geometry (tf32-split, 256 threads)
// ============================================================================
#define GTM 128
#define GTN 128
#define GKC 32
#define NCHUNK (DM / GKC)
#define TILE_B (GTM * 128)
#define STAGE_B (4 * TILE_B)
#define GEMM_SMEM (1024 + 1024 + 2 * STAGE_B)

// Attention smem: slack + Q(2 tiles x 32K) + K(2 stages x 32K) + V(2 stages x 32K)
#define ATT_SMEM (1024 + 65536 + 65536 + 65536)
// TMEM columns
#define TM_OA  0
#define TM_OB  64
#define TM_S   128
#define TM_PHA 256
#define TM_PLA 320
#define TM_PHB 384
#define TM_PLB 448

#if HAS_TC
// ============================================================================
// PTX helpers (sm_103a feature target only)
// ============================================================================
__device__ __forceinline__ uint32_t smem_u32(const void* p) {
    uint32_t a;
    asm("{ .reg .u64 t; cvta.to.shared.u64 t, %1; cvt.u32.u64 %0, t; }"
        : "=r"(a) : "l"(p));
    return a;
}
__device__ __forceinline__ uint32_t elect_one() {
    uint32_t p;
    asm volatile("{ .reg .pred p; elect.sync _|p, 0xFFFFFFFF; selp.b32 %0, 1, 0, p; }" : "=r"(p));
    return p;
}
#define SW128(off) ((off) ^ (((off) >> 3) & 0x70))

#define MBAR_INIT(addr, cnt) \
    asm volatile("mbarrier.init.shared.b64 [%0], %1;" :: "r"(addr), "r"(cnt) : "memory")

#define MBAR_WAIT(addr, parity) do {                                           \
    asm volatile(                                                              \
        "{\n\t.reg .pred P1;\n\t"                                              \
        "WL_%=:\n\t"                                                           \
        "mbarrier.try_wait.parity.acquire.cta.shared::cta.b64 P1, [%0], %1, 0x989680;\n\t" \
        "@P1 bra.uni WD_%=;\n\t"                                               \
        "bra.uni WL_%=;\n\t"                                                   \
        "WD_%=:\n\t}"                                                          \
        :: "r"(addr), "r"(parity) : "memory");                                 \
} while (0)

#define TC_ALLOC(smem_addr, ncols) \
    asm volatile("tcgen05.alloc.cta_group::1.sync.aligned.shared::cta.b32 [%0], %1;" \
                 :: "r"(smem_addr), "r"(ncols) : "memory")
#define TC_DEALLOC(tmem, ncols) \
    asm volatile("tcgen05.dealloc.cta_group::1.sync.aligned.b32 %0, %1;" :: "r"(tmem), "r"(ncols))
#define TC_RELINQ() \
    asm volatile("tcgen05.relinquish_alloc_permit.cta_group::1.sync.aligned;")
#define TC_COMMIT(mbar) \
    asm volatile("tcgen05.commit.cta_group::1.mbarrier::arrive::one.shared::cluster.b64 [%0];" \
                 :: "r"(mbar) : "memory")
#define TC_FENCE_AFTER()  asm volatile("tcgen05.fence::after_thread_sync;" ::: "memory")
#define TC_FENCE_BEFORE() asm volatile("tcgen05.fence::before_thread_sync;" ::: "memory")
#define TC_WAIT_LD()      asm volatile("tcgen05.wait::ld.sync.aligned;" ::: "memory")
#define TC_WAIT_ST()      asm volatile("tcgen05.wait::st.sync.aligned;" ::: "memory")
#define FENCE_ASYNC_SHARED() asm volatile("fence.proxy.async.shared::cta;" ::: "memory")

#define TC_LD_X32(r, tmem)                                                     \
    asm volatile(                                                              \
        "tcgen05.ld.sync.aligned.32x32b.x32.b32 "                              \
        "{%0, %1, %2, %3, %4, %5, %6, %7, "                                    \
        " %8, %9, %10, %11, %12, %13, %14, %15, "                              \
        " %16, %17, %18, %19, %20, %21, %22, %23, "                            \
        " %24, %25, %26, %27, %28, %29, %30, %31}, [%32];"                     \
        : "=r"((r)[0]),  "=r"((r)[1]),  "=r"((r)[2]),  "=r"((r)[3]),           \
          "=r"((r)[4]),  "=r"((r)[5]),  "=r"((r)[6]),  "=r"((r)[7]),           \
          "=r"((r)[8]),  "=r"((r)[9]),  "=r"((r)[10]), "=r"((r)[11]),          \
          "=r"((r)[12]), "=r"((r)[13]), "=r"((r)[14]), "=r"((r)[15]),          \
          "=r"((r)[16]), "=r"((r)[17]), "=r"((r)[18]), "=r"((r)[19]),          \
          "=r"((r)[20]), "=r"((r)[21]), "=r"((r)[22]), "=r"((r)[23]),          \
          "=r"((r)[24]), "=r"((r)[25]), "=r"((r)[26]), "=r"((r)[27]),          \
          "=r"((r)[28]), "=r"((r)[29]), "=r"((r)[30]), "=r"((r)[31])           \
        : "r"(tmem))

#define TC_ST_X32(tmem, r)                                                     \
    asm volatile(                                                              \
        "tcgen05.st.sync.aligned.32x32b.x32.b32 [%0], "                        \
        "{%1, %2, %3, %4, %5, %6, %7, %8, "                                    \
        " %9, %10, %11, %12, %13, %14, %15, %16, "                             \
        " %17, %18, %19, %20, %21, %22, %23, %24, "                            \
        " %25, %26, %27, %28, %29, %30, %31, %32};"                            \
        :: "r"(tmem),                                                          \
           "r"((r)[0]),  "r"((r)[1]),  "r"((r)[2]),  "r"((r)[3]),              \
           "r"((r)[4]),  "r"((r)[5]),  "r"((r)[6]),  "r"((r)[7]),              \
           "r"((r)[8]),  "r"((r)[9]),  "r"((r)[10]), "r"((r)[11]),             \
           "r"((r)[12]), "r"((r)[13]), "r"((r)[14]), "r"((r)[15]),             \
           "r"((r)[16]), "r"((r)[17]), "r"((r)[18]), "r"((r)[19]),             \
           "r"((r)[20]), "r"((r)[21]), "r"((r)[22]), "r"((r)[23]),             \
           "r"((r)[24]), "r"((r)[25]), "r"((r)[26]), "r"((r)[27]),             \
           "r"((r)[28]), "r"((r)[29]), "r"((r)[30]), "r"((r)[31])              \
        : "memory")

__device__ __forceinline__ uint64_t make_desc_sw128(uint32_t addr) {
    return ((uint64_t)2 << 61) | ((uint64_t)1 << 46) | ((uint64_t)64 << 32)
         | ((uint64_t)1 << 16) | (((uint64_t)(addr >> 4)) & 0x3FFF);
}

__device__ __forceinline__ void mma_tf32_ss(uint32_t d, uint64_t ad, uint64_t bd,
                                            uint32_t idesc, uint32_t en) {
    asm volatile(
        "{\n\t.reg .pred p;\n\tsetp.ne.u32 p, %4, 0;\n\t"
        "tcgen05.mma.cta_group::1.kind::tf32 [%0], %1, %2, %3, p;\n\t}"
        :: "r"(d), "l"(ad), "l"(bd), "r"(idesc), "r"(en) : "memory");
}
__device__ __forceinline__ void mma_f16_ss(uint32_t d, uint64_t ad, uint64_t bd,
                                           uint32_t idesc, uint32_t en) {
    asm volatile(
        "{\n\t.reg .pred p;\n\tsetp.ne.u32 p, %4, 0;\n\t"
        "tcgen05.mma.cta_group::1.kind::f16 [%0], %1, %2, %3, p;\n\t}"
        :: "r"(d), "l"(ad), "l"(bd), "r"(idesc), "r"(en) : "memory");
}
__device__ __forceinline__ void mma_f16_ts(uint32_t d, uint32_t a, uint64_t bd,
                                           uint32_t idesc, uint32_t en) {
    asm volatile(
        "{\n\t.reg .pred p;\n\tsetp.ne.u32 p, %4, 0;\n\t"
        "tcgen05.mma.cta_group::1.kind::f16 [%0], [%1], %2, %3, p;\n\t}"
        :: "r"(d), "r"(a), "l"(bd), "r"(idesc), "r"(en) : "memory");
}

__device__ __forceinline__ float tf32_hi(float x) {
    uint32_t u;
    asm("cvt.rna.tf32.f32 %0, %1;" : "=r"(u) : "f"(x));
    return __uint_as_float(u);
}
__device__ __forceinline__ uint32_t bf16x2_of(float lo, float hi) {
    uint32_t r;
    asm("cvt.rn.bf16x2.f32 %0, %1, %2;" : "=r"(r) : "f"(hi), "f"(lo));
    return r;
}
__device__ __forceinline__ float bf16f(float x) {
    return __bfloat162float(__float2bfloat16(x));
}
__device__ __forceinline__ float ex2f(float x) {
    float r;
    asm("ex2.approx.ftz.f32 %0, %1;" : "=f"(r) : "f"(x));
    return r;
}
__device__ __forceinline__ uint32_t prmt(uint32_t a, uint32_t b, uint32_t sel) {
    uint32_t r;
    asm("prmt.b32 %0, %1, %2, %3;" : "=r"(r) : "r"(a), "r"(b), "r"(sel));
    return r;
}

#define IDESC_TF32  ((1u << 4) | (2u << 7) | (2u << 10) | ((GTN / 8) << 17) | ((GTM / 16) << 24))
#define IDESC_S16   ((1u << 4) | (1u << 7) | (1u << 10) | (16u << 17) | (8u << 24))  /* M=128 N=128 */
#define IDESC_PV16  ((1u << 4) | (1u << 7) | (1u << 10) | (8u << 17)  | (8u << 24))  /* M=128 N=64 */

// ============================================================================
// Projection GEMM (split-tf32 SS, 256 threads)
// ============================================================================
__device__ __forceinline__ void load_split(const float* __restrict__ src,
                                           int row0, int k0,
                                           uint32_t hi_t, uint32_t lo_t, int t)
{
#pragma unroll
    for (int i = 0; i < 4; i++) {
        int idx = i * 256 + t;
        int r = idx >> 3, c4 = idx & 7;
        float4 v = *(const float4*)&src[(row0 + r) * DM + k0 + c4 * 4];
        float4 h, l;
        h.x = tf32_hi(v.x); l.x = v.x - h.x;
        h.y = tf32_hi(v.y); l.y = v.y - h.y;
        h.z = tf32_hi(v.z); l.z = v.z - h.z;
        h.w = tf32_hi(v.w); l.w = v.w - h.w;
        uint32_t off = SW128((uint32_t)(r * 128 + c4 * 16));
        asm volatile("st.shared.v4.b32 [%0], {%1,%2,%3,%4};" ::
            "r"(hi_t + off), "r"(__float_as_uint(h.x)), "r"(__float_as_uint(h.y)),
            "r"(__float_as_uint(h.z)), "r"(__float_as_uint(h.w)) : "memory");
        asm volatile("st.shared.v4.b32 [%0], {%1,%2,%3,%4};" ::
            "r"(lo_t + off), "r"(__float_as_uint(l.x)), "r"(__float_as_uint(l.y)),
            "r"(__float_as_uint(l.z)), "r"(__float_as_uint(l.w)) : "memory");
    }
}

// outHi/outLo non-null -> bf16 hi/lo split output; else fp32 to outF.
__device__ __forceinline__ void gemm_body(const float* __restrict__ A,
                                          const float* __restrict__ W,
                                          const float* __restrict__ bias,
                                          uint16_t* __restrict__ outHi,
                                          uint16_t* __restrict__ outLo,
                                          float* __restrict__ outF,
                                          float scale)
{
    extern __shared__ char smraw[];
    const uint32_t base = (smem_u32(smraw) + 1023) & ~1023u;
    const uint32_t mbar0 = base + 8, mbar1 = base + 16;
    const uint32_t tiles = base + 1024;

    const int t   = threadIdx.x;
    const int wid = t >> 5, lid = t & 31;
    const int m0  = blockIdx.y * GTM;
    const int n0  = blockIdx.x * GTN;

    if (wid == 0) { TC_ALLOC(base, 128); TC_RELINQ(); }
    if (t == 0) { MBAR_INIT(mbar0, 1); MBAR_INIT(mbar1, 1); }
    __syncthreads();
    uint32_t tmem;
    asm volatile("ld.shared.b32 %0, [%1];" : "=r"(tmem) : "r"(base));

    int ph0 = 0, ph1 = 0;

    for (int c = 0; c < NCHUNK; c++) {
        const int s = c & 1;
        const uint32_t st = tiles + s * STAGE_B;
        const uint32_t aHi = st, aLo = st + TILE_B, bHi = st + 2 * TILE_B, bLo = st + 3 * TILE_B;

        if (c >= 2) {
            if (s == 0) { MBAR_WAIT(mbar0, ph0); ph0 ^= 1; }
            else        { MBAR_WAIT(mbar1, ph1); ph1 ^= 1; }
        }

        load_split(A, m0, c * GKC, aHi, aLo, t);
        load_split(W, n0, c * GKC, bHi, bLo, t);

        FENCE_ASYNC_SHARED();
        __syncthreads();

        if (wid == 0 && elect_one()) {
            uint64_t dA[2] = { make_desc_sw128(aHi), make_desc_sw128(aLo) };
            uint64_t dB[2] = { make_desc_sw128(bHi), make_desc_sw128(bLo) };
#pragma unroll
            for (int cb = 0; cb < 3; cb++) {
                uint64_t ad = dA[cb == 2 ? 1 : 0];
                uint64_t bd = dB[cb == 1 ? 1 : 0];
#pragma unroll
                for (int ks = 0; ks < 4; ks++) {
                    uint32_t en = !(c == 0 && cb == 0 && ks == 0);
                    mma_tf32_ss(tmem, ad + ks * 2, bd + ks * 2, IDESC_TF32, en);
                }
            }
            TC_COMMIT(s == 0 ? mbar0 : mbar1);
        }
    }

    MBAR_WAIT(mbar0, ph0);
    MBAR_WAIT(mbar1, ph1);
    TC_FENCE_AFTER();

    // epilogue: 8 warps, warp covers rows (wid&3)*32, cols (wid>>2)*64
    const int colhalf = (wid >> 2) * 64;
    const int m = m0 + (wid & 3) * 32 + lid;
    uint32_t dr[64];
    TC_LD_X32(dr,      tmem + colhalf);
    TC_LD_X32(dr + 32, tmem + colhalf + 32);
    TC_WAIT_LD();
    TC_FENCE_BEFORE();

    if (outHi) {
#pragma unroll
        for (int c4 = 0; c4 < 16; c4++) {
            int n = n0 + colhalf + c4 * 4;
            float v0 = (__uint_as_float(dr[c4 * 4 + 0]) + bias[n + 0]) * scale;
            float v1 = (__uint_as_float(dr[c4 * 4 + 1]) + bias[n + 1]) * scale;
            float v2 = (__uint_as_float(dr[c4 * 4 + 2]) + bias[n + 2]) * scale;
            float v3 = (__uint_as_float(dr[c4 * 4 + 3]) + bias[n + 3]) * scale;
            uint2 hw, lw;
            hw.x = bf16x2_of(v0, v1);
            hw.y = bf16x2_of(v2, v3);
            lw.x = bf16x2_of(v0 - bf16f(v0), v1 - bf16f(v1));
            lw.y = bf16x2_of(v2 - bf16f(v2), v3 - bf16f(v3));
            *(uint2*)&outHi[m * DM + n] = hw;
            *(uint2*)&outLo[m * DM + n] = lw;
        }
    } else {
#pragma unroll
        for (int c4 = 0; c4 < 16; c4++) {
            int n = n0 + colhalf + c4 * 4;
            float4 o;
            o.x = (__uint_as_float(dr[c4 * 4 + 0]) + bias[n + 0]) * scale;
            o.y = (__uint_as_float(dr[c4 * 4 + 1]) + bias[n + 1]) * scale;
            o.z = (__uint_as_float(dr[c4 * 4 + 2]) + bias[n + 2]) * scale;
            o.w = (__uint_as_float(dr[c4 * 4 + 3]) + bias[n + 3]) * scale;
            *(float4*)&outF[m * DM + n] = o;
        }
    }

    __syncthreads();
    if (wid == 0) TC_DEALLOC(tmem, 128);
}

// ---- attention copy loaders (pure copies, bf16 already split) ----
// [128 rows][64 bf16] tile -> SW128 smem (128B rows)
__device__ __forceinline__ void copy_tile(const uint16_t* __restrict__ src,
                                          int row0, int h, uint32_t dst, int t)
{
#pragma unroll
    for (int i = 0; i < 4; i++) {
        int idx = i * 256 + t;
        int r = idx >> 3, c = idx & 7;
        uint4 v = *(const uint4*)&src[(row0 + r) * DM + h * DK + c * 8];
        uint32_t off = SW128((uint32_t)(r * 128 + c * 16));
        asm volatile("st.shared.v4.b32 [%0], {%1,%2,%3,%4};" ::
            "r"(dst + off), "r"(v.x), "r"(v.y), "r"(v.z), "r"(v.w) : "memory");
    }
}

// V transposed: 2 chunks [64 dv][64 keys bf16] (keys packed bf16x2)
__device__ __forceinline__ void copy_vt(const uint16_t* __restrict__ src,
                                        int kb, int h, uint32_t dst, int t)
{
#pragma unroll
    for (int i = 0; i < 4; i++) {
        int idx = i * 256 + t;
        int u = idx & 63, g = idx >> 6;     // key pair u, dv group g (4 dims)
        const uint16_t* p0 = &src[(kb * 128 + 2 * u) * DM + h * DK + g * 4];
        uint2 a = *(const uint2*)p0;
        uint2 b = *(const uint2*)(p0 + DM);
        int kc = u >> 5, up = u & 31;
        uint32_t cbase = dst + kc * 8192;
        uint32_t w0 = prmt(a.x, b.x, 0x5410), w1 = prmt(a.x, b.x, 0x7632);
        uint32_t w2 = prmt(a.y, b.y, 0x5410), w3 = prmt(a.y, b.y, 0x7632);
        asm volatile("st.shared.b32 [%0], %1;" :: "r"(cbase + SW128((uint32_t)((g * 4 + 0) * 128 + up * 4))), "r"(w0) : "memory");
        asm volatile("st.shared.b32 [%0], %1;" :: "r"(cbase + SW128((uint32_t)((g * 4 + 1) * 128 + up * 4))), "r"(w1) : "memory");
        asm volatile("st.shared.b32 [%0], %1;" :: "r"(cbase + SW128((uint32_t)((g * 4 + 2) * 128 + up * 4))), "r"(w2) : "memory");
        asm volatile("st.shared.b32 [%0], %1;" :: "r"(cbase + SW128((uint32_t)((g * 4 + 3) * 128 + up * 4))), "r"(w3) : "memory");
    }
}

__device__ __forceinline__ void issue_S(uint32_t tmem, uint32_t Qbase, uint32_t Kst)
{
#pragma unroll
    for (int cb = 0; cb < 3; cb++) {
        uint64_t ad = make_desc_sw128(Qbase + (cb == 2 ? 16384u : 0u));
        uint64_t bd = make_desc_sw128(Kst   + (cb == 1 ? 16384u : 0u));
#pragma unroll
        for (int ks = 0; ks < 4; ks++)
            mma_f16_ss(tmem + TM_S, ad + ks * 2, bd + ks * 2,
                       IDESC_S16, !(cb == 0 && ks == 0));
    }
}

__device__ __forceinline__ void issue_PV(uint32_t tmem, int oCol, int phCol, int plCol,
                                         uint32_t Vst, int first)
{
#pragma unroll
    for (int cb = 0; cb < 3; cb++) {
        uint32_t pa = tmem + (cb == 2 ? plCol : phCol);
        uint32_t vsel = Vst + (cb == 1 ? 16384u : 0u);
#pragma unroll
        for (int kc = 0; kc < 2; kc++) {
            uint64_t bd = make_desc_sw128(vsel + kc * 8192);
#pragma unroll
            for (int ks = 0; ks < 4; ks++) {
                uint32_t en = !(first && cb == 0 && kc == 0 && ks == 0);
                mma_f16_ts(tmem + oCol, pa + kc * 32 + ks * 8, bd + ks * 2,
                           IDESC_PV16, en);
            }
        }
    }
}

__device__ __forceinline__ void exp_phase(uint32_t tmem, int wg, int sub, int kb,
                                          int qglob, int phCol, int plCol, float& lpart)
{
    const int colbase = wg * 64;
    uint32_t sr0[32], sr1[32];
    TC_LD_X32(sr0, tmem + TM_S + colbase);
    TC_LD_X32(sr1, tmem + TM_S + colbase + 32);
    TC_WAIT_LD();
    uint32_t hr[32], lr[32];
#pragma unroll
    for (int j = 0; j < 16; j++) {
        int key0 = kb * 128 + colbase + 2 * j;
        float p0 = (key0     <= qglob) ? ex2f(__uint_as_float(sr0[2*j])   - EXPC) : 0.f;
        float p1 = (key0 + 1 <= qglob) ? ex2f(__uint_as_float(sr0[2*j+1]) - EXPC) : 0.f;
        lpart += p0 + p1;
        hr[j] = bf16x2_of(p0, p1);
        lr[j] = bf16x2_of(p0 - bf16f(p0), p1 - bf16f(p1));
        int key2 = key0 + 32;
        float q0 = (key2     <= qglob) ? ex2f(__uint_as_float(sr1[2*j])   - EXPC) : 0.f;
        float q1 = (key2 + 1 <= qglob) ? ex2f(__uint_as_float(sr1[2*j+1]) - EXPC) : 0.f;
        lpart += q0 + q1;
        hr[16 + j] = bf16x2_of(q0, q1);
        lr[16 + j] = bf16x2_of(q0 - bf16f(q0), q1 - bf16f(q1));
    }
    TC_ST_X32(tmem + phCol + wg * 32 + (sub << 21), hr);
    TC_ST_X32(tmem + plCol + wg * 32 + (sub << 21), lr);
    TC_WAIT_ST();
}
#else  // !HAS_TC fallback GEMM (dead code on GB300)
__device__ __forceinline__ void gemm_body(const float* __restrict__ A,
                                          const float* __restrict__ W,
                                          const float* __restrict__ bias,
                                          uint16_t* __restrict__ outHi,
                                          uint16_t* __restrict__ outLo,
                                          float* __restrict__ outF,
                                          float scale)
{
    extern __shared__ char smraw[];
    float* Ws = (float*)smraw;
    float* As = (float*)smraw + GKC * 128;

    const int t  = threadIdx.x;
    const int m0 = blockIdx.y * GTM;
    const int n0 = blockIdx.x * GTN;
    const int tr = (t >> 4) * 8;
    const int tc = (t & 15) * 8;

    float acc[8][8] = {};
    for (int k0 = 0; k0 < DM; k0 += GKC) {
        __syncthreads();
        for (int idx = t; idx < GKC * 128 / 4; idx += 256) {
            int r = (idx * 4) >> 5, k4 = (idx * 4) & 31;
            float4 wv = *(const float4*)&W[(n0 + r) * DM + k0 + k4];
            Ws[(k4 + 0) * 128 + r] = wv.x; Ws[(k4 + 1) * 128 + r] = wv.y;
            Ws[(k4 + 2) * 128 + r] = wv.z; Ws[(k4 + 3) * 128 + r] = wv.w;
            float4 av = *(const float4*)&A[(m0 + r) * DM + k0 + k4];
            As[(k4 + 0) * 128 + r] = av.x; As[(k4 + 1) * 128 + r] = av.y;
            As[(k4 + 2) * 128 + r] = av.z; As[(k4 + 3) * 128 + r] = av.w;
        }
        __syncthreads();
        for (int k = 0; k < GKC; k++) {
            float a_[8], b_[8];
#pragma unroll
            for (int i = 0; i < 8; i++) a_[i] = As[k * 128 + tr + i];
#pragma unroll
            for (int j = 0; j < 8; j++) b_[j] = Ws[k * 128 + tc + j];
#pragma unroll
            for (int i = 0; i < 8; i++)
#pragma unroll
                for (int j = 0; j < 8; j++) acc[i][j] += a_[i] * b_[j];
        }
    }
#pragma unroll
    for (int i = 0; i < 8; i++)
#pragma unroll
        for (int j = 0; j < 8; j++) {
            float v = (acc[i][j] + bias[n0 + tc + j]) * scale;
            int idx = (m0 + tr + i) * DM + n0 + tc + j;
            if (outHi) {
                __nv_bfloat16 hb = __float2bfloat16(v);
                float hv = __bfloat162float(hb);
                __nv_bfloat16 lb = __float2bfloat16(v - hv);
                outHi[idx] = *(uint16_t*)&hb;
                outLo[idx] = *(uint16_t*)&lb;
            } else {
                outF[idx] = v;
            }
        }
}
#endif  // HAS_TC

__global__ __launch_bounds__(256) void qkv_tc(
    const float* __restrict__ x,
    const float* __restrict__ Wq, const float* __restrict__ bq,
    const float* __restrict__ Wk, const float* __restrict__ bk,
    const float* __restrict__ Wv, const float* __restrict__ bv)
{
    int w = blockIdx.z;
    if (w == 0)      gemm_body(x, Wq, bq, g_qh, g_ql, 0, QSCALE);
    else if (w == 1) gemm_body(x, Wk, bk, g_kh, g_kl, 0, 1.0f);
    else             gemm_body(x, Wv, bv, g_vh, g_vl, 0, 1.0f);
}

__global__ __launch_bounds__(256) void out_tc(
    const float* __restrict__ Wo, const float* __restrict__ bo,
    float* __restrict__ out)
{
    gemm_body(g_ctx, Wo, bo, 0, 0, out, 1.0f);
}

// ============================================================================
// tcgen05 flash attention: paired q-tiles (qbA = bid, qbB = 31-bid),
// bf16 hi/lo, fixed-max softmax via ex2, double-buffered K/V copy loaders.
// ============================================================================
__global__ __launch_bounds__(256) void attn_tc()
{
#if HAS_TC
    extern __shared__ char smraw[];
    __shared__ uint64_t s_bar[3];
    __shared__ uint32_t s_tptr;
    __shared__ float s_lA[256], s_lB[256];

    const uint32_t base = (smem_u32(smraw) + 1023) & ~1023u;
    const uint32_t QO = base;               // QA hi/lo (32K), QB hi/lo (32K)
    const uint32_t KO = base + 65536;       // stage s: KH 16K | KL 16K
    const uint32_t VO = base + 131072;      // stage s: VH 16K (2x8K) | VL 16K
    const uint32_t mbar_s1  = smem_u32(&s_bar[0]);
    const uint32_t mbar_s2  = smem_u32(&s_bar[1]);
    const uint32_t mbar_pvB = smem_u32(&s_bar[2]);
    const uint32_t tptr_a   = smem_u32(&s_tptr);

    const int t    = threadIdx.x;
    const int wid  = t >> 5, lane = t & 31;
    const int sub  = wid & 3, wg = wid >> 2;
    const int qbA  = blockIdx.x;                 // 0..15
    const int qbB  = (SEQ / 128 - 1) - qbA;      // 31..16
    const int h    = blockIdx.y;
    const int row  = sub * 32 + lane;
    const int qgA  = qbA * 128 + row;
    const int qgB  = qbB * 128 + row;

    if (wid == 0) { TC_ALLOC(tptr_a, 512); TC_RELINQ(); }
    if (t == 0) { MBAR_INIT(mbar_s1, 1); MBAR_INIT(mbar_s2, 1); MBAR_INIT(mbar_pvB, 1); }
    __syncthreads();
    uint32_t tmem;
    asm volatile("ld.shared.b32 %0, [%1];" : "=r"(tmem) : "r"(tptr_a));

    // preload both Q tiles + K/V stage 0
    copy_tile(g_qh, qbA * 128, h, QO, t);
    copy_tile(g_ql, qbA * 128, h, QO + 16384, t);
    copy_tile(g_qh, qbB * 128, h, QO + 32768, t);
    copy_tile(g_ql, qbB * 128, h, QO + 49152, t);
    copy_tile(g_kh, 0, h, KO, t);
    copy_tile(g_kl, 0, h, KO + 16384, t);
    copy_vt(g_vh, 0, h, VO, t);
    copy_vt(g_vl, 0, h, VO + 16384, t);
    FENCE_ASYNC_SHARED();

    float lpartA = 0.f, lpartB = 0.f;
    int ph_s1 = 0, ph_s2 = 0, ph_pvB = 0;

    for (int kb = 0; kb <= qbB; kb++) {
        const int s = kb & 1;
        const uint32_t Kst = KO + s * 32768;
        const uint32_t Vst = VO + s * 32768;
        const int dual = (kb <= qbA);

        __syncthreads();   // stage-s loads visible; TM_S free (prior exp done)

        // issue S for first tile (A if dual else B)
        if (wid == 0 && elect_one()) {
            issue_S(tmem, dual ? QO : QO + 32768, Kst);
            TC_COMMIT(mbar_s1);
        }

        // drain PV(kb-1) before reusing stage s^1 / P regions
        if (kb > 0) { MBAR_WAIT(mbar_pvB, ph_pvB); ph_pvB ^= 1; }

        // prefetch next K/V tile (overlaps S MMA)
        if (kb < qbB) {
            const uint32_t Kn = KO + (s ^ 1) * 32768;
            const uint32_t Vn = VO + (s ^ 1) * 32768;
            copy_tile(g_kh, (kb + 1) * 128, h, Kn, t);
            copy_tile(g_kl, (kb + 1) * 128, h, Kn + 16384, t);
            copy_vt(g_vh, kb + 1, h, Vn, t);
            copy_vt(g_vl, kb + 1, h, Vn + 16384, t);
            FENCE_ASYNC_SHARED();
        }

        MBAR_WAIT(mbar_s1, ph_s1); ph_s1 ^= 1;
        TC_FENCE_AFTER();

        // exp for first tile
        if (dual) exp_phase(tmem, wg, sub, kb, qgA, TM_PHA, TM_PLA, lpartA);
        else      exp_phase(tmem, wg, sub, kb, qgB, TM_PHB, TM_PLB, lpartB);
        TC_FENCE_BEFORE();
        __syncthreads();

        if (wid == 0 && elect_one()) {
            TC_FENCE_AFTER();
            if (dual) {
                issue_PV(tmem, TM_OA, TM_PHA, TM_PLA, Vst, kb == 0);
                issue_S(tmem, QO + 32768, Kst);     // S for tile B
                TC_COMMIT(mbar_s2);
            } else {
                issue_PV(tmem, TM_OB, TM_PHB, TM_PLB, Vst, 0);
                TC_COMMIT(mbar_pvB);
            }
        }

        if (dual) {
            MBAR_WAIT(mbar_s2, ph_s2); ph_s2 ^= 1;
            TC_FENCE_AFTER();
            exp_phase(tmem, wg, sub, kb, qgB, TM_PHB, TM_PLB, lpartB);
            TC_FENCE_BEFORE();
            __syncthreads();
            if (wid == 0 && elect_one()) {
                TC_FENCE_AFTER();
                issue_PV(tmem, TM_OB, TM_PHB, TM_PLB, Vst, kb == 0);
                TC_COMMIT(mbar_pvB);
            }
        }
    }

    MBAR_WAIT(mbar_pvB, ph_pvB);
    TC_FENCE_AFTER();

    s_lA[wg * 128 + row] = lpartA;
    s_lB[wg * 128 + row] = lpartB;
    __syncthreads();

    // epilogue: 8 warps; warp covers O cols wg*32..wg*32+31 of its subpartition rows
    {
        uint32_t orr[32];
        float invA = 1.f / (s_lA[row] + s_lA[128 + row]);
        TC_LD_X32(orr, tmem + TM_OA + wg * 32);
        TC_WAIT_LD();
#pragma unroll
        for (int c4 = 0; c4 < 8; c4++) {
            float4 o;
            o.x = __uint_as_float(orr[c4 * 4 + 0]) * invA;
            o.y = __uint_as_float(orr[c4 * 4 + 1]) * invA;
            o.z = __uint_as_float(orr[c4 * 4 + 2]) * invA;
            o.w = __uint_as_float(orr[c4 * 4 + 3]) * invA;
            *(float4*)&g_ctx[(qbA * 128 + row) * DM + h * DK + wg * 32 + c4 * 4] = o;
        }
        float invB = 1.f / (s_lB[row] + s_lB[128 + row]);
        TC_LD_X32(orr, tmem + TM_OB + wg * 32);
        TC_WAIT_LD();
#pragma unroll
        for (int c4 = 0; c4 < 8; c4++) {
            float4 o;
            o.x = __uint_as_float(orr[c4 * 4 + 0]) * invB;
            o.y = __uint_as_float(orr[c4 * 4 + 1]) * invB;
            o.z = __uint_as_float(orr[c4 * 4 + 2]) * invB;
            o.w = __uint_as_float(orr[c4 * 4 + 3]) * invB;
            *(float4*)&g_ctx[(qbB * 128 + row) * DM + h * DK + wg * 32 + c4 * 4] = o;
        }
        TC_FENCE_BEFORE();
    }
    __syncthreads();
    if (wid == 0) TC_DEALLOC(tmem, 512);

#else  // naive fallback (dead code on GB300; correctness only)
    const int t = threadIdx.x;
    const int qbA = blockIdx.x, qbB = (SEQ / 128 - 1) - qbA;
    const int h = blockIdx.y;
    int row = (t < 128) ? (qbA * 128 + t) : (qbB * 128 + (t - 128));
    float l = 0.f, o[DK];
    for (int d = 0; d < DK; d++) o[d] = 0.f;
    for (int key = 0; key <= row; key++) {
        float s = 0.f;
        for (int d = 0; d < DK; d++) {
            float qv = __bfloat162float(*(__nv_bfloat16*)&g_qh[row * DM + h * DK + d])
                     + __bfloat162float(*(__nv_bfloat16*)&g_ql[row * DM + h * DK + d]);
            float kv = __bfloat162float(*(__nv_bfloat16*)&g_kh[key * DM + h * DK + d])
                     + __bfloat162float(*(__nv_bfloat16*)&g_kl[key * DM + h * DK + d]);
            s += qv * kv;
        }
        float p = exp2f(s - EXPC);
        l += p;
        for (int d = 0; d < DK; d++) {
            float vv = __bfloat162float(*(__nv_bfloat16*)&g_vh[key * DM + h * DK + d])
                     + __bfloat162float(*(__nv_bfloat16*)&g_vl[key * DM + h * DK + d]);
            o[d] += p * vv;
        }
    }
    for (int d = 0; d < DK; d++) g_ctx[row * DM + h * DK + d] = o[d] / l;
#endif
}

// ---------------------------------------------------------------------------
extern "C" void kernel_launch(void* const* d_in, const int* in_sizes, int n_in,
                              void* d_out, int out_size)
{
    const float* x  = (const float*)d_in[0];
    const float* Wq = (const float*)d_in[1];
    const float* bq = (const float*)d_in[2];
    const float* Wk = (const float*)d_in[3];
    const float* bk = (const float*)d_in[4];
    const float* Wv = (const float*)d_in[5];
    const float* bv = (const float*)d_in[6];
    const float* Wo = (const float*)d_in[7];
    const float* bo = (const float*)d_in[8];
    float* out = (float*)d_out;

    cudaFuncSetAttribute(qkv_tc, cudaFuncAttributeMaxDynamicSharedMemorySize, GEMM_SMEM);
    cudaFuncSetAttribute(out_tc, cudaFuncAttributeMaxDynamicSharedMemorySize, GEMM_SMEM);
    cudaFuncSetAttribute(attn_tc, cudaFuncAttributeMaxDynamicSharedMemorySize, ATT_SMEM);

    qkv_tc<<<dim3(DM / GTN, SEQ / GTM, 3), 256, GEMM_SMEM>>>(x, Wq, bq, Wk, bk, Wv, bv);
    attn_tc<<<dim3(SEQ / 256, NH), 256, ATT_SMEM>>>();
    out_tc<<<dim3(DM / GTN, SEQ / GTM), 256, GEMM_SMEM>>>(Wo, bo, out);
}

// round 7
// speedup vs baseline: 4.3507x; 1.4593x over previous
#include <cuda_runtime.h>
#include <cuda_bf16.h>
#include <math.h>
#include <stdint.h>

#define SEQ 4096
#define DM  768
#define NH  12
#define DK  64

#if defined(__CUDA_ARCH__) && (__CUDA_ARCH__ == 1030) && defined(__CUDA_ARCH_FEAT_SM103_ALL)
#define HAS_TC 1
#else
#define HAS_TC 0
#endif

// q scaled by 0.125*log2(e); softmax p = 2^(s' - EXPC), EXPC = 16*log2(e)
#define QSCALE 0.18033688011112042f
#define EXPC   23.083120654223414f

// Scratch (allocation-free rule: __device__ globals)
__device__ uint16_t g_qh[SEQ * DM], g_ql[SEQ * DM];
__device__ uint16_t g_kh[SEQ * DM], g_kl[SEQ * DM];
__device__ uint16_t g_vth[DM * SEQ], g_vtl[DM * SEQ];   // V transposed [dim][seq]
__device__ float    g_ctx[SEQ * DM];

// ============================================================================
// Projection GEMM geometry (tf32-split, 256 threads)
// ============================================================================
#define GTM 128
#define GTN 128
#define GKC 32
#define NCHUNK (DM / GKC)
#define TILE_B (GTM * 128)
#define STAGE_B (4 * TILE_B)
#define GEMM_SMEM (1024 + 1024 + 2 * STAGE_B)

// Attention smem: slack + Q(2 tiles x 32K) + K(2 stages x 32K) + V(2 stages x 32K)
#define ATT_SMEM (1024 + 3 * 65536)
#define ATH 512                  /* attention threads */
// TMEM columns
#define TM_OA 0
#define TM_OB 64
#define TM_S1 128
#define TM_S2 256
#define TM_PH 384
#define TM_PL 448

#if HAS_TC
// ============================================================================
// PTX helpers (sm_103a feature target only)
// ============================================================================
__device__ __forceinline__ uint32_t smem_u32(const void* p) {
    uint32_t a;
    asm("{ .reg .u64 t; cvta.to.shared.u64 t, %1; cvt.u32.u64 %0, t; }"
        : "=r"(a) : "l"(p));
    return a;
}
__device__ __forceinline__ uint32_t elect_one() {
    uint32_t p;
    asm volatile("{ .reg .pred p; elect.sync _|p, 0xFFFFFFFF; selp.b32 %0, 1, 0, p; }" : "=r"(p));
    return p;
}
#define SW128(off) ((off) ^ (((off) >> 3) & 0x70))

#define MBAR_INIT(addr, cnt) \
    asm volatile("mbarrier.init.shared.b64 [%0], %1;" :: "r"(addr), "r"(cnt) : "memory")

#define MBAR_WAIT(addr, parity) do {                                           \
    asm volatile(                                                              \
        "{\n\t.reg .pred P1;\n\t"                                              \
        "WL_%=:\n\t"                                                           \
        "mbarrier.try_wait.parity.acquire.cta.shared::cta.b64 P1, [%0], %1, 0x989680;\n\t" \
        "@P1 bra.uni WD_%=;\n\t"                                               \
        "bra.uni WL_%=;\n\t"                                                   \
        "WD_%=:\n\t}"                                                          \
        :: "r"(addr), "r"(parity) : "memory");                                 \
} while (0)

#define TC_ALLOC(smem_addr, ncols) \
    asm volatile("tcgen05.alloc.cta_group::1.sync.aligned.shared::cta.b32 [%0], %1;" \
                 :: "r"(smem_addr), "r"(ncols) : "memory")
#define TC_DEALLOC(tmem, ncols) \
    asm volatile("tcgen05.dealloc.cta_group::1.sync.aligned.b32 %0, %1;" :: "r"(tmem), "r"(ncols))
#define TC_RELINQ() \
    asm volatile("tcgen05.relinquish_alloc_permit.cta_group::1.sync.aligned;")
#define TC_COMMIT(mbar) \
    asm volatile("tcgen05.commit.cta_group::1.mbarrier::arrive::one.shared::cluster.b64 [%0];" \
                 :: "r"(mbar) : "memory")
#define TC_FENCE_AFTER()  asm volatile("tcgen05.fence::after_thread_sync;" ::: "memory")
#define TC_FENCE_BEFORE() asm volatile("tcgen05.fence::before_thread_sync;" ::: "memory")
#define TC_WAIT_LD()      asm volatile("tcgen05.wait::ld.sync.aligned;" ::: "memory")
#define TC_WAIT_ST()      asm volatile("tcgen05.wait::st.sync.aligned;" ::: "memory")
#define FENCE_ASYNC_SHARED() asm volatile("fence.proxy.async.shared::cta;" ::: "memory")

#define TC_LD_X32(r, tmem)                                                     \
    asm volatile(                                                              \
        "tcgen05.ld.sync.aligned.32x32b.x32.b32 "                              \
        "{%0, %1, %2, %3, %4, %5, %6, %7, "                                    \
        " %8, %9, %10, %11, %12, %13, %14, %15, "                              \
        " %16, %17, %18, %19, %20, %21, %22, %23, "                            \
        " %24, %25, %26, %27, %28, %29, %30, %31}, [%32];"                     \
        : "=r"((r)[0]),  "=r"((r)[1]),  "=r"((r)[2]),  "=r"((r)[3]),           \
          "=r"((r)[4]),  "=r"((r)[5]),  "=r"((r)[6]),  "=r"((r)[7]),           \
          "=r"((r)[8]),  "=r"((r)[9]),  "=r"((r)[10]), "=r"((r)[11]),          \
          "=r"((r)[12]), "=r"((r)[13]), "=r"((r)[14]), "=r"((r)[15]),          \
          "=r"((r)[16]), "=r"((r)[17]), "=r"((r)[18]), "=r"((r)[19]),          \
          "=r"((r)[20]), "=r"((r)[21]), "=r"((r)[22]), "=r"((r)[23]),          \
          "=r"((r)[24]), "=r"((r)[25]), "=r"((r)[26]), "=r"((r)[27]),          \
          "=r"((r)[28]), "=r"((r)[29]), "=r"((r)[30]), "=r"((r)[31])           \
        : "r"(tmem))

#define TC_LD_X16(r, tmem)                                                     \
    asm volatile(                                                              \
        "tcgen05.ld.sync.aligned.32x32b.x16.b32 "                              \
        "{%0, %1, %2, %3, %4, %5, %6, %7, "                                    \
        " %8, %9, %10, %11, %12, %13, %14, %15}, [%16];"                       \
        : "=r"((r)[0]),  "=r"((r)[1]),  "=r"((r)[2]),  "=r"((r)[3]),           \
          "=r"((r)[4]),  "=r"((r)[5]),  "=r"((r)[6]),  "=r"((r)[7]),           \
          "=r"((r)[8]),  "=r"((r)[9]),  "=r"((r)[10]), "=r"((r)[11]),          \
          "=r"((r)[12]), "=r"((r)[13]), "=r"((r)[14]), "=r"((r)[15])           \
        : "r"(tmem))

#define TC_ST_X16(tmem, r)                                                     \
    asm volatile(                                                              \
        "tcgen05.st.sync.aligned.32x32b.x16.b32 [%0], "                        \
        "{%1, %2, %3, %4, %5, %6, %7, %8, "                                    \
        " %9, %10, %11, %12, %13, %14, %15, %16};"                             \
        :: "r"(tmem),                                                          \
           "r"((r)[0]),  "r"((r)[1]),  "r"((r)[2]),  "r"((r)[3]),              \
           "r"((r)[4]),  "r"((r)[5]),  "r"((r)[6]),  "r"((r)[7]),              \
           "r"((r)[8]),  "r"((r)[9]),  "r"((r)[10]), "r"((r)[11]),             \
           "r"((r)[12]), "r"((r)[13]), "r"((r)[14]), "r"((r)[15])              \
        : "memory")

__device__ __forceinline__ uint64_t make_desc_sw128(uint32_t addr) {
    return ((uint64_t)2 << 61) | ((uint64_t)1 << 46) | ((uint64_t)64 << 32)
         | ((uint64_t)1 << 16) | (((uint64_t)(addr >> 4)) & 0x3FFF);
}

__device__ __forceinline__ void mma_tf32_ss(uint32_t d, uint64_t ad, uint64_t bd,
                                            uint32_t idesc, uint32_t en) {
    asm volatile(
        "{\n\t.reg .pred p;\n\tsetp.ne.u32 p, %4, 0;\n\t"
        "tcgen05.mma.cta_group::1.kind::tf32 [%0], %1, %2, %3, p;\n\t}"
        :: "r"(d), "l"(ad), "l"(bd), "r"(idesc), "r"(en) : "memory");
}
__device__ __forceinline__ void mma_f16_ss(uint32_t d, uint64_t ad, uint64_t bd,
                                           uint32_t idesc, uint32_t en) {
    asm volatile(
        "{\n\t.reg .pred p;\n\tsetp.ne.u32 p, %4, 0;\n\t"
        "tcgen05.mma.cta_group::1.kind::f16 [%0], %1, %2, %3, p;\n\t}"
        :: "r"(d), "l"(ad), "l"(bd), "r"(idesc), "r"(en) : "memory");
}
__device__ __forceinline__ void mma_f16_ts(uint32_t d, uint32_t a, uint64_t bd,
                                           uint32_t idesc, uint32_t en) {
    asm volatile(
        "{\n\t.reg .pred p;\n\tsetp.ne.u32 p, %4, 0;\n\t"
        "tcgen05.mma.cta_group::1.kind::f16 [%0], [%1], %2, %3, p;\n\t}"
        :: "r"(d), "r"(a), "l"(bd), "r"(idesc), "r"(en) : "memory");
}

__device__ __forceinline__ float tf32_hi(float x) {
    uint32_t u;
    asm("cvt.rna.tf32.f32 %0, %1;" : "=r"(u) : "f"(x));
    return __uint_as_float(u);
}
__device__ __forceinline__ uint32_t bf16x2_of(float lo, float hi) {
    uint32_t r;
    asm("cvt.rn.bf16x2.f32 %0, %1, %2;" : "=r"(r) : "f"(hi), "f"(lo));
    return r;
}
__device__ __forceinline__ float bf16f(float x) {
    return __bfloat162float(__float2bfloat16(x));
}
__device__ __forceinline__ float ex2f(float x) {
    float r;
    asm("ex2.approx.ftz.f32 %0, %1;" : "=f"(r) : "f"(x));
    return r;
}
__device__ __forceinline__ uint32_t prmt(uint32_t a, uint32_t b, uint32_t sel) {
    uint32_t r;
    asm("prmt.b32 %0, %1, %2, %3;" : "=r"(r) : "r"(a), "r"(b), "r"(sel));
    return r;
}

#define IDESC_TF32  ((1u << 4) | (2u << 7) | (2u << 10) | ((GTN / 8) << 17) | ((GTM / 16) << 24))
#define IDESC_S16   ((1u << 4) | (1u << 7) | (1u << 10) | (16u << 17) | (8u << 24))  /* M=128 N=128 */
#define IDESC_PV16  ((1u << 4) | (1u << 7) | (1u << 10) | (8u << 17)  | (8u << 24))  /* M=128 N=64 */

// ============================================================================
// Projection GEMM (split-tf32 SS, 256 threads). vmode: V writes transposed
// bf16 hi/lo to g_vth/g_vtl; outHi mode writes bf16 hi/lo row-major; else fp32.
// ============================================================================
__device__ __forceinline__ void load_split(const float* __restrict__ src,
                                           int row0, int k0,
                                           uint32_t hi_t, uint32_t lo_t, int t)
{
#pragma unroll
    for (int i = 0; i < 4; i++) {
        int idx = i * 256 + t;
        int r = idx >> 3, c4 = idx & 7;
        float4 v = *(const float4*)&src[(row0 + r) * DM + k0 + c4 * 4];
        float4 h, l;
        h.x = tf32_hi(v.x); l.x = v.x - h.x;
        h.y = tf32_hi(v.y); l.y = v.y - h.y;
        h.z = tf32_hi(v.z); l.z = v.z - h.z;
        h.w = tf32_hi(v.w); l.w = v.w - h.w;
        uint32_t off = SW128((uint32_t)(r * 128 + c4 * 16));
        asm volatile("st.shared.v4.b32 [%0], {%1,%2,%3,%4};" ::
            "r"(hi_t + off), "r"(__float_as_uint(h.x)), "r"(__float_as_uint(h.y)),
            "r"(__float_as_uint(h.z)), "r"(__float_as_uint(h.w)) : "memory");
        asm volatile("st.shared.v4.b32 [%0], {%1,%2,%3,%4};" ::
            "r"(lo_t + off), "r"(__float_as_uint(l.x)), "r"(__float_as_uint(l.y)),
            "r"(__float_as_uint(l.z)), "r"(__float_as_uint(l.w)) : "memory");
    }
}

__device__ __forceinline__ void gemm_body(const float* __restrict__ A,
                                          const float* __restrict__ W,
                                          const float* __restrict__ bias,
                                          uint16_t* __restrict__ outHi,
                                          uint16_t* __restrict__ outLo,
                                          float* __restrict__ outF,
                                          float scale, int vmode)
{
    extern __shared__ char smraw[];
    const uint32_t base = (smem_u32(smraw) + 1023) & ~1023u;
    const uint32_t mbar0 = base + 8, mbar1 = base + 16;
    const uint32_t tiles = base + 1024;

    const int t   = threadIdx.x;
    const int wid = t >> 5, lid = t & 31;
    const int m0  = blockIdx.y * GTM;
    const int n0  = blockIdx.x * GTN;

    if (wid == 0) { TC_ALLOC(base, 128); TC_RELINQ(); }
    if (t == 0) { MBAR_INIT(mbar0, 1); MBAR_INIT(mbar1, 1); }
    __syncthreads();
    uint32_t tmem;
    asm volatile("ld.shared.b32 %0, [%1];" : "=r"(tmem) : "r"(base));

    int ph0 = 0, ph1 = 0;

    for (int c = 0; c < NCHUNK; c++) {
        const int s = c & 1;
        const uint32_t st = tiles + s * STAGE_B;
        const uint32_t aHi = st, aLo = st + TILE_B, bHi = st + 2 * TILE_B, bLo = st + 3 * TILE_B;

        if (c >= 2) {
            if (s == 0) { MBAR_WAIT(mbar0, ph0); ph0 ^= 1; }
            else        { MBAR_WAIT(mbar1, ph1); ph1 ^= 1; }
        }

        load_split(A, m0, c * GKC, aHi, aLo, t);
        load_split(W, n0, c * GKC, bHi, bLo, t);

        FENCE_ASYNC_SHARED();
        __syncthreads();

        if (wid == 0 && elect_one()) {
            uint64_t dA[2] = { make_desc_sw128(aHi), make_desc_sw128(aLo) };
            uint64_t dB[2] = { make_desc_sw128(bHi), make_desc_sw128(bLo) };
#pragma unroll
            for (int cb = 0; cb < 3; cb++) {
                uint64_t ad = dA[cb == 2 ? 1 : 0];
                uint64_t bd = dB[cb == 1 ? 1 : 0];
#pragma unroll
                for (int ks = 0; ks < 4; ks++) {
                    uint32_t en = !(c == 0 && cb == 0 && ks == 0);
                    mma_tf32_ss(tmem, ad + ks * 2, bd + ks * 2, IDESC_TF32, en);
                }
            }
            TC_COMMIT(s == 0 ? mbar0 : mbar1);
        }
    }

    MBAR_WAIT(mbar0, ph0);
    MBAR_WAIT(mbar1, ph1);
    TC_FENCE_AFTER();

    // epilogue: 8 warps, warp covers rows (wid&3)*32, cols (wid>>2)*64
    const int colhalf = (wid >> 2) * 64;
    const int mloc = (wid & 3) * 32 + lid;
    const int m = m0 + mloc;
    uint32_t dr[64];
    TC_LD_X32(dr,      tmem + colhalf);
    TC_LD_X32(dr + 32, tmem + colhalf + 32);
    TC_WAIT_LD();
    TC_FENCE_BEFORE();

    if (vmode) {
        // transpose via smem (tiles region is dead): padded row stride 130 u16
        uint32_t smh = tiles, sml = tiles + 33280;
#pragma unroll
        for (int c4 = 0; c4 < 16; c4++) {
            int n = n0 + colhalf + c4 * 4;
            float v0 = (__uint_as_float(dr[c4 * 4 + 0]) + bias[n + 0]);
            float v1 = (__uint_as_float(dr[c4 * 4 + 1]) + bias[n + 1]);
            float v2 = (__uint_as_float(dr[c4 * 4 + 2]) + bias[n + 2]);
            float v3 = (__uint_as_float(dr[c4 * 4 + 3]) + bias[n + 3]);
            uint32_t a0 = (uint32_t)(mloc * 130 + colhalf + c4 * 4) * 2;
            asm volatile("st.shared.b32 [%0], %1;" :: "r"(smh + a0),     "r"(bf16x2_of(v0, v1)) : "memory");
            asm volatile("st.shared.b32 [%0], %1;" :: "r"(smh + a0 + 4), "r"(bf16x2_of(v2, v3)) : "memory");
            float l0 = v0 - bf16f(v0), l1 = v1 - bf16f(v1);
            float l2 = v2 - bf16f(v2), l3 = v3 - bf16f(v3);
            asm volatile("st.shared.b32 [%0], %1;" :: "r"(sml + a0),     "r"(bf16x2_of(l0, l1)) : "memory");
            asm volatile("st.shared.b32 [%0], %1;" :: "r"(sml + a0 + 4), "r"(bf16x2_of(l2, l3)) : "memory");
        }
        __syncthreads();
        // phase 2: thread -> dim d = t>>1, rows half*64..+63, coalesced STG
        const int d = t >> 1, half = t & 1;
#pragma unroll
        for (int rg = 0; rg < 8; rg++) {
            int r0 = half * 64 + rg * 8;
            uint32_t w[4], wl[4];
#pragma unroll
            for (int j = 0; j < 4; j++) {
                uint32_t ah, bh, al, bl;
                uint32_t adr0 = (uint32_t)((r0 + 2 * j) * 130 + d) * 2;
                uint32_t adr1 = (uint32_t)((r0 + 2 * j + 1) * 130 + d) * 2;
                asm volatile("ld.shared.u16 %0, [%1];" : "=r"(ah) : "r"(smh + adr0));
                asm volatile("ld.shared.u16 %0, [%1];" : "=r"(bh) : "r"(smh + adr1));
                asm volatile("ld.shared.u16 %0, [%1];" : "=r"(al) : "r"(sml + adr0));
                asm volatile("ld.shared.u16 %0, [%1];" : "=r"(bl) : "r"(sml + adr1));
                w[j]  = ah | (bh << 16);
                wl[j] = al | (bl << 16);
            }
            *(uint4*)&g_vth[(n0 + d) * SEQ + m0 + r0] = make_uint4(w[0], w[1], w[2], w[3]);
            *(uint4*)&g_vtl[(n0 + d) * SEQ + m0 + r0] = make_uint4(wl[0], wl[1], wl[2], wl[3]);
        }
    } else if (outHi) {
#pragma unroll
        for (int c4 = 0; c4 < 16; c4++) {
            int n = n0 + colhalf + c4 * 4;
            float v0 = (__uint_as_float(dr[c4 * 4 + 0]) + bias[n + 0]) * scale;
            float v1 = (__uint_as_float(dr[c4 * 4 + 1]) + bias[n + 1]) * scale;
            float v2 = (__uint_as_float(dr[c4 * 4 + 2]) + bias[n + 2]) * scale;
            float v3 = (__uint_as_float(dr[c4 * 4 + 3]) + bias[n + 3]) * scale;
            uint2 hw, lw;
            hw.x = bf16x2_of(v0, v1);
            hw.y = bf16x2_of(v2, v3);
            lw.x = bf16x2_of(v0 - bf16f(v0), v1 - bf16f(v1));
            lw.y = bf16x2_of(v2 - bf16f(v2), v3 - bf16f(v3));
            *(uint2*)&outHi[m * DM + n] = hw;
            *(uint2*)&outLo[m * DM + n] = lw;
        }
    } else {
#pragma unroll
        for (int c4 = 0; c4 < 16; c4++) {
            int n = n0 + colhalf + c4 * 4;
            float4 o;
            o.x = (__uint_as_float(dr[c4 * 4 + 0]) + bias[n + 0]) * scale;
            o.y = (__uint_as_float(dr[c4 * 4 + 1]) + bias[n + 1]) * scale;
            o.z = (__uint_as_float(dr[c4 * 4 + 2]) + bias[n + 2]) * scale;
            o.w = (__uint_as_float(dr[c4 * 4 + 3]) + bias[n + 3]) * scale;
            *(float4*)&outF[m * DM + n] = o;
        }
    }

    __syncthreads();
    if (wid == 0) TC_DEALLOC(tmem, 128);
}

// ---- attention copy loaders (ATH=512 threads) ----
// [128 rows][64 bf16] tile -> SW128 smem (128B rows)
__device__ __forceinline__ void copy_tile(const uint16_t* __restrict__ src,
                                          int row0, int h, uint32_t dst, int t)
{
#pragma unroll
    for (int i = 0; i < 2; i++) {
        int idx = i * ATH + t;
        int r = idx >> 3, c = idx & 7;
        uint4 v = *(const uint4*)&src[(row0 + r) * DM + h * DK + c * 8];
        uint32_t off = SW128((uint32_t)(r * 128 + c * 16));
        asm volatile("st.shared.v4.b32 [%0], {%1,%2,%3,%4};" ::
            "r"(dst + off), "r"(v.x), "r"(v.y), "r"(v.z), "r"(v.w) : "memory");
    }
}

// V transposed global [dim][seq] -> 2 smem chunks [64 dv][64 keys] (coalesced)
__device__ __forceinline__ void copy_vt(const uint16_t* __restrict__ src,
                                        int kb, int h, uint32_t dst, int t)
{
#pragma unroll
    for (int i = 0; i < 2; i++) {
        int idx = i * ATH + t;
        int dv = idx >> 4, g = idx & 15;
        uint4 v = *(const uint4*)&src[(h * DK + dv) * SEQ + kb * 128 + g * 8];
        int kc = g >> 3;
        uint32_t off = SW128((uint32_t)(dv * 128 + (g & 7) * 16));
        asm volatile("st.shared.v4.b32 [%0], {%1,%2,%3,%4};" ::
            "r"(dst + kc * 8192 + off), "r"(v.x), "r"(v.y), "r"(v.z), "r"(v.w) : "memory");
    }
}

__device__ __forceinline__ void issue_S(uint32_t tmem, int sCol, uint32_t Qbase, uint32_t Kst)
{
#pragma unroll
    for (int cb = 0; cb < 3; cb++) {
        uint64_t ad = make_desc_sw128(Qbase + (cb == 2 ? 16384u : 0u));
        uint64_t bd = make_desc_sw128(Kst   + (cb == 1 ? 16384u : 0u));
#pragma unroll
        for (int ks = 0; ks < 4; ks++)
            mma_f16_ss(tmem + sCol, ad + ks * 2, bd + ks * 2,
                       IDESC_S16, !(cb == 0 && ks == 0));
    }
}

__device__ __forceinline__ void issue_PV(uint32_t tmem, int oCol, uint32_t Vst, int first)
{
#pragma unroll
    for (int cb = 0; cb < 3; cb++) {
        uint32_t pa = tmem + (cb == 2 ? TM_PL : TM_PH);
        uint32_t vsel = Vst + (cb == 1 ? 16384u : 0u);
#pragma unroll
        for (int kc = 0; kc < 2; kc++) {
            uint64_t bd = make_desc_sw128(vsel + kc * 8192);
#pragma unroll
            for (int ks = 0; ks < 4; ks++) {
                uint32_t en = !(first && cb == 0 && kc == 0 && ks == 0);
                mma_f16_ts(tmem + oCol, pa + kc * 32 + ks * 8, bd + ks * 2,
                           IDESC_PV16, en);
            }
        }
    }
}

// exp over this warp-group's 32 S columns -> hr/lr (16 bf16x2 pairs)
__device__ __forceinline__ void exp_compute(uint32_t tmem, int sCol, int wg,
                                            int kb, int qglob,
                                            uint32_t* hr, uint32_t* lr, float& lpart)
{
    uint32_t sr[32];
    TC_LD_X32(sr, tmem + sCol + wg * 32);
    TC_WAIT_LD();
#pragma unroll
    for (int j = 0; j < 16; j++) {
        int key0 = kb * 128 + wg * 32 + 2 * j;
        float p0 = (key0     <= qglob) ? ex2f(__uint_as_float(sr[2*j])   - EXPC) : 0.f;
        float p1 = (key0 + 1 <= qglob) ? ex2f(__uint_as_float(sr[2*j+1]) - EXPC) : 0.f;
        lpart += p0 + p1;
        uint32_t b0 = __float_as_uint(p0), b1 = __float_as_uint(p1);
        hr[j] = prmt(b0, b1, 0x7632);           // [trunc(p0), trunc(p1)]
        float h0 = __uint_as_float(b0 & 0xFFFF0000u);
        float h1 = __uint_as_float(b1 & 0xFFFF0000u);
        lr[j] = bf16x2_of(p0 - h0, p1 - h1);
    }
}
#else  // !HAS_TC fallback GEMM (dead code on GB300)
__device__ __forceinline__ void gemm_body(const float* __restrict__ A,
                                          const float* __restrict__ W,
                                          const float* __restrict__ bias,
                                          uint16_t* __restrict__ outHi,
                                          uint16_t* __restrict__ outLo,
                                          float* __restrict__ outF,
                                          float scale, int vmode)
{
    extern __shared__ char smraw[];
    float* Ws = (float*)smraw;
    float* As = (float*)smraw + GKC * 128;

    const int t  = threadIdx.x;
    const int m0 = blockIdx.y * GTM;
    const int n0 = blockIdx.x * GTN;
    const int tr = (t >> 4) * 8;
    const int tc = (t & 15) * 8;

    float acc[8][8] = {};
    for (int k0 = 0; k0 < DM; k0 += GKC) {
        __syncthreads();
        for (int idx = t; idx < GKC * 128 / 4; idx += 256) {
            int r = (idx * 4) >> 5, k4 = (idx * 4) & 31;
            float4 wv = *(const float4*)&W[(n0 + r) * DM + k0 + k4];
            Ws[(k4 + 0) * 128 + r] = wv.x; Ws[(k4 + 1) * 128 + r] = wv.y;
            Ws[(k4 + 2) * 128 + r] = wv.z; Ws[(k4 + 3) * 128 + r] = wv.w;
            float4 av = *(const float4*)&A[(m0 + r) * DM + k0 + k4];
            As[(k4 + 0) * 128 + r] = av.x; As[(k4 + 1) * 128 + r] = av.y;
            As[(k4 + 2) * 128 + r] = av.z; As[(k4 + 3) * 128 + r] = av.w;
        }
        __syncthreads();
        for (int k = 0; k < GKC; k++) {
            float a_[8], b_[8];
#pragma unroll
            for (int i = 0; i < 8; i++) a_[i] = As[k * 128 + tr + i];
#pragma unroll
            for (int j = 0; j < 8; j++) b_[j] = Ws[k * 128 + tc + j];
#pragma unroll
            for (int i = 0; i < 8; i++)
#pragma unroll
                for (int j = 0; j < 8; j++) acc[i][j] += a_[i] * b_[j];
        }
    }
#pragma unroll
    for (int i = 0; i < 8; i++)
#pragma unroll
        for (int j = 0; j < 8; j++) {
            float v = (acc[i][j] + bias[n0 + tc + j]) * scale;
            int mi = m0 + tr + i, ni = n0 + tc + j;
            __nv_bfloat16 hb = __float2bfloat16(v);
            float hv = __bfloat162float(hb);
            __nv_bfloat16 lb = __float2bfloat16(v - hv);
            if (vmode) {
                g_vth[ni * SEQ + mi] = *(uint16_t*)&hb;
                g_vtl[ni * SEQ + mi] = *(uint16_t*)&lb;
            } else if (outHi) {
                outHi[mi * DM + ni] = *(uint16_t*)&hb;
                outLo[mi * DM + ni] = *(uint16_t*)&lb;
            } else {
                outF[mi * DM + ni] = v;
            }
        }
}
#endif  // HAS_TC

__global__ __launch_bounds__(256) void qkv_tc(
    const float* __restrict__ x,
    const float* __restrict__ Wq, const float* __restrict__ bq,
    const float* __restrict__ Wk, const float* __restrict__ bk,
    const float* __restrict__ Wv, const float* __restrict__ bv)
{
    int w = blockIdx.z;
    if (w == 0)      gemm_body(x, Wq, bq, g_qh, g_ql, 0, QSCALE, 0);
    else if (w == 1) gemm_body(x, Wk, bk, g_kh, g_kl, 0, 1.0f, 0);
    else             gemm_body(x, Wv, bv, 0, 0, 0, 1.0f, 1);
}

__global__ __launch_bounds__(256) void out_tc(
    const float* __restrict__ Wo, const float* __restrict__ bo,
    float* __restrict__ out)
{
    gemm_body(g_ctx, Wo, bo, 0, 0, out, 1.0f, 0);
}

// ============================================================================
// tcgen05 flash attention: paired q-tiles, S double-buffered in TMEM,
// single P buffer, 512 threads, coalesced loaders, fixed-max softmax.
// ============================================================================
__global__ __launch_bounds__(ATH) void attn_tc()
{
#if HAS_TC
    extern __shared__ char smraw[];
    __shared__ uint64_t s_bar[3];
    __shared__ uint32_t s_tptr;
    __shared__ float s_lA[ATH], s_lB[ATH];

    const uint32_t base = (smem_u32(smraw) + 1023) & ~1023u;
    const uint32_t QO = base;               // QA hi/lo (32K), QB hi/lo (32K)
    const uint32_t KO = base + 65536;       // stage s: KH 16K | KL 16K
    const uint32_t VO = base + 131072;      // stage s: VH 16K (2x8K) | VL 16K
    const uint32_t mbar_s1 = smem_u32(&s_bar[0]);
    const uint32_t mbar_s2 = smem_u32(&s_bar[1]);
    const uint32_t mbar_pv = smem_u32(&s_bar[2]);
    const uint32_t tptr_a  = smem_u32(&s_tptr);

    const int t    = threadIdx.x;
    const int wid  = t >> 5, lane = t & 31;
    const int sub  = wid & 3, wg = wid >> 2;          // wg 0..3
    const int qbA  = blockIdx.x;                      // 0..15
    const int qbB  = (SEQ / 128 - 1) - qbA;           // 31..16
    const int h    = blockIdx.y;
    const int row  = sub * 32 + lane;
    const int qgA  = qbA * 128 + row;
    const int qgB  = qbB * 128 + row;

    if (wid == 0) { TC_ALLOC(tptr_a, 512); TC_RELINQ(); }
    if (t == 0) { MBAR_INIT(mbar_s1, 1); MBAR_INIT(mbar_s2, 1); MBAR_INIT(mbar_pv, 1); }
    __syncthreads();
    uint32_t tmem;
    asm volatile("ld.shared.b32 %0, [%1];" : "=r"(tmem) : "r"(tptr_a));

    // preload both Q tiles + K/V stage 0
    copy_tile(g_qh, qbA * 128, h, QO, t);
    copy_tile(g_ql, qbA * 128, h, QO + 16384, t);
    copy_tile(g_qh, qbB * 128, h, QO + 32768, t);
    copy_tile(g_ql, qbB * 128, h, QO + 49152, t);
    copy_tile(g_kh, 0, h, KO, t);
    copy_tile(g_kl, 0, h, KO + 16384, t);
    copy_vt(g_vth, 0, h, VO, t);
    copy_vt(g_vtl, 0, h, VO + 16384, t);
    FENCE_ASYNC_SHARED();

    float lpartA = 0.f, lpartB = 0.f;
    int ph1 = 0, ph2 = 0, php = 0;

    for (int kb = 0; kb <= qbB; kb++) {
        const int s = kb & 1;
        const uint32_t Kst = KO + s * 32768;
        const uint32_t Vst = VO + s * 32768;
        const int dual = (kb <= qbA);

        __syncthreads();   // stage loads visible; S1/S2 free (prior LDTMs done)

        // issue S MMAs for both tiles up-front (overlap with exp below)
        if (wid == 0 && elect_one()) {
            issue_S(tmem, TM_S1, dual ? QO : QO + 32768, Kst);
            TC_COMMIT(mbar_s1);
            if (dual) {
                issue_S(tmem, TM_S2, QO + 32768, Kst);
                TC_COMMIT(mbar_s2);
            }
        }

        // PV(s) of kb-1 done before overwriting stage s^1 / P
        if (kb > 0) { MBAR_WAIT(mbar_pv, php); php ^= 1; }

        // prefetch next K/V tile (overlaps S MMAs)
        if (kb < qbB) {
            const uint32_t Kn = KO + (s ^ 1) * 32768;
            const uint32_t Vn = VO + (s ^ 1) * 32768;
            copy_tile(g_kh, (kb + 1) * 128, h, Kn, t);
            copy_tile(g_kl, (kb + 1) * 128, h, Kn + 16384, t);
            copy_vt(g_vth, kb + 1, h, Vn, t);
            copy_vt(g_vtl, kb + 1, h, Vn + 16384, t);
            FENCE_ASYNC_SHARED();
        }

        // ---- first tile (A if dual else B) ----
        MBAR_WAIT(mbar_s1, ph1); ph1 ^= 1;
        TC_FENCE_AFTER();
        {
            uint32_t hr[16], lr[16];
            if (dual) exp_compute(tmem, TM_S1, wg, kb, qgA, hr, lr, lpartA);
            else      exp_compute(tmem, TM_S1, wg, kb, qgB, hr, lr, lpartB);
            TC_ST_X16(tmem + TM_PH + wg * 16 + (sub << 21), hr);
            TC_ST_X16(tmem + TM_PL + wg * 16 + (sub << 21), lr);
            TC_WAIT_ST();
        }
        TC_FENCE_BEFORE();
        __syncthreads();
        if (wid == 0 && elect_one()) {
            TC_FENCE_AFTER();
            issue_PV(tmem, dual ? TM_OA : TM_OB, Vst, kb == 0);
            TC_COMMIT(mbar_pv);
        }

        // ---- second tile (B), dual only ----
        if (dual) {
            MBAR_WAIT(mbar_s2, ph2); ph2 ^= 1;
            TC_FENCE_AFTER();
            uint32_t hr[16], lr[16];
            exp_compute(tmem, TM_S2, wg, kb, qgB, hr, lr, lpartB);
            MBAR_WAIT(mbar_pv, php); php ^= 1;   // PV_A done -> P free
            TC_FENCE_AFTER();
            TC_ST_X16(tmem + TM_PH + wg * 16 + (sub << 21), hr);
            TC_ST_X16(tmem + TM_PL + wg * 16 + (sub << 21), lr);
            TC_WAIT_ST();
            TC_FENCE_BEFORE();
            __syncthreads();
            if (wid == 0 && elect_one()) {
                TC_FENCE_AFTER();
                issue_PV(tmem, TM_OB, Vst, kb == 0);
                TC_COMMIT(mbar_pv);
            }
        }
    }

    MBAR_WAIT(mbar_pv, php);
    TC_FENCE_AFTER();

    s_lA[wg * 128 + row] = lpartA;
    s_lB[wg * 128 + row] = lpartB;
    __syncthreads();

    // epilogue: 16 warps; warp covers O cols wg*16..+15 of its subpartition rows
    {
        uint32_t orr[16];
        float invA = 1.f / (s_lA[row] + s_lA[128 + row] + s_lA[256 + row] + s_lA[384 + row]);
        TC_LD_X16(orr, tmem + TM_OA + wg * 16);
        TC_WAIT_LD();
#pragma unroll
        for (int c4 = 0; c4 < 4; c4++) {
            float4 o;
            o.x = __uint_as_float(orr[c4 * 4 + 0]) * invA;
            o.y = __uint_as_float(orr[c4 * 4 + 1]) * invA;
            o.z = __uint_as_float(orr[c4 * 4 + 2]) * invA;
            o.w = __uint_as_float(orr[c4 * 4 + 3]) * invA;
            *(float4*)&g_ctx[(qbA * 128 + row) * DM + h * DK + wg * 16 + c4 * 4] = o;
        }
        float invB = 1.f / (s_lB[row] + s_lB[128 + row] + s_lB[256 + row] + s_lB[384 + row]);
        TC_LD_X16(orr, tmem + TM_OB + wg * 16);
        TC_WAIT_LD();
#pragma unroll
        for (int c4 = 0; c4 < 4; c4++) {
            float4 o;
            o.x = __uint_as_float(orr[c4 * 4 + 0]) * invB;
            o.y = __uint_as_float(orr[c4 * 4 + 1]) * invB;
            o.z = __uint_as_float(orr[c4 * 4 + 2]) * invB;
            o.w = __uint_as_float(orr[c4 * 4 + 3]) * invB;
            *(float4*)&g_ctx[(qbB * 128 + row) * DM + h * DK + wg * 16 + c4 * 4] = o;
        }
        TC_FENCE_BEFORE();
    }
    __syncthreads();
    if (wid == 0) TC_DEALLOC(tmem, 512);

#else  // naive fallback (dead code on GB300; correctness only)
    const int t = threadIdx.x;
    const int qbA = blockIdx.x, qbB = (SEQ / 128 - 1) - qbA;
    const int h = blockIdx.y;
    if (t < 256) {
        int row = (t < 128) ? (qbA * 128 + t) : (qbB * 128 + (t - 128));
        float l = 0.f, o[DK];
        for (int d = 0; d < DK; d++) o[d] = 0.f;
        for (int key = 0; key <= row; key++) {
            float s = 0.f;
            for (int d = 0; d < DK; d++) {
                float qv = __bfloat162float(*(__nv_bfloat16*)&g_qh[row * DM + h * DK + d])
                         + __bfloat162float(*(__nv_bfloat16*)&g_ql[row * DM + h * DK + d]);
                float kv = __bfloat162float(*(__nv_bfloat16*)&g_kh[key * DM + h * DK + d])
                         + __bfloat162float(*(__nv_bfloat16*)&g_kl[key * DM + h * DK + d]);
                s += qv * kv;
            }
            float p = exp2f(s - EXPC);
            l += p;
            for (int d = 0; d < DK; d++) {
                float vv = __bfloat162float(*(__nv_bfloat16*)&g_vth[(h * DK + d) * SEQ + key])
                         + __bfloat162float(*(__nv_bfloat16*)&g_vtl[(h * DK + d) * SEQ + key]);
                o[d] += p * vv;
            }
        }
        for (int d = 0; d < DK; d++) g_ctx[row * DM + h * DK + d] = o[d] / l;
    }
#endif
}

// ---------------------------------------------------------------------------
extern "C" void kernel_launch(void* const* d_in, const int* in_sizes, int n_in,
                              void* d_out, int out_size)
{
    const float* x  = (const float*)d_in[0];
    const float* Wq = (const float*)d_in[1];
    const float* bq = (const float*)d_in[2];
    const float* Wk = (const float*)d_in[3];
    const float* bk = (const float*)d_in[4];
    const float* Wv = (const float*)d_in[5];
    const float* bv = (const float*)d_in[6];
    const float* Wo = (const float*)d_in[7];
    const float* bo = (const float*)d_in[8];
    float* out = (float*)d_out;

    cudaFuncSetAttribute(qkv_tc, cudaFuncAttributeMaxDynamicSharedMemorySize, GEMM_SMEM);
    cudaFuncSetAttribute(out_tc, cudaFuncAttributeMaxDynamicSharedMemorySize, GEMM_SMEM);
    cudaFuncSetAttribute(attn_tc, cudaFuncAttributeMaxDynamicSharedMemorySize, ATT_SMEM);

    qkv_tc<<<dim3(DM / GTN, SEQ / GTM, 3), 256, GEMM_SMEM>>>(x, Wq, bq, Wk, bk, Wv, bv);
    attn_tc<<<dim3(SEQ / 256, NH), ATH, ATT_SMEM>>>();
    out_tc<<<dim3(DM / GTN, SEQ / GTM), 256, GEMM_SMEM>>>(Wo, bo, out);
}

// round 8
// speedup vs baseline: 4.9906x; 1.1471x over previous
#include <cuda_runtime.h>
#include <cuda_bf16.h>
#include <math.h>
#include <stdint.h>

#define SEQ 4096
#define DM  768
#define NH  12
#define DK  64

#if defined(__CUDA_ARCH__) && (__CUDA_ARCH__ == 1030) && defined(__CUDA_ARCH_FEAT_SM103_ALL)
#define HAS_TC 1
#else
#define HAS_TC 0
#endif

// q scaled by 0.125*log2(e); softmax p = 2^(s' - EXPC), EXPC = 16*log2(e)
#define QSCALE 0.18033688011112042f
#define EXPC   23.083120654223414f

// Scratch (allocation-free rule: __device__ globals)
__device__ uint16_t g_xh[SEQ * DM], g_xl[SEQ * DM];          // x split
__device__ uint16_t g_wh[4 * DM * DM], g_wl[4 * DM * DM];    // Wq,Wk,Wv,Wo split
__device__ uint16_t g_qh[SEQ * DM], g_ql[SEQ * DM];
__device__ uint16_t g_kh[SEQ * DM], g_kl[SEQ * DM];
__device__ uint16_t g_vth[DM * SEQ], g_vtl[DM * SEQ];        // V transposed [dim][seq]
__device__ uint16_t g_ctxh[SEQ * DM], g_ctxl[SEQ * DM];

// ============================================================================
// bf16 copy-GEMM geometry (256 threads)
// ============================================================================
#define BKC 64                               /* K per chunk (bf16, 128B rows) */
#define NCH16 (DM / BKC)                     /* 12 */
#define TILE16 16384                         /* 128 rows x 128 B */
#define STAGE16 (4 * TILE16)                 /* ah, al, bh, bl */
#define GEMM_SMEM (1024 + 1024 + 2 * STAGE16)

// Attention smem: slack + Q(2 tiles x 32K) + K(2 stages x 32K) + V(2 stages x 32K)
#define ATT_SMEM (1024 + 3 * 65536)
#define ATH 512
// TMEM columns
#define TM_OA 0
#define TM_OB 64
#define TM_S1 128
#define TM_S2 256
#define TM_PH 384
#define TM_PL 448

// ---------------- common helpers (safe on all targets) ----------------
__device__ __forceinline__ uint32_t bf16x2_of(float lo, float hi) {
    uint32_t r;
    asm("cvt.rn.bf16x2.f32 %0, %1, %2;" : "=r"(r) : "f"(hi), "f"(lo));
    return r;
}
__device__ __forceinline__ float bf16f(float x) {
    return __bfloat162float(__float2bfloat16(x));
}

// ============================================================================
// Prepass: split x and W into bf16 hi/lo (one LDG.128 + 2 STG.64 per 4 elems)
// ============================================================================
#define X4   (SEQ * DM / 4)          /* 786432 */
#define W4   (DM * DM / 4)           /* 147456 */
#define PREP_TOT (X4 + 4 * W4)       /* 1376256 */

__global__ __launch_bounds__(256) void prep_split(
    const float* __restrict__ x,
    const float* __restrict__ Wq, const float* __restrict__ Wk,
    const float* __restrict__ Wv, const float* __restrict__ Wo)
{
    int idx = blockIdx.x * 256 + threadIdx.x;
    if (idx >= PREP_TOT) return;
    const float* src;
    uint16_t *dh, *dl;
    int off;
    if (idx < X4) {
        src = x; dh = g_xh; dl = g_xl; off = idx;
    } else {
        int r = idx - X4;
        int w = r / W4;
        off = r - w * W4;
        src = (w == 0) ? Wq : (w == 1) ? Wk : (w == 2) ? Wv : Wo;
        dh = g_wh + w * (DM * DM);
        dl = g_wl + w * (DM * DM);
    }
    float4 v = *(const float4*)&src[off * 4];
    uint2 hw, lw;
    hw.x = bf16x2_of(v.x, v.y);
    hw.y = bf16x2_of(v.z, v.w);
    lw.x = bf16x2_of(v.x - bf16f(v.x), v.y - bf16f(v.y));
    lw.y = bf16x2_of(v.z - bf16f(v.z), v.w - bf16f(v.w));
    *(uint2*)&dh[off * 4] = hw;
    *(uint2*)&dl[off * 4] = lw;
}

#if HAS_TC
// ============================================================================
// PTX helpers (sm_103a feature target only)
// ============================================================================
__device__ __forceinline__ uint32_t smem_u32(const void* p) {
    uint32_t a;
    asm("{ .reg .u64 t; cvta.to.shared.u64 t, %1; cvt.u32.u64 %0, t; }"
        : "=r"(a) : "l"(p));
    return a;
}
__device__ __forceinline__ uint32_t elect_one() {
    uint32_t p;
    asm volatile("{ .reg .pred p; elect.sync _|p, 0xFFFFFFFF; selp.b32 %0, 1, 0, p; }" : "=r"(p));
    return p;
}
#define SW128(off) ((off) ^ (((off) >> 3) & 0x70))

#define MBAR_INIT(addr, cnt) \
    asm volatile("mbarrier.init.shared.b64 [%0], %1;" :: "r"(addr), "r"(cnt) : "memory")

#define MBAR_WAIT(addr, parity) do {                                           \
    asm volatile(                                                              \
        "{\n\t.reg .pred P1;\n\t"                                              \
        "WL_%=:\n\t"                                                           \
        "mbarrier.try_wait.parity.acquire.cta.shared::cta.b64 P1, [%0], %1, 0x989680;\n\t" \
        "@P1 bra.uni WD_%=;\n\t"                                               \
        "bra.uni WL_%=;\n\t"                                                   \
        "WD_%=:\n\t}"                                                          \
        :: "r"(addr), "r"(parity) : "memory");                                 \
} while (0)

#define TC_ALLOC(smem_addr, ncols) \
    asm volatile("tcgen05.alloc.cta_group::1.sync.aligned.shared::cta.b32 [%0], %1;" \
                 :: "r"(smem_addr), "r"(ncols) : "memory")
#define TC_DEALLOC(tmem, ncols) \
    asm volatile("tcgen05.dealloc.cta_group::1.sync.aligned.b32 %0, %1;" :: "r"(tmem), "r"(ncols))
#define TC_RELINQ() \
    asm volatile("tcgen05.relinquish_alloc_permit.cta_group::1.sync.aligned;")
#define TC_COMMIT(mbar) \
    asm volatile("tcgen05.commit.cta_group::1.mbarrier::arrive::one.shared::cluster.b64 [%0];" \
                 :: "r"(mbar) : "memory")
#define TC_FENCE_AFTER()  asm volatile("tcgen05.fence::after_thread_sync;" ::: "memory")
#define TC_FENCE_BEFORE() asm volatile("tcgen05.fence::before_thread_sync;" ::: "memory")
#define TC_WAIT_LD()      asm volatile("tcgen05.wait::ld.sync.aligned;" ::: "memory")
#define TC_WAIT_ST()      asm volatile("tcgen05.wait::st.sync.aligned;" ::: "memory")
#define FENCE_ASYNC_SHARED() asm volatile("fence.proxy.async.shared::cta;" ::: "memory")

#define TC_LD_X32(r, tmem)                                                     \
    asm volatile(                                                              \
        "tcgen05.ld.sync.aligned.32x32b.x32.b32 "                              \
        "{%0, %1, %2, %3, %4, %5, %6, %7, "                                    \
        " %8, %9, %10, %11, %12, %13, %14, %15, "                              \
        " %16, %17, %18, %19, %20, %21, %22, %23, "                            \
        " %24, %25, %26, %27, %28, %29, %30, %31}, [%32];"                     \
        : "=r"((r)[0]),  "=r"((r)[1]),  "=r"((r)[2]),  "=r"((r)[3]),           \
          "=r"((r)[4]),  "=r"((r)[5]),  "=r"((r)[6]),  "=r"((r)[7]),           \
          "=r"((r)[8]),  "=r"((r)[9]),  "=r"((r)[10]), "=r"((r)[11]),          \
          "=r"((r)[12]), "=r"((r)[13]), "=r"((r)[14]), "=r"((r)[15]),          \
          "=r"((r)[16]), "=r"((r)[17]), "=r"((r)[18]), "=r"((r)[19]),          \
          "=r"((r)[20]), "=r"((r)[21]), "=r"((r)[22]), "=r"((r)[23]),          \
          "=r"((r)[24]), "=r"((r)[25]), "=r"((r)[26]), "=r"((r)[27]),          \
          "=r"((r)[28]), "=r"((r)[29]), "=r"((r)[30]), "=r"((r)[31])           \
        : "r"(tmem))

#define TC_LD_X16(r, tmem)                                                     \
    asm volatile(                                                              \
        "tcgen05.ld.sync.aligned.32x32b.x16.b32 "                              \
        "{%0, %1, %2, %3, %4, %5, %6, %7, "                                    \
        " %8, %9, %10, %11, %12, %13, %14, %15}, [%16];"                       \
        : "=r"((r)[0]),  "=r"((r)[1]),  "=r"((r)[2]),  "=r"((r)[3]),           \
          "=r"((r)[4]),  "=r"((r)[5]),  "=r"((r)[6]),  "=r"((r)[7]),           \
          "=r"((r)[8]),  "=r"((r)[9]),  "=r"((r)[10]), "=r"((r)[11]),          \
          "=r"((r)[12]), "=r"((r)[13]), "=r"((r)[14]), "=r"((r)[15])           \
        : "r"(tmem))

#define TC_ST_X16(tmem, r)                                                     \
    asm volatile(                                                              \
        "tcgen05.st.sync.aligned.32x32b.x16.b32 [%0], "                        \
        "{%1, %2, %3, %4, %5, %6, %7, %8, "                                    \
        " %9, %10, %11, %12, %13, %14, %15, %16};"                             \
        :: "r"(tmem),                                                          \
           "r"((r)[0]),  "r"((r)[1]),  "r"((r)[2]),  "r"((r)[3]),              \
           "r"((r)[4]),  "r"((r)[5]),  "r"((r)[6]),  "r"((r)[7]),              \
           "r"((r)[8]),  "r"((r)[9]),  "r"((r)[10]), "r"((r)[11]),             \
           "r"((r)[12]), "r"((r)[13]), "r"((r)[14]), "r"((r)[15])              \
        : "memory")

__device__ __forceinline__ uint64_t make_desc_sw128(uint32_t addr) {
    return ((uint64_t)2 << 61) | ((uint64_t)1 << 46) | ((uint64_t)64 << 32)
         | ((uint64_t)1 << 16) | (((uint64_t)(addr >> 4)) & 0x3FFF);
}

__device__ __forceinline__ void mma_f16_ss(uint32_t d, uint64_t ad, uint64_t bd,
                                           uint32_t idesc, uint32_t en) {
    asm volatile(
        "{\n\t.reg .pred p;\n\tsetp.ne.u32 p, %4, 0;\n\t"
        "tcgen05.mma.cta_group::1.kind::f16 [%0], %1, %2, %3, p;\n\t}"
        :: "r"(d), "l"(ad), "l"(bd), "r"(idesc), "r"(en) : "memory");
}
__device__ __forceinline__ void mma_f16_ts(uint32_t d, uint32_t a, uint64_t bd,
                                           uint32_t idesc, uint32_t en) {
    asm volatile(
        "{\n\t.reg .pred p;\n\tsetp.ne.u32 p, %4, 0;\n\t"
        "tcgen05.mma.cta_group::1.kind::f16 [%0], [%1], %2, %3, p;\n\t}"
        :: "r"(d), "r"(a), "l"(bd), "r"(idesc), "r"(en) : "memory");
}
__device__ __forceinline__ float ex2f(float x) {
    float r;
    asm("ex2.approx.ftz.f32 %0, %1;" : "=f"(r) : "f"(x));
    return r;
}
__device__ __forceinline__ uint32_t prmt(uint32_t a, uint32_t b, uint32_t sel) {
    uint32_t r;
    asm("prmt.b32 %0, %1, %2, %3;" : "=r"(r) : "r"(a), "r"(b), "r"(sel));
    return r;
}

#define IDESC_G16   ((1u << 4) | (1u << 7) | (1u << 10) | (16u << 17) | (8u << 24))  /* M=128 N=128 */
#define IDESC_PV16  ((1u << 4) | (1u << 7) | (1u << 10) | (8u << 17)  | (8u << 24))  /* M=128 N=64 */

// ============================================================================
// bf16 copy-GEMM: C = A(split) * B(split)^T + bias, tile 128x128, chunk K=64
// ============================================================================
// copy [128 rows][64 bf16] chunk (k0 offset) -> SW128 smem
__device__ __forceinline__ void copy_chunk(const uint16_t* __restrict__ src,
                                           int row0, int k0, uint32_t dst, int t)
{
#pragma unroll
    for (int i = 0; i < 4; i++) {
        int idx = i * 256 + t;
        int r = idx >> 3, c = idx & 7;
        uint4 v = *(const uint4*)&src[(row0 + r) * DM + k0 + c * 8];
        uint32_t off = SW128((uint32_t)(r * 128 + c * 16));
        asm volatile("st.shared.v4.b32 [%0], {%1,%2,%3,%4};" ::
            "r"(dst + off), "r"(v.x), "r"(v.y), "r"(v.z), "r"(v.w) : "memory");
    }
}

__device__ __forceinline__ void gemm16_body(const uint16_t* __restrict__ Ah,
                                            const uint16_t* __restrict__ Al,
                                            const uint16_t* __restrict__ Bh,
                                            const uint16_t* __restrict__ Bl,
                                            const float* __restrict__ bias,
                                            uint16_t* __restrict__ outHi,
                                            uint16_t* __restrict__ outLo,
                                            float* __restrict__ outF,
                                            float scale, int vmode)
{
    extern __shared__ char smraw[];
    const uint32_t base = (smem_u32(smraw) + 1023) & ~1023u;
    const uint32_t mbar0 = base + 8, mbar1 = base + 16;
    const uint32_t tiles = base + 1024;

    const int t   = threadIdx.x;
    const int wid = t >> 5, lid = t & 31;
    const int m0  = blockIdx.y * 128;
    const int n0  = blockIdx.x * 128;

    if (wid == 0) { TC_ALLOC(base, 128); TC_RELINQ(); }
    if (t == 0) { MBAR_INIT(mbar0, 1); MBAR_INIT(mbar1, 1); }
    __syncthreads();
    uint32_t tmem;
    asm volatile("ld.shared.b32 %0, [%1];" : "=r"(tmem) : "r"(base));

    int ph0 = 0, ph1 = 0;

    for (int c = 0; c < NCH16; c++) {
        const int s = c & 1;
        const uint32_t st = tiles + s * STAGE16;
        const uint32_t aHi = st, aLo = st + TILE16;
        const uint32_t bHi = st + 2 * TILE16, bLo = st + 3 * TILE16;

        if (c >= 2) {
            if (s == 0) { MBAR_WAIT(mbar0, ph0); ph0 ^= 1; }
            else        { MBAR_WAIT(mbar1, ph1); ph1 ^= 1; }
        }

        copy_chunk(Ah, m0, c * BKC, aHi, t);
        copy_chunk(Al, m0, c * BKC, aLo, t);
        copy_chunk(Bh, n0, c * BKC, bHi, t);
        copy_chunk(Bl, n0, c * BKC, bLo, t);

        FENCE_ASYNC_SHARED();
        __syncthreads();

        if (wid == 0 && elect_one()) {
            uint64_t dA[2] = { make_desc_sw128(aHi), make_desc_sw128(aLo) };
            uint64_t dB[2] = { make_desc_sw128(bHi), make_desc_sw128(bLo) };
#pragma unroll
            for (int cb = 0; cb < 3; cb++) {
                uint64_t ad = dA[cb == 2 ? 1 : 0];
                uint64_t bd = dB[cb == 1 ? 1 : 0];
#pragma unroll
                for (int ks = 0; ks < 4; ks++) {
                    uint32_t en = !(c == 0 && cb == 0 && ks == 0);
                    mma_f16_ss(tmem, ad + ks * 2, bd + ks * 2, IDESC_G16, en);
                }
            }
            TC_COMMIT(s == 0 ? mbar0 : mbar1);
        }
    }

    MBAR_WAIT(mbar0, ph0);
    MBAR_WAIT(mbar1, ph1);
    TC_FENCE_AFTER();

    // epilogue: 8 warps; warp covers rows (wid&3)*32, cols (wid>>2)*64
    const int colhalf = (wid >> 2) * 64;
    const int mloc = (wid & 3) * 32 + lid;
    const int m = m0 + mloc;
    uint32_t dr[64];
    TC_LD_X32(dr,      tmem + colhalf);
    TC_LD_X32(dr + 32, tmem + colhalf + 32);
    TC_WAIT_LD();
    TC_FENCE_BEFORE();

    if (vmode) {
        // transpose via smem (tiles region dead): padded row stride 130 u16
        uint32_t smh = tiles, sml = tiles + 33280;
#pragma unroll
        for (int c4 = 0; c4 < 16; c4++) {
            int n = n0 + colhalf + c4 * 4;
            float v0 = (__uint_as_float(dr[c4 * 4 + 0]) + bias[n + 0]);
            float v1 = (__uint_as_float(dr[c4 * 4 + 1]) + bias[n + 1]);
            float v2 = (__uint_as_float(dr[c4 * 4 + 2]) + bias[n + 2]);
            float v3 = (__uint_as_float(dr[c4 * 4 + 3]) + bias[n + 3]);
            uint32_t a0 = (uint32_t)(mloc * 130 + colhalf + c4 * 4) * 2;
            asm volatile("st.shared.b32 [%0], %1;" :: "r"(smh + a0),     "r"(bf16x2_of(v0, v1)) : "memory");
            asm volatile("st.shared.b32 [%0], %1;" :: "r"(smh + a0 + 4), "r"(bf16x2_of(v2, v3)) : "memory");
            float l0 = v0 - bf16f(v0), l1 = v1 - bf16f(v1);
            float l2 = v2 - bf16f(v2), l3 = v3 - bf16f(v3);
            asm volatile("st.shared.b32 [%0], %1;" :: "r"(sml + a0),     "r"(bf16x2_of(l0, l1)) : "memory");
            asm volatile("st.shared.b32 [%0], %1;" :: "r"(sml + a0 + 4), "r"(bf16x2_of(l2, l3)) : "memory");
        }
        __syncthreads();
        const int d = t >> 1, half = t & 1;
#pragma unroll
        for (int rg = 0; rg < 8; rg++) {
            int r0 = half * 64 + rg * 8;
            uint32_t w[4], wl[4];
#pragma unroll
            for (int j = 0; j < 4; j++) {
                uint32_t ah, bh, al, bl;
                uint32_t adr0 = (uint32_t)((r0 + 2 * j) * 130 + d) * 2;
                uint32_t adr1 = (uint32_t)((r0 + 2 * j + 1) * 130 + d) * 2;
                asm volatile("ld.shared.u16 %0, [%1];" : "=r"(ah) : "r"(smh + adr0));
                asm volatile("ld.shared.u16 %0, [%1];" : "=r"(bh) : "r"(smh + adr1));
                asm volatile("ld.shared.u16 %0, [%1];" : "=r"(al) : "r"(sml + adr0));
                asm volatile("ld.shared.u16 %0, [%1];" : "=r"(bl) : "r"(sml + adr1));
                w[j]  = ah | (bh << 16);
                wl[j] = al | (bl << 16);
            }
            *(uint4*)&g_vth[(n0 + d) * SEQ + m0 + r0] = make_uint4(w[0], w[1], w[2], w[3]);
            *(uint4*)&g_vtl[(n0 + d) * SEQ + m0 + r0] = make_uint4(wl[0], wl[1], wl[2], wl[3]);
        }
    } else if (outHi) {
#pragma unroll
        for (int c4 = 0; c4 < 16; c4++) {
            int n = n0 + colhalf + c4 * 4;
            float v0 = (__uint_as_float(dr[c4 * 4 + 0]) + bias[n + 0]) * scale;
            float v1 = (__uint_as_float(dr[c4 * 4 + 1]) + bias[n + 1]) * scale;
            float v2 = (__uint_as_float(dr[c4 * 4 + 2]) + bias[n + 2]) * scale;
            float v3 = (__uint_as_float(dr[c4 * 4 + 3]) + bias[n + 3]) * scale;
            uint2 hw, lw;
            hw.x = bf16x2_of(v0, v1);
            hw.y = bf16x2_of(v2, v3);
            lw.x = bf16x2_of(v0 - bf16f(v0), v1 - bf16f(v1));
            lw.y = bf16x2_of(v2 - bf16f(v2), v3 - bf16f(v3));
            *(uint2*)&outHi[m * DM + n] = hw;
            *(uint2*)&outLo[m * DM + n] = lw;
        }
    } else {
#pragma unroll
        for (int c4 = 0; c4 < 16; c4++) {
            int n = n0 + colhalf + c4 * 4;
            float4 o;
            o.x = (__uint_as_float(dr[c4 * 4 + 0]) + bias[n + 0]) * scale;
            o.y = (__uint_as_float(dr[c4 * 4 + 1]) + bias[n + 1]) * scale;
            o.z = (__uint_as_float(dr[c4 * 4 + 2]) + bias[n + 2]) * scale;
            o.w = (__uint_as_float(dr[c4 * 4 + 3]) + bias[n + 3]) * scale;
            *(float4*)&outF[m * DM + n] = o;
        }
    }

    __syncthreads();
    if (wid == 0) TC_DEALLOC(tmem, 128);
}

// ---- attention copy loaders (ATH=512 threads) ----
__device__ __forceinline__ void copy_tile(const uint16_t* __restrict__ src,
                                          int row0, int h, uint32_t dst, int t)
{
#pragma unroll
    for (int i = 0; i < 2; i++) {
        int idx = i * ATH + t;
        int r = idx >> 3, c = idx & 7;
        uint4 v = *(const uint4*)&src[(row0 + r) * DM + h * DK + c * 8];
        uint32_t off = SW128((uint32_t)(r * 128 + c * 16));
        asm volatile("st.shared.v4.b32 [%0], {%1,%2,%3,%4};" ::
            "r"(dst + off), "r"(v.x), "r"(v.y), "r"(v.z), "r"(v.w) : "memory");
    }
}

__device__ __forceinline__ void copy_vt(const uint16_t* __restrict__ src,
                                        int kb, int h, uint32_t dst, int t)
{
#pragma unroll
    for (int i = 0; i < 2; i++) {
        int idx = i * ATH + t;
        int dv = idx >> 4, g = idx & 15;
        uint4 v = *(const uint4*)&src[(h * DK + dv) * SEQ + kb * 128 + g * 8];
        int kc = g >> 3;
        uint32_t off = SW128((uint32_t)(dv * 128 + (g & 7) * 16));
        asm volatile("st.shared.v4.b32 [%0], {%1,%2,%3,%4};" ::
            "r"(dst + kc * 8192 + off), "r"(v.x), "r"(v.y), "r"(v.z), "r"(v.w) : "memory");
    }
}

__device__ __forceinline__ void issue_S(uint32_t tmem, int sCol, uint32_t Qbase, uint32_t Kst)
{
#pragma unroll
    for (int cb = 0; cb < 3; cb++) {
        uint64_t ad = make_desc_sw128(Qbase + (cb == 2 ? 16384u : 0u));
        uint64_t bd = make_desc_sw128(Kst   + (cb == 1 ? 16384u : 0u));
#pragma unroll
        for (int ks = 0; ks < 4; ks++)
            mma_f16_ss(tmem + sCol, ad + ks * 2, bd + ks * 2,
                       IDESC_G16, !(cb == 0 && ks == 0));
    }
}

__device__ __forceinline__ void issue_PV(uint32_t tmem, int oCol, uint32_t Vst, int first)
{
#pragma unroll
    for (int cb = 0; cb < 3; cb++) {
        uint32_t pa = tmem + (cb == 2 ? TM_PL : TM_PH);
        uint32_t vsel = Vst + (cb == 1 ? 16384u : 0u);
#pragma unroll
        for (int kc = 0; kc < 2; kc++) {
            uint64_t bd = make_desc_sw128(vsel + kc * 8192);
#pragma unroll
            for (int ks = 0; ks < 4; ks++) {
                uint32_t en = !(first && cb == 0 && kc == 0 && ks == 0);
                mma_f16_ts(tmem + oCol, pa + kc * 32 + ks * 8, bd + ks * 2,
                           IDESC_PV16, en);
            }
        }
    }
}

__device__ __forceinline__ void exp_compute(uint32_t tmem, int sCol, int wg,
                                            int kb, int qglob,
                                            uint32_t* hr, uint32_t* lr, float& lpart)
{
    uint32_t sr[32];
    TC_LD_X32(sr, tmem + sCol + wg * 32);
    TC_WAIT_LD();
#pragma unroll
    for (int j = 0; j < 16; j++) {
        int key0 = kb * 128 + wg * 32 + 2 * j;
        float p0 = (key0     <= qglob) ? ex2f(__uint_as_float(sr[2*j])   - EXPC) : 0.f;
        float p1 = (key0 + 1 <= qglob) ? ex2f(__uint_as_float(sr[2*j+1]) - EXPC) : 0.f;
        lpart += p0 + p1;
        uint32_t b0 = __float_as_uint(p0), b1 = __float_as_uint(p1);
        hr[j] = prmt(b0, b1, 0x7632);
        float h0 = __uint_as_float(b0 & 0xFFFF0000u);
        float h1 = __uint_as_float(b1 & 0xFFFF0000u);
        lr[j] = bf16x2_of(p0 - h0, p1 - h1);
    }
}
#else  // !HAS_TC fallback GEMM (dead code on GB300)
__device__ __forceinline__ void gemm16_body(const uint16_t* __restrict__ Ah,
                                            const uint16_t* __restrict__ Al,
                                            const uint16_t* __restrict__ Bh,
                                            const uint16_t* __restrict__ Bl,
                                            const float* __restrict__ bias,
                                            uint16_t* __restrict__ outHi,
                                            uint16_t* __restrict__ outLo,
                                            float* __restrict__ outF,
                                            float scale, int vmode)
{
    const int t  = threadIdx.x;
    const int m0 = blockIdx.y * 128;
    const int n0 = blockIdx.x * 128;
    const int tr = (t >> 4) * 8;
    const int tc = (t & 15) * 8;
#pragma unroll 1
    for (int i = 0; i < 8; i++)
        for (int j = 0; j < 8; j++) {
            int mi = m0 + tr + i, ni = n0 + tc + j;
            float acc = 0.f;
            for (int k = 0; k < DM; k++) {
                float av = __bfloat162float(*(__nv_bfloat16*)&Ah[mi * DM + k])
                         + __bfloat162float(*(__nv_bfloat16*)&Al[mi * DM + k]);
                float bv = __bfloat162float(*(__nv_bfloat16*)&Bh[ni * DM + k])
                         + __bfloat162float(*(__nv_bfloat16*)&Bl[ni * DM + k]);
                acc += av * bv;
            }
            float v = (acc + bias[ni]) * scale;
            __nv_bfloat16 hb = __float2bfloat16(v);
            float hv = __bfloat162float(hb);
            __nv_bfloat16 lb = __float2bfloat16(v - hv);
            if (vmode) {
                g_vth[ni * SEQ + mi] = *(uint16_t*)&hb;
                g_vtl[ni * SEQ + mi] = *(uint16_t*)&lb;
            } else if (outHi) {
                outHi[mi * DM + ni] = *(uint16_t*)&hb;
                outLo[mi * DM + ni] = *(uint16_t*)&lb;
            } else {
                outF[mi * DM + ni] = v;
            }
        }
}
#endif  // HAS_TC

__global__ __launch_bounds__(256) void qkv_tc(
    const float* __restrict__ bq, const float* __restrict__ bk,
    const float* __restrict__ bv)
{
    int w = blockIdx.z;
    if (w == 0)
        gemm16_body(g_xh, g_xl, g_wh, g_wl, bq, g_qh, g_ql, 0, QSCALE, 0);
    else if (w == 1)
        gemm16_body(g_xh, g_xl, g_wh + DM * DM, g_wl + DM * DM, bk, g_kh, g_kl, 0, 1.0f, 0);
    else
        gemm16_body(g_xh, g_xl, g_wh + 2 * DM * DM, g_wl + 2 * DM * DM, bv, 0, 0, 0, 1.0f, 1);
}

__global__ __launch_bounds__(256) void out_tc(
    const float* __restrict__ bo, float* __restrict__ out)
{
    gemm16_body(g_ctxh, g_ctxl, g_wh + 3 * DM * DM, g_wl + 3 * DM * DM, bo,
                0, 0, out, 1.0f, 0);
}

// ============================================================================
// tcgen05 flash attention (unchanged from R7 except ctx written as bf16 hi/lo)
// ============================================================================
__global__ __launch_bounds__(ATH) void attn_tc()
{
#if HAS_TC
    extern __shared__ char smraw[];
    __shared__ uint64_t s_bar[3];
    __shared__ uint32_t s_tptr;
    __shared__ float s_lA[ATH], s_lB[ATH];

    const uint32_t base = (smem_u32(smraw) + 1023) & ~1023u;
    const uint32_t QO = base;
    const uint32_t KO = base + 65536;
    const uint32_t VO = base + 131072;
    const uint32_t mbar_s1 = smem_u32(&s_bar[0]);
    const uint32_t mbar_s2 = smem_u32(&s_bar[1]);
    const uint32_t mbar_pv = smem_u32(&s_bar[2]);
    const uint32_t tptr_a  = smem_u32(&s_tptr);

    const int t    = threadIdx.x;
    const int wid  = t >> 5, lane = t & 31;
    const int sub  = wid & 3, wg = wid >> 2;
    const int qbA  = blockIdx.x;
    const int qbB  = (SEQ / 128 - 1) - qbA;
    const int h    = blockIdx.y;
    const int row  = sub * 32 + lane;
    const int qgA  = qbA * 128 + row;
    const int qgB  = qbB * 128 + row;

    if (wid == 0) { TC_ALLOC(tptr_a, 512); TC_RELINQ(); }
    if (t == 0) { MBAR_INIT(mbar_s1, 1); MBAR_INIT(mbar_s2, 1); MBAR_INIT(mbar_pv, 1); }
    __syncthreads();
    uint32_t tmem;
    asm volatile("ld.shared.b32 %0, [%1];" : "=r"(tmem) : "r"(tptr_a));

    copy_tile(g_qh, qbA * 128, h, QO, t);
    copy_tile(g_ql, qbA * 128, h, QO + 16384, t);
    copy_tile(g_qh, qbB * 128, h, QO + 32768, t);
    copy_tile(g_ql, qbB * 128, h, QO + 49152, t);
    copy_tile(g_kh, 0, h, KO, t);
    copy_tile(g_kl, 0, h, KO + 16384, t);
    copy_vt(g_vth, 0, h, VO, t);
    copy_vt(g_vtl, 0, h, VO + 16384, t);
    FENCE_ASYNC_SHARED();

    float lpartA = 0.f, lpartB = 0.f;
    int ph1 = 0, ph2 = 0, php = 0;

    for (int kb = 0; kb <= qbB; kb++) {
        const int s = kb & 1;
        const uint32_t Kst = KO + s * 32768;
        const uint32_t Vst = VO + s * 32768;
        const int dual = (kb <= qbA);

        __syncthreads();

        if (wid == 0 && elect_one()) {
            issue_S(tmem, TM_S1, dual ? QO : QO + 32768, Kst);
            TC_COMMIT(mbar_s1);
            if (dual) {
                issue_S(tmem, TM_S2, QO + 32768, Kst);
                TC_COMMIT(mbar_s2);
            }
        }

        if (kb > 0) { MBAR_WAIT(mbar_pv, php); php ^= 1; }

        if (kb < qbB) {
            const uint32_t Kn = KO + (s ^ 1) * 32768;
            const uint32_t Vn = VO + (s ^ 1) * 32768;
            copy_tile(g_kh, (kb + 1) * 128, h, Kn, t);
            copy_tile(g_kl, (kb + 1) * 128, h, Kn + 16384, t);
            copy_vt(g_vth, kb + 1, h, Vn, t);
            copy_vt(g_vtl, kb + 1, h, Vn + 16384, t);
            FENCE_ASYNC_SHARED();
        }

        MBAR_WAIT(mbar_s1, ph1); ph1 ^= 1;
        TC_FENCE_AFTER();
        {
            uint32_t hr[16], lr[16];
            if (dual) exp_compute(tmem, TM_S1, wg, kb, qgA, hr, lr, lpartA);
            else      exp_compute(tmem, TM_S1, wg, kb, qgB, hr, lr, lpartB);
            TC_ST_X16(tmem + TM_PH + wg * 16 + (sub << 21), hr);
            TC_ST_X16(tmem + TM_PL + wg * 16 + (sub << 21), lr);
            TC_WAIT_ST();
        }
        TC_FENCE_BEFORE();
        __syncthreads();
        if (wid == 0 && elect_one()) {
            TC_FENCE_AFTER();
            issue_PV(tmem, dual ? TM_OA : TM_OB, Vst, kb == 0);
            TC_COMMIT(mbar_pv);
        }

        if (dual) {
            MBAR_WAIT(mbar_s2, ph2); ph2 ^= 1;
            TC_FENCE_AFTER();
            uint32_t hr[16], lr[16];
            exp_compute(tmem, TM_S2, wg, kb, qgB, hr, lr, lpartB);
            MBAR_WAIT(mbar_pv, php); php ^= 1;
            TC_FENCE_AFTER();
            TC_ST_X16(tmem + TM_PH + wg * 16 + (sub << 21), hr);
            TC_ST_X16(tmem + TM_PL + wg * 16 + (sub << 21), lr);
            TC_WAIT_ST();
            TC_FENCE_BEFORE();
            __syncthreads();
            if (wid == 0 && elect_one()) {
                TC_FENCE_AFTER();
                issue_PV(tmem, TM_OB, Vst, kb == 0);
                TC_COMMIT(mbar_pv);
            }
        }
    }

    MBAR_WAIT(mbar_pv, php);
    TC_FENCE_AFTER();

    s_lA[wg * 128 + row] = lpartA;
    s_lB[wg * 128 + row] = lpartB;
    __syncthreads();

    // epilogue: write ctx as bf16 hi/lo
    {
        uint32_t orr[16];
        float invA = 1.f / (s_lA[row] + s_lA[128 + row] + s_lA[256 + row] + s_lA[384 + row]);
        TC_LD_X16(orr, tmem + TM_OA + wg * 16);
        TC_WAIT_LD();
#pragma unroll
        for (int c4 = 0; c4 < 4; c4++) {
            float v0 = __uint_as_float(orr[c4 * 4 + 0]) * invA;
            float v1 = __uint_as_float(orr[c4 * 4 + 1]) * invA;
            float v2 = __uint_as_float(orr[c4 * 4 + 2]) * invA;
            float v3 = __uint_as_float(orr[c4 * 4 + 3]) * invA;
            uint2 hw, lw;
            hw.x = bf16x2_of(v0, v1); hw.y = bf16x2_of(v2, v3);
            lw.x = bf16x2_of(v0 - bf16f(v0), v1 - bf16f(v1));
            lw.y = bf16x2_of(v2 - bf16f(v2), v3 - bf16f(v3));
            int off = (qbA * 128 + row) * DM + h * DK + wg * 16 + c4 * 4;
            *(uint2*)&g_ctxh[off] = hw;
            *(uint2*)&g_ctxl[off] = lw;
        }
        float invB = 1.f / (s_lB[row] + s_lB[128 + row] + s_lB[256 + row] + s_lB[384 + row]);
        TC_LD_X16(orr, tmem + TM_OB + wg * 16);
        TC_WAIT_LD();
#pragma unroll
        for (int c4 = 0; c4 < 4; c4++) {
            float v0 = __uint_as_float(orr[c4 * 4 + 0]) * invB;
            float v1 = __uint_as_float(orr[c4 * 4 + 1]) * invB;
            float v2 = __uint_as_float(orr[c4 * 4 + 2]) * invB;
            float v3 = __uint_as_float(orr[c4 * 4 + 3]) * invB;
            uint2 hw, lw;
            hw.x = bf16x2_of(v0, v1); hw.y = bf16x2_of(v2, v3);
            lw.x = bf16x2_of(v0 - bf16f(v0), v1 - bf16f(v1));
            lw.y = bf16x2_of(v2 - bf16f(v2), v3 - bf16f(v3));
            int off = (qbB * 128 + row) * DM + h * DK + wg * 16 + c4 * 4;
            *(uint2*)&g_ctxh[off] = hw;
            *(uint2*)&g_ctxl[off] = lw;
        }
        TC_FENCE_BEFORE();
    }
    __syncthreads();
    if (wid == 0) TC_DEALLOC(tmem, 512);

#else  // naive fallback (dead code on GB300; correctness only)
    const int t = threadIdx.x;
    const int qbA = blockIdx.x, qbB = (SEQ / 128 - 1) - qbA;
    const int h = blockIdx.y;
    if (t < 256) {
        int row = (t < 128) ? (qbA * 128 + t) : (qbB * 128 + (t - 128));
        float l = 0.f, o[DK];
        for (int d = 0; d < DK; d++) o[d] = 0.f;
        for (int key = 0; key <= row; key++) {
            float s = 0.f;
            for (int d = 0; d < DK; d++) {
                float qv = __bfloat162float(*(__nv_bfloat16*)&g_qh[row * DM + h * DK + d])
                         + __bfloat162float(*(__nv_bfloat16*)&g_ql[row * DM + h * DK + d]);
                float kv = __bfloat162float(*(__nv_bfloat16*)&g_kh[key * DM + h * DK + d])
                         + __bfloat162float(*(__nv_bfloat16*)&g_kl[key * DM + h * DK + d]);
                s += qv * kv;
            }
            float p = exp2f(s - EXPC);
            l += p;
            for (int d = 0; d < DK; d++) {
                float vv = __bfloat162float(*(__nv_bfloat16*)&g_vth[(h * DK + d) * SEQ + key])
                         + __bfloat162float(*(__nv_bfloat16*)&g_vtl[(h * DK + d) * SEQ + key]);
                o[d] += p * vv;
            }
        }
        for (int d = 0; d < DK; d++) {
            float v = o[d] / l;
            __nv_bfloat16 hb = __float2bfloat16(v);
            float hv = __bfloat162float(hb);
            __nv_bfloat16 lb = __float2bfloat16(v - hv);
            g_ctxh[row * DM + h * DK + d] = *(uint16_t*)&hb;
            g_ctxl[row * DM + h * DK + d] = *(uint16_t*)&lb;
        }
    }
#endif
}

// ---------------------------------------------------------------------------
extern "C" void kernel_launch(void* const* d_in, const int* in_sizes, int n_in,
                              void* d_out, int out_size)
{
    const float* x  = (const float*)d_in[0];
    const float* Wq = (const float*)d_in[1];
    const float* bq = (const float*)d_in[2];
    const float* Wk = (const float*)d_in[3];
    const float* bk = (const float*)d_in[4];
    const float* Wv = (const float*)d_in[5];
    const float* bv = (const float*)d_in[6];
    const float* Wo = (const float*)d_in[7];
    const float* bo = (const float*)d_in[8];
    float* out = (float*)d_out;

    cudaFuncSetAttribute(qkv_tc, cudaFuncAttributeMaxDynamicSharedMemorySize, GEMM_SMEM);
    cudaFuncSetAttribute(out_tc, cudaFuncAttributeMaxDynamicSharedMemorySize, GEMM_SMEM);
    cudaFuncSetAttribute(attn_tc, cudaFuncAttributeMaxDynamicSharedMemorySize, ATT_SMEM);

    prep_split<<<(PREP_TOT + 255) / 256, 256>>>(x, Wq, Wk, Wv, Wo);
    qkv_tc<<<dim3(DM / 128, SEQ / 128, 3), 256, GEMM_SMEM>>>(bq, bk, bv);
    attn_tc<<<dim3(SEQ / 256, NH), ATH, ATT_SMEM>>>();
    out_tc<<<dim3(DM / 128, SEQ / 128), 256, GEMM_SMEM>>>(bo, out);
}

// round 10
// speedup vs baseline: 7.9284x; 1.5887x over previous
#include <cuda_runtime.h>
#include <cuda.h>
#include <cuda_bf16.h>
#include <math.h>
#include <stdint.h>

#define SEQ 4096
#define DM  768
#define NH  12
#define DK  64

#if defined(__CUDA_ARCH__) && (__CUDA_ARCH__ == 1030) && defined(__CUDA_ARCH_FEAT_SM103_ALL)
#define HAS_TC 1
#else
#define HAS_TC 0
#endif

// q scaled by 0.125*log2(e); softmax p = 2^(s' - EXPC), EXPC = 16*log2(e)
#define QSCALE 0.18033688011112042f
#define EXPC   23.083120654223414f

// Scratch (allocation-free rule: __device__ globals). 128B-aligned for TMA.
__device__ __align__(128) uint16_t g_xh[SEQ * DM], g_xl[SEQ * DM];
__device__ __align__(128) uint16_t g_wh[4 * DM * DM], g_wl[4 * DM * DM];
__device__ __align__(128) uint16_t g_qh[SEQ * DM], g_ql[SEQ * DM];
__device__ __align__(128) uint16_t g_kh[SEQ * DM], g_kl[SEQ * DM];
__device__ __align__(128) uint16_t g_vth[DM * SEQ], g_vtl[DM * SEQ];
__device__ __align__(128) uint16_t g_ctxh[SEQ * DM], g_ctxl[SEQ * DM];

// ============================================================================
// bf16 GEMM geometry (256 threads, 3-stage TMA pipeline)
// ============================================================================
#define BKC 64
#define NCH16 (DM / BKC)                     /* 12 */
#define TILE16 16384                         /* 128 rows x 128 B */
#define STAGE16 (4 * TILE16)
#define NSTG 3
#define GEMM_SMEM (1024 + 1024 + NSTG * STAGE16)

// Attention smem: slack + Q(2 tiles x 32K) + K(2 stages x 32K) + V(2 stages x 32K)
#define ATT_SMEM (1024 + 3 * 65536)
#define ATH 512
// TMEM columns
#define TM_OA 0
#define TM_OB 64
#define TM_S1 128
#define TM_S2 256
#define TM_PH 384
#define TM_PL 448

// ---------------- common helpers ----------------
__device__ __forceinline__ uint32_t bf16x2_of(float lo, float hi) {
    uint32_t r;
    asm("cvt.rn.bf16x2.f32 %0, %1, %2;" : "=r"(r) : "f"(hi), "f"(lo));
    return r;
}
__device__ __forceinline__ float bf16f(float x) {
    return __bfloat162float(__float2bfloat16(x));
}

// ============================================================================
// Prepass: split x and W into bf16 hi/lo
// ============================================================================
#define X4   (SEQ * DM / 4)
#define W4   (DM * DM / 4)
#define PREP_TOT (X4 + 4 * W4)

__global__ __launch_bounds__(256) void prep_split(
    const float* __restrict__ x,
    const float* __restrict__ Wq, const float* __restrict__ Wk,
    const float* __restrict__ Wv, const float* __restrict__ Wo)
{
    int idx = blockIdx.x * 256 + threadIdx.x;
    if (idx >= PREP_TOT) return;
    const float* src;
    uint16_t *dh, *dl;
    int off;
    if (idx < X4) {
        src = x; dh = g_xh; dl = g_xl; off = idx;
    } else {
        int r = idx - X4;
        int w = r / W4;
        off = r - w * W4;
        src = (w == 0) ? Wq : (w == 1) ? Wk : (w == 2) ? Wv : Wo;
        dh = g_wh + w * (DM * DM);
        dl = g_wl + w * (DM * DM);
    }
    float4 v = *(const float4*)&src[off * 4];
    uint2 hw, lw;
    hw.x = bf16x2_of(v.x, v.y);
    hw.y = bf16x2_of(v.z, v.w);
    lw.x = bf16x2_of(v.x - bf16f(v.x), v.y - bf16f(v.y));
    lw.y = bf16x2_of(v.z - bf16f(v.z), v.w - bf16f(v.w));
    *(uint2*)&dh[off * 4] = hw;
    *(uint2*)&dl[off * 4] = lw;
}

#if HAS_TC
// ============================================================================
// PTX helpers (sm_103a feature target only)
// ============================================================================
__device__ __forceinline__ uint32_t smem_u32(const void* p) {
    uint32_t a;
    asm("{ .reg .u64 t; cvta.to.shared.u64 t, %1; cvt.u32.u64 %0, t; }"
        : "=r"(a) : "l"(p));
    return a;
}
__device__ __forceinline__ uint32_t elect_one() {
    uint32_t p;
    asm volatile("{ .reg .pred p; elect.sync _|p, 0xFFFFFFFF; selp.b32 %0, 1, 0, p; }" : "=r"(p));
    return p;
}
#define SW128(off) ((off) ^ (((off) >> 3) & 0x70))

#define MBAR_INIT(addr, cnt) \
    asm volatile("mbarrier.init.shared.b64 [%0], %1;" :: "r"(addr), "r"(cnt) : "memory")
#define MBAR_EXPECT(addr, bytes) \
    asm volatile("mbarrier.arrive.expect_tx.shared.b64 _, [%0], %1;" :: "r"(addr), "r"(bytes) : "memory")

#define MBAR_WAIT(addr, parity) do {                                           \
    asm volatile(                                                              \
        "{\n\t.reg .pred P1;\n\t"                                              \
        "WL_%=:\n\t"                                                           \
        "mbarrier.try_wait.parity.acquire.cta.shared::cta.b64 P1, [%0], %1, 0x989680;\n\t" \
        "@P1 bra.uni WD_%=;\n\t"                                               \
        "bra.uni WL_%=;\n\t"                                                   \
        "WD_%=:\n\t}"                                                          \
        :: "r"(addr), "r"(parity) : "memory");                                 \
} while (0)

#define TMA2(dst, map, c0, c1, mbar)                                           \
    asm volatile(                                                              \
        "cp.async.bulk.tensor.2d.shared::cta.global.tile.mbarrier::complete_tx::bytes " \
        "[%0], [%1, {%2, %3}], [%4];"                                          \
        :: "r"(dst), "l"(map), "r"(c0), "r"(c1), "r"(mbar) : "memory")

#define TC_ALLOC(smem_addr, ncols) \
    asm volatile("tcgen05.alloc.cta_group::1.sync.aligned.shared::cta.b32 [%0], %1;" \
                 :: "r"(smem_addr), "r"(ncols) : "memory")
#define TC_DEALLOC(tmem, ncols) \
    asm volatile("tcgen05.dealloc.cta_group::1.sync.aligned.b32 %0, %1;" :: "r"(tmem), "r"(ncols))
#define TC_RELINQ() \
    asm volatile("tcgen05.relinquish_alloc_permit.cta_group::1.sync.aligned;")
#define TC_COMMIT(mbar) \
    asm volatile("tcgen05.commit.cta_group::1.mbarrier::arrive::one.shared::cluster.b64 [%0];" \
                 :: "r"(mbar) : "memory")
#define TC_FENCE_AFTER()  asm volatile("tcgen05.fence::after_thread_sync;" ::: "memory")
#define TC_FENCE_BEFORE() asm volatile("tcgen05.fence::before_thread_sync;" ::: "memory")
#define TC_WAIT_LD()      asm volatile("tcgen05.wait::ld.sync.aligned;" ::: "memory")
#define TC_WAIT_ST()      asm volatile("tcgen05.wait::st.sync.aligned;" ::: "memory")
#define FENCE_ASYNC_SHARED() asm volatile("fence.proxy.async.shared::cta;" ::: "memory")

#define TC_LD_X32(r, tmem)                                                     \
    asm volatile(                                                              \
        "tcgen05.ld.sync.aligned.32x32b.x32.b32 "                              \
        "{%0, %1, %2, %3, %4, %5, %6, %7, "                                    \
        " %8, %9, %10, %11, %12, %13, %14, %15, "                              \
        " %16, %17, %18, %19, %20, %21, %22, %23, "                            \
        " %24, %25, %26, %27, %28, %29, %30, %31}, [%32];"                     \
        : "=r"((r)[0]),  "=r"((r)[1]),  "=r"((r)[2]),  "=r"((r)[3]),           \
          "=r"((r)[4]),  "=r"((r)[5]),  "=r"((r)[6]),  "=r"((r)[7]),           \
          "=r"((r)[8]),  "=r"((r)[9]),  "=r"((r)[10]), "=r"((r)[11]),          \
          "=r"((r)[12]), "=r"((r)[13]), "=r"((r)[14]), "=r"((r)[15]),          \
          "=r"((r)[16]), "=r"((r)[17]), "=r"((r)[18]), "=r"((r)[19]),          \
          "=r"((r)[20]), "=r"((r)[21]), "=r"((r)[22]), "=r"((r)[23]),          \
          "=r"((r)[24]), "=r"((r)[25]), "=r"((r)[26]), "=r"((r)[27]),          \
          "=r"((r)[28]), "=r"((r)[29]), "=r"((r)[30]), "=r"((r)[31])           \
        : "r"(tmem))

#define TC_LD_X16(r, tmem)                                                     \
    asm volatile(                                                              \
        "tcgen05.ld.sync.aligned.32x32b.x16.b32 "                              \
        "{%0, %1, %2, %3, %4, %5, %6, %7, "                                    \
        " %8, %9, %10, %11, %12, %13, %14, %15}, [%16];"                       \
        : "=r"((r)[0]),  "=r"((r)[1]),  "=r"((r)[2]),  "=r"((r)[3]),           \
          "=r"((r)[4]),  "=r"((r)[5]),  "=r"((r)[6]),  "=r"((r)[7]),           \
          "=r"((r)[8]),  "=r"((r)[9]),  "=r"((r)[10]), "=r"((r)[11]),          \
          "=r"((r)[12]), "=r"((r)[13]), "=r"((r)[14]), "=r"((r)[15])           \
        : "r"(tmem))

#define TC_ST_X16(tmem, r)                                                     \
    asm volatile(                                                              \
        "tcgen05.st.sync.aligned.32x32b.x16.b32 [%0], "                        \
        "{%1, %2, %3, %4, %5, %6, %7, %8, "                                    \
        " %9, %10, %11, %12, %13, %14, %15, %16};"                             \
        :: "r"(tmem),                                                          \
           "r"((r)[0]),  "r"((r)[1]),  "r"((r)[2]),  "r"((r)[3]),              \
           "r"((r)[4]),  "r"((r)[5]),  "r"((r)[6]),  "r"((r)[7]),              \
           "r"((r)[8]),  "r"((r)[9]),  "r"((r)[10]), "r"((r)[11]),             \
           "r"((r)[12]), "r"((r)[13]), "r"((r)[14]), "r"((r)[15])              \
        : "memory")

__device__ __forceinline__ uint64_t make_desc_sw128(uint32_t addr) {
    return ((uint64_t)2 << 61) | ((uint64_t)1 << 46) | ((uint64_t)64 << 32)
         | ((uint64_t)1 << 16) | (((uint64_t)(addr >> 4)) & 0x3FFF);
}

__device__ __forceinline__ void mma_f16_ss(uint32_t d, uint64_t ad, uint64_t bd,
                                           uint32_t idesc, uint32_t en) {
    asm volatile(
        "{\n\t.reg .pred p;\n\tsetp.ne.u32 p, %4, 0;\n\t"
        "tcgen05.mma.cta_group::1.kind::f16 [%0], %1, %2, %3, p;\n\t}"
        :: "r"(d), "l"(ad), "l"(bd), "r"(idesc), "r"(en) : "memory");
}
__device__ __forceinline__ void mma_f16_ts(uint32_t d, uint32_t a, uint64_t bd,
                                           uint32_t idesc, uint32_t en) {
    asm volatile(
        "{\n\t.reg .pred p;\n\tsetp.ne.u32 p, %4, 0;\n\t"
        "tcgen05.mma.cta_group::1.kind::f16 [%0], [%1], %2, %3, p;\n\t}"
        :: "r"(d), "r"(a), "l"(bd), "r"(idesc), "r"(en) : "memory");
}
__device__ __forceinline__ float ex2f(float x) {
    float r;
    asm("ex2.approx.ftz.f32 %0, %1;" : "=f"(r) : "f"(x));
    return r;
}
__device__ __forceinline__ uint32_t prmt(uint32_t a, uint32_t b, uint32_t sel) {
    uint32_t r;
    asm("prmt.b32 %0, %1, %2, %3;" : "=r"(r) : "r"(a), "r"(b), "r"(sel));
    return r;
}

#define IDESC_G16   ((1u << 4) | (1u << 7) | (1u << 10) | (16u << 17) | (8u << 24))
#define IDESC_PV16  ((1u << 4) | (1u << 7) | (1u << 10) | (8u << 17)  | (8u << 24))

// ============================================================================
// bf16 TMA GEMM: C = A(split) * B(split)^T + bias, 128x128 tile, 3-stage
// ============================================================================
__device__ __forceinline__ void gemm16_tma(
    const CUtensorMap* mAh, const CUtensorMap* mAl,
    const CUtensorMap* mBh, const CUtensorMap* mBl,
    int brow_base,
    const float* __restrict__ bias,
    uint16_t* __restrict__ outHi, uint16_t* __restrict__ outLo,
    float* __restrict__ outF, float scale, int vmode)
{
    extern __shared__ char smraw[];
    const uint32_t base  = (smem_u32(smraw) + 1023) & ~1023u;
    const uint32_t tiles = base + 1024;
    // base+0: tmem ptr; full[s] = base+8+8s; done[s] = base+32+8s; alldone = base+56

    const int t   = threadIdx.x;
    const int wid = t >> 5, lid = t & 31;
    const int m0  = blockIdx.y * 128;
    const int n0  = blockIdx.x * 128;

    if (wid == 0) { TC_ALLOC(base, 128); TC_RELINQ(); }
    if (t == 0) {
#pragma unroll
        for (int i = 0; i < 7; i++) MBAR_INIT(base + 8 + 8 * i, 1);
    }
    __syncthreads();
    uint32_t tmem;
    asm volatile("ld.shared.b32 %0, [%1];" : "=r"(tmem) : "r"(base));

    if (t == 64) {                       // producer
        int pd[NSTG] = {0, 0, 0};
        for (int c = 0; c < NCH16; c++) {
            int s = c % NSTG;
            if (c >= NSTG) { MBAR_WAIT(base + 32 + 8 * s, pd[s]); pd[s] ^= 1; }
            uint32_t full = base + 8 + 8 * s;
            MBAR_EXPECT(full, 4 * TILE16);
            uint32_t st = tiles + s * STAGE16;
            TMA2(st,              mAh, c * BKC, m0, full);
            TMA2(st + TILE16,     mAl, c * BKC, m0, full);
            TMA2(st + 2 * TILE16, mBh, c * BKC, brow_base + n0, full);
            TMA2(st + 3 * TILE16, mBl, c * BKC, brow_base + n0, full);
        }
    }
    if (wid == 0 && elect_one()) {       // MMA issuer
        int pf[NSTG] = {0, 0, 0};
        for (int c = 0; c < NCH16; c++) {
            int s = c % NSTG;
            MBAR_WAIT(base + 8 + 8 * s, pf[s]); pf[s] ^= 1;
            uint32_t st = tiles + s * STAGE16;
            uint64_t dA[2] = { make_desc_sw128(st),             make_desc_sw128(st + TILE16) };
            uint64_t dB[2] = { make_desc_sw128(st + 2 * TILE16), make_desc_sw128(st + 3 * TILE16) };
#pragma unroll
            for (int cb = 0; cb < 3; cb++) {
                uint64_t ad = dA[cb == 2 ? 1 : 0];
                uint64_t bd = dB[cb == 1 ? 1 : 0];
#pragma unroll
                for (int ks = 0; ks < 4; ks++) {
                    uint32_t en = !(c == 0 && cb == 0 && ks == 0);
                    mma_f16_ss(tmem, ad + ks * 2, bd + ks * 2, IDESC_G16, en);
                }
            }
            if (c <= NCH16 - 1 - NSTG) TC_COMMIT(base + 32 + 8 * s);
        }
        TC_COMMIT(base + 56);
    }

    MBAR_WAIT(base + 56, 0);
    TC_FENCE_AFTER();

    // epilogue: 8 warps; warp covers rows (wid&3)*32, cols (wid>>2)*64
    const int colhalf = (wid >> 2) * 64;
    const int mloc = (wid & 3) * 32 + lid;
    const int m = m0 + mloc;
    uint32_t dr[64];
    TC_LD_X32(dr,      tmem + colhalf);
    TC_LD_X32(dr + 32, tmem + colhalf + 32);
    TC_WAIT_LD();
    TC_FENCE_BEFORE();

    if (vmode) {
        uint32_t smh = tiles, sml = tiles + 33280;
#pragma unroll
        for (int c4 = 0; c4 < 16; c4++) {
            int n = n0 + colhalf + c4 * 4;
            float v0 = (__uint_as_float(dr[c4 * 4 + 0]) + bias[n + 0]);
            float v1 = (__uint_as_float(dr[c4 * 4 + 1]) + bias[n + 1]);
            float v2 = (__uint_as_float(dr[c4 * 4 + 2]) + bias[n + 2]);
            float v3 = (__uint_as_float(dr[c4 * 4 + 3]) + bias[n + 3]);
            uint32_t a0 = (uint32_t)(mloc * 130 + colhalf + c4 * 4) * 2;
            asm volatile("st.shared.b32 [%0], %1;" :: "r"(smh + a0),     "r"(bf16x2_of(v0, v1)) : "memory");
            asm volatile("st.shared.b32 [%0], %1;" :: "r"(smh + a0 + 4), "r"(bf16x2_of(v2, v3)) : "memory");
            float l0 = v0 - bf16f(v0), l1 = v1 - bf16f(v1);
            float l2 = v2 - bf16f(v2), l3 = v3 - bf16f(v3);
            asm volatile("st.shared.b32 [%0], %1;" :: "r"(sml + a0),     "r"(bf16x2_of(l0, l1)) : "memory");
            asm volatile("st.shared.b32 [%0], %1;" :: "r"(sml + a0 + 4), "r"(bf16x2_of(l2, l3)) : "memory");
        }
        __syncthreads();
        const int d = t >> 1, half = t & 1;
#pragma unroll
        for (int rg = 0; rg < 8; rg++) {
            int r0 = half * 64 + rg * 8;
            uint32_t w[4], wl[4];
#pragma unroll
            for (int j = 0; j < 4; j++) {
                uint32_t ah, bh, al, bl;
                uint32_t adr0 = (uint32_t)((r0 + 2 * j) * 130 + d) * 2;
                uint32_t adr1 = (uint32_t)((r0 + 2 * j + 1) * 130 + d) * 2;
                asm volatile("ld.shared.u16 %0, [%1];" : "=r"(ah) : "r"(smh + adr0));
                asm volatile("ld.shared.u16 %0, [%1];" : "=r"(bh) : "r"(smh + adr1));
                asm volatile("ld.shared.u16 %0, [%1];" : "=r"(al) : "r"(sml + adr0));
                asm volatile("ld.shared.u16 %0, [%1];" : "=r"(bl) : "r"(sml + adr1));
                w[j]  = ah | (bh << 16);
                wl[j] = al | (bl << 16);
            }
            *(uint4*)&g_vth[(n0 + d) * SEQ + m0 + r0] = make_uint4(w[0], w[1], w[2], w[3]);
            *(uint4*)&g_vtl[(n0 + d) * SEQ + m0 + r0] = make_uint4(wl[0], wl[1], wl[2], wl[3]);
        }
    } else if (outHi) {
#pragma unroll
        for (int c4 = 0; c4 < 16; c4++) {
            int n = n0 + colhalf + c4 * 4;
            float v0 = (__uint_as_float(dr[c4 * 4 + 0]) + bias[n + 0]) * scale;
            float v1 = (__uint_as_float(dr[c4 * 4 + 1]) + bias[n + 1]) * scale;
            float v2 = (__uint_as_float(dr[c4 * 4 + 2]) + bias[n + 2]) * scale;
            float v3 = (__uint_as_float(dr[c4 * 4 + 3]) + bias[n + 3]) * scale;
            uint2 hw, lw;
            hw.x = bf16x2_of(v0, v1);
            hw.y = bf16x2_of(v2, v3);
            lw.x = bf16x2_of(v0 - bf16f(v0), v1 - bf16f(v1));
            lw.y = bf16x2_of(v2 - bf16f(v2), v3 - bf16f(v3));
            *(uint2*)&outHi[m * DM + n] = hw;
            *(uint2*)&outLo[m * DM + n] = lw;
        }
    } else {
#pragma unroll
        for (int c4 = 0; c4 < 16; c4++) {
            int n = n0 + colhalf + c4 * 4;
            float4 o;
            o.x = (__uint_as_float(dr[c4 * 4 + 0]) + bias[n + 0]) * scale;
            o.y = (__uint_as_float(dr[c4 * 4 + 1]) + bias[n + 1]) * scale;
            o.z = (__uint_as_float(dr[c4 * 4 + 2]) + bias[n + 2]) * scale;
            o.w = (__uint_as_float(dr[c4 * 4 + 3]) + bias[n + 3]) * scale;
            *(float4*)&outF[m * DM + n] = o;
        }
    }

    __syncthreads();
    if (wid == 0) TC_DEALLOC(tmem, 128);
}

// ---- attention helpers ----
__device__ __forceinline__ void copy_tile(const uint16_t* __restrict__ src,
                                          int row0, int h, uint32_t dst, int t)
{
#pragma unroll
    for (int i = 0; i < 2; i++) {
        int idx = i * ATH + t;
        int r = idx >> 3, c = idx & 7;
        uint4 v = *(const uint4*)&src[(row0 + r) * DM + h * DK + c * 8];
        uint32_t off = SW128((uint32_t)(r * 128 + c * 16));
        asm volatile("st.shared.v4.b32 [%0], {%1,%2,%3,%4};" ::
            "r"(dst + off), "r"(v.x), "r"(v.y), "r"(v.z), "r"(v.w) : "memory");
    }
}

__device__ __forceinline__ void issue_S(uint32_t tmem, int sCol, uint32_t Qbase, uint32_t Kst)
{
#pragma unroll
    for (int cb = 0; cb < 3; cb++) {
        uint64_t ad = make_desc_sw128(Qbase + (cb == 2 ? 16384u : 0u));
        uint64_t bd = make_desc_sw128(Kst   + (cb == 1 ? 16384u : 0u));
#pragma unroll
        for (int ks = 0; ks < 4; ks++)
            mma_f16_ss(tmem + sCol, ad + ks * 2, bd + ks * 2,
                       IDESC_G16, !(cb == 0 && ks == 0));
    }
}

__device__ __forceinline__ void issue_PV(uint32_t tmem, int oCol, uint32_t Vst, int first)
{
#pragma unroll
    for (int cb = 0; cb < 3; cb++) {
        uint32_t pa = tmem + (cb == 2 ? TM_PL : TM_PH);
        uint32_t vsel = Vst + (cb == 1 ? 16384u : 0u);
#pragma unroll
        for (int kc = 0; kc < 2; kc++) {
            uint64_t bd = make_desc_sw128(vsel + kc * 8192);
#pragma unroll
            for (int ks = 0; ks < 4; ks++) {
                uint32_t en = !(first && cb == 0 && kc == 0 && ks == 0);
                mma_f16_ts(tmem + oCol, pa + kc * 32 + ks * 8, bd + ks * 2,
                           IDESC_PV16, en);
            }
        }
    }
}

__device__ __forceinline__ void exp_compute(uint32_t tmem, int sCol, int wg,
                                            int kb, int qglob,
                                            uint32_t* hr, uint32_t* lr, float& lpart)
{
    uint32_t sr[32];
    TC_LD_X32(sr, tmem + sCol + wg * 32);
    TC_WAIT_LD();
#pragma unroll
    for (int j = 0; j < 16; j++) {
        int key0 = kb * 128 + wg * 32 + 2 * j;
        float p0 = (key0     <= qglob) ? ex2f(__uint_as_float(sr[2*j])   - EXPC) : 0.f;
        float p1 = (key0 + 1 <= qglob) ? ex2f(__uint_as_float(sr[2*j+1]) - EXPC) : 0.f;
        lpart += p0 + p1;
        uint32_t b0 = __float_as_uint(p0), b1 = __float_as_uint(p1);
        hr[j] = prmt(b0, b1, 0x7632);
        float h0 = __uint_as_float(b0 & 0xFFFF0000u);
        float h1 = __uint_as_float(b1 & 0xFFFF0000u);
        lr[j] = bf16x2_of(p0 - h0, p1 - h1);
    }
}
#endif  // HAS_TC

// ============================================================================
// GEMM kernels
// ============================================================================
__global__ __launch_bounds__(256) void qkv_tc(
    const __grid_constant__ CUtensorMap mxh, const __grid_constant__ CUtensorMap mxl,
    const __grid_constant__ CUtensorMap mwh, const __grid_constant__ CUtensorMap mwl,
    const float* __restrict__ bq, const float* __restrict__ bk,
    const float* __restrict__ bv)
{
#if HAS_TC
    int w = blockIdx.z;
    if (w == 0)
        gemm16_tma(&mxh, &mxl, &mwh, &mwl, 0, bq, g_qh, g_ql, 0, QSCALE, 0);
    else if (w == 1)
        gemm16_tma(&mxh, &mxl, &mwh, &mwl, DM, bk, g_kh, g_kl, 0, 1.0f, 0);
    else
        gemm16_tma(&mxh, &mxl, &mwh, &mwl, 2 * DM, bv, 0, 0, 0, 1.0f, 1);
#else
    // fallback: naive bf16 GEMM from globals
    const int t = threadIdx.x;
    const int m0 = blockIdx.y * 128, n0 = blockIdx.x * 128;
    int w = blockIdx.z;
    const float* bias = (w == 0) ? bq : (w == 1) ? bk : bv;
    const uint16_t* Bh = g_wh + w * DM * DM;
    const uint16_t* Bl = g_wl + w * DM * DM;
    float scale = (w == 0) ? QSCALE : 1.0f;
    const int tr = (t >> 4) * 8, tc = (t & 15) * 8;
    for (int i = 0; i < 8; i++)
        for (int j = 0; j < 8; j++) {
            int mi = m0 + tr + i, ni = n0 + tc + j;
            float acc = 0.f;
            for (int k = 0; k < DM; k++) {
                float av = __bfloat162float(*(__nv_bfloat16*)&g_xh[mi * DM + k])
                         + __bfloat162float(*(__nv_bfloat16*)&g_xl[mi * DM + k]);
                float bvv = __bfloat162float(*(__nv_bfloat16*)&Bh[ni * DM + k])
                          + __bfloat162float(*(__nv_bfloat16*)&Bl[ni * DM + k]);
                acc += av * bvv;
            }
            float v = (acc + bias[ni]) * scale;
            __nv_bfloat16 hb = __float2bfloat16(v);
            float hv = __bfloat162float(hb);
            __nv_bfloat16 lb = __float2bfloat16(v - hv);
            if (w == 2) {
                g_vth[ni * SEQ + mi] = *(uint16_t*)&hb;
                g_vtl[ni * SEQ + mi] = *(uint16_t*)&lb;
            } else if (w == 0) {
                g_qh[mi * DM + ni] = *(uint16_t*)&hb;
                g_ql[mi * DM + ni] = *(uint16_t*)&lb;
            } else {
                g_kh[mi * DM + ni] = *(uint16_t*)&hb;
                g_kl[mi * DM + ni] = *(uint16_t*)&lb;
            }
        }
#endif
}

__global__ __launch_bounds__(256) void out_tc(
    const __grid_constant__ CUtensorMap mch, const __grid_constant__ CUtensorMap mcl,
    const __grid_constant__ CUtensorMap mwh, const __grid_constant__ CUtensorMap mwl,
    const float* __restrict__ bo, float* __restrict__ out)
{
#if HAS_TC
    gemm16_tma(&mch, &mcl, &mwh, &mwl, 3 * DM, bo, 0, 0, out, 1.0f, 0);
#else
    const int t = threadIdx.x;
    const int m0 = blockIdx.y * 128, n0 = blockIdx.x * 128;
    const uint16_t* Bh = g_wh + 3 * DM * DM;
    const uint16_t* Bl = g_wl + 3 * DM * DM;
    const int tr = (t >> 4) * 8, tc = (t & 15) * 8;
    for (int i = 0; i < 8; i++)
        for (int j = 0; j < 8; j++) {
            int mi = m0 + tr + i, ni = n0 + tc + j;
            float acc = 0.f;
            for (int k = 0; k < DM; k++) {
                float av = __bfloat162float(*(__nv_bfloat16*)&g_ctxh[mi * DM + k])
                         + __bfloat162float(*(__nv_bfloat16*)&g_ctxl[mi * DM + k]);
                float bvv = __bfloat162float(*(__nv_bfloat16*)&Bh[ni * DM + k])
                          + __bfloat162float(*(__nv_bfloat16*)&Bl[ni * DM + k]);
                acc += av * bvv;
            }
            out[mi * DM + ni] = acc + bo[ni];
        }
#endif
}

// ============================================================================
// tcgen05 flash attention: TMA K/V stages, paired q-tiles, S double-buffered
// ============================================================================
__global__ __launch_bounds__(ATH) void attn_tc(
    const __grid_constant__ CUtensorMap mkh, const __grid_constant__ CUtensorMap mkl,
    const __grid_constant__ CUtensorMap mvh, const __grid_constant__ CUtensorMap mvl)
{
#if HAS_TC
    extern __shared__ char smraw[];
    __shared__ uint64_t s_bar[5];      // s1, s2, pv, kv0, kv1
    __shared__ uint32_t s_tptr;
    __shared__ float s_lA[ATH], s_lB[ATH];

    const uint32_t base = (smem_u32(smraw) + 1023) & ~1023u;
    const uint32_t QO = base;
    const uint32_t KO = base + 65536;
    const uint32_t VO = base + 131072;
    const uint32_t mbar_s1 = smem_u32(&s_bar[0]);
    const uint32_t mbar_s2 = smem_u32(&s_bar[1]);
    const uint32_t mbar_pv = smem_u32(&s_bar[2]);
    const uint32_t kvb0    = smem_u32(&s_bar[3]);
    const uint32_t kvb1    = smem_u32(&s_bar[4]);
    const uint32_t tptr_a  = smem_u32(&s_tptr);

    const int t    = threadIdx.x;
    const int wid  = t >> 5, lane = t & 31;
    const int sub  = wid & 3, wg = wid >> 2;
    const int qbA  = blockIdx.x;
    const int qbB  = (SEQ / 128 - 1) - qbA;
    const int h    = blockIdx.y;
    const int row  = sub * 32 + lane;
    const int qgA  = qbA * 128 + row;
    const int qgB  = qbB * 128 + row;

    if (wid == 0) { TC_ALLOC(tptr_a, 512); TC_RELINQ(); }
    if (t == 0) {
        MBAR_INIT(mbar_s1, 1); MBAR_INIT(mbar_s2, 1); MBAR_INIT(mbar_pv, 1);
        MBAR_INIT(kvb0, 1); MBAR_INIT(kvb1, 1);
    }
    __syncthreads();
    uint32_t tmem;
    asm volatile("ld.shared.b32 %0, [%1];" : "=r"(tmem) : "r"(tptr_a));

    // Q preload (SIMT); K/V stage 0 via TMA
    copy_tile(g_qh, qbA * 128, h, QO, t);
    copy_tile(g_ql, qbA * 128, h, QO + 16384, t);
    copy_tile(g_qh, qbB * 128, h, QO + 32768, t);
    copy_tile(g_ql, qbB * 128, h, QO + 49152, t);
    FENCE_ASYNC_SHARED();
    if (t == 0) {
        MBAR_EXPECT(kvb0, 65536);
        TMA2(KO,           &mkh, h * DK, 0, kvb0);
        TMA2(KO + 16384,   &mkl, h * DK, 0, kvb0);
        TMA2(VO,           &mvh, 0,  h * DK, kvb0);
        TMA2(VO + 8192,    &mvh, 64, h * DK, kvb0);
        TMA2(VO + 16384,   &mvl, 0,  h * DK, kvb0);
        TMA2(VO + 24576,   &mvl, 64, h * DK, kvb0);
    }

    float lpartA = 0.f, lpartB = 0.f;
    int ph1 = 0, ph2 = 0, php = 0;
    int pkv0 = 0, pkv1 = 0;

    for (int kb = 0; kb <= qbB; kb++) {
        const int s = kb & 1;
        const uint32_t Kst = KO + s * 32768;
        const uint32_t Vst = VO + s * 32768;
        const int dual = (kb <= qbA);

        __syncthreads();   // TMEM S1/S2 free (prior exp LDTMs done); Q visible (kb=0)

        if (wid == 0 && elect_one()) {
            if (s == 0) { MBAR_WAIT(kvb0, pkv0); pkv0 ^= 1; }
            else        { MBAR_WAIT(kvb1, pkv1); pkv1 ^= 1; }
            issue_S(tmem, TM_S1, dual ? QO : QO + 32768, Kst);
            TC_COMMIT(mbar_s1);
            if (dual) {
                issue_S(tmem, TM_S2, QO + 32768, Kst);
                TC_COMMIT(mbar_s2);
            }
        }

        if (kb > 0) { MBAR_WAIT(mbar_pv, php); php ^= 1; }

        // prefetch next K/V stage via TMA (stage s^1 free: PV(kb-1) done)
        if (kb < qbB && t == 0) {
            const int sn = s ^ 1;
            const uint32_t Kn = KO + sn * 32768;
            const uint32_t Vn = VO + sn * 32768;
            const uint32_t kvb = sn == 0 ? kvb0 : kvb1;
            const int kr = (kb + 1) * 128;
            MBAR_EXPECT(kvb, 65536);
            TMA2(Kn,          &mkh, h * DK, kr, kvb);
            TMA2(Kn + 16384,  &mkl, h * DK, kr, kvb);
            TMA2(Vn,          &mvh, kr,      h * DK, kvb);
            TMA2(Vn + 8192,   &mvh, kr + 64, h * DK, kvb);
            TMA2(Vn + 16384,  &mvl, kr,      h * DK, kvb);
            TMA2(Vn + 24576,  &mvl, kr + 64, h * DK, kvb);
        }

        MBAR_WAIT(mbar_s1, ph1); ph1 ^= 1;
        TC_FENCE_AFTER();
        {
            uint32_t hr[16], lr[16];
            if (dual) exp_compute(tmem, TM_S1, wg, kb, qgA, hr, lr, lpartA);
            else      exp_compute(tmem, TM_S1, wg, kb, qgB, hr, lr, lpartB);
            TC_ST_X16(tmem + TM_PH + wg * 16 + (sub << 21), hr);
            TC_ST_X16(tmem + TM_PL + wg * 16 + (sub << 21), lr);
            TC_WAIT_ST();
        }
        TC_FENCE_BEFORE();
        __syncthreads();
        if (wid == 0 && elect_one()) {
            TC_FENCE_AFTER();
            issue_PV(tmem, dual ? TM_OA : TM_OB, Vst, kb == 0);
            TC_COMMIT(mbar_pv);
        }

        if (dual) {
            MBAR_WAIT(mbar_s2, ph2); ph2 ^= 1;
            TC_FENCE_AFTER();
            uint32_t hr[16], lr[16];
            exp_compute(tmem, TM_S2, wg, kb, qgB, hr, lr, lpartB);
            MBAR_WAIT(mbar_pv, php); php ^= 1;
            TC_FENCE_AFTER();
            TC_ST_X16(tmem + TM_PH + wg * 16 + (sub << 21), hr);
            TC_ST_X16(tmem + TM_PL + wg * 16 + (sub << 21), lr);
            TC_WAIT_ST();
            TC_FENCE_BEFORE();
            __syncthreads();
            if (wid == 0 && elect_one()) {
                TC_FENCE_AFTER();
                issue_PV(tmem, TM_OB, Vst, kb == 0);
                TC_COMMIT(mbar_pv);
            }
        }
    }

    MBAR_WAIT(mbar_pv, php);
    TC_FENCE_AFTER();

    s_lA[wg * 128 + row] = lpartA;
    s_lB[wg * 128 + row] = lpartB;
    __syncthreads();

    {
        uint32_t orr[16];
        float invA = 1.f / (s_lA[row] + s_lA[128 + row] + s_lA[256 + row] + s_lA[384 + row]);
        TC_LD_X16(orr, tmem + TM_OA + wg * 16);
        TC_WAIT_LD();
#pragma unroll
        for (int c4 = 0; c4 < 4; c4++) {
            float v0 = __uint_as_float(orr[c4 * 4 + 0]) * invA;
            float v1 = __uint_as_float(orr[c4 * 4 + 1]) * invA;
            float v2 = __uint_as_float(orr[c4 * 4 + 2]) * invA;
            float v3 = __uint_as_float(orr[c4 * 4 + 3]) * invA;
            uint2 hw, lw;
            hw.x = bf16x2_of(v0, v1); hw.y = bf16x2_of(v2, v3);
            lw.x = bf16x2_of(v0 - bf16f(v0), v1 - bf16f(v1));
            lw.y = bf16x2_of(v2 - bf16f(v2), v3 - bf16f(v3));
            int off = (qbA * 128 + row) * DM + h * DK + wg * 16 + c4 * 4;
            *(uint2*)&g_ctxh[off] = hw;
            *(uint2*)&g_ctxl[off] = lw;
        }
        float invB = 1.f / (s_lB[row] + s_lB[128 + row] + s_lB[256 + row] + s_lB[384 + row]);
        TC_LD_X16(orr, tmem + TM_OB + wg * 16);
        TC_WAIT_LD();
#pragma unroll
        for (int c4 = 0; c4 < 4; c4++) {
            float v0 = __uint_as_float(orr[c4 * 4 + 0]) * invB;
            float v1 = __uint_as_float(orr[c4 * 4 + 1]) * invB;
            float v2 = __uint_as_float(orr[c4 * 4 + 2]) * invB;
            float v3 = __uint_as_float(orr[c4 * 4 + 3]) * invB;
            uint2 hw, lw;
            hw.x = bf16x2_of(v0, v1); hw.y = bf16x2_of(v2, v3);
            lw.x = bf16x2_of(v0 - bf16f(v0), v1 - bf16f(v1));
            lw.y = bf16x2_of(v2 - bf16f(v2), v3 - bf16f(v3));
            int off = (qbB * 128 + row) * DM + h * DK + wg * 16 + c4 * 4;
            *(uint2*)&g_ctxh[off] = hw;
            *(uint2*)&g_ctxl[off] = lw;
        }
        TC_FENCE_BEFORE();
    }
    __syncthreads();
    if (wid == 0) TC_DEALLOC(tmem, 512);

#else  // naive fallback (dead code on GB300)
    const int t = threadIdx.x;
    const int qbA = blockIdx.x, qbB = (SEQ / 128 - 1) - qbA;
    const int h = blockIdx.y;
    if (t < 256) {
        int row = (t < 128) ? (qbA * 128 + t) : (qbB * 128 + (t - 128));
        float l = 0.f, o[DK];
        for (int d = 0; d < DK; d++) o[d] = 0.f;
        for (int key = 0; key <= row; key++) {
            float s = 0.f;
            for (int d = 0; d < DK; d++) {
                float qv = __bfloat162float(*(__nv_bfloat16*)&g_qh[row * DM + h * DK + d])
                         + __bfloat162float(*(__nv_bfloat16*)&g_ql[row * DM + h * DK + d]);
                float kv = __bfloat162float(*(__nv_bfloat16*)&g_kh[key * DM + h * DK + d])
                         + __bfloat162float(*(__nv_bfloat16*)&g_kl[key * DM + h * DK + d]);
                s += qv * kv;
            }
            float p = exp2f(s - EXPC);
            l += p;
            for (int d = 0; d < DK; d++) {
                float vv = __bfloat162float(*(__nv_bfloat16*)&g_vth[(h * DK + d) * SEQ + key])
                         + __bfloat162float(*(__nv_bfloat16*)&g_vtl[(h * DK + d) * SEQ + key]);
                o[d] += p * vv;
            }
        }
        for (int d = 0; d < DK; d++) {
            float v = o[d] / l;
            __nv_bfloat16 hb = __float2bfloat16(v);
            float hv = __bfloat162float(hb);
            __nv_bfloat16 lb = __float2bfloat16(v - hv);
            g_ctxh[row * DM + h * DK + d] = *(uint16_t*)&hb;
            g_ctxl[row * DM + h * DK + d] = *(uint16_t*)&lb;
        }
    }
#endif
}

// ============================================================================
// Host side
// ============================================================================
typedef CUresult (*TMEncFn)(CUtensorMap*, CUtensorMapDataType, cuuint32_t, void*,
                            const cuuint64_t*, const cuuint64_t*, const cuuint32_t*,
                            const cuuint32_t*, CUtensorMapInterleave, CUtensorMapSwizzle,
                            CUtensorMapL2promotion, CUtensorMapFloatOOBfill);

static void make2d(TMEncFn enc, CUtensorMap* m, void* ptr,
                   uint64_t d0, uint64_t d1, uint32_t b0, uint32_t b1)
{
    cuuint64_t dims[2] = {d0, d1};
    cuuint64_t strides[1] = {d0 * 2};
    cuuint32_t box[2] = {b0, b1};
    cuuint32_t es[2] = {1, 1};
    enc(m, CU_TENSOR_MAP_DATA_TYPE_UINT16, 2, ptr, dims, strides, box, es,
        CU_TENSOR_MAP_INTERLEAVE_NONE, CU_TENSOR_MAP_SWIZZLE_128B,
        CU_TENSOR_MAP_L2_PROMOTION_L2_128B, CU_TENSOR_MAP_FLOAT_OOB_FILL_NONE);
}

extern "C" void kernel_launch(void* const* d_in, const int* in_sizes, int n_in,
                              void* d_out, int out_size)
{
    const float* x  = (const float*)d_in[0];
    const float* Wq = (const float*)d_in[1];
    const float* bq = (const float*)d_in[2];
    const float* Wk = (const float*)d_in[3];
    const float* bk = (const float*)d_in[4];
    const float* Wv = (const float*)d_in[5];
    const float* bv = (const float*)d_in[6];
    const float* Wo = (const float*)d_in[7];
    const float* bo = (const float*)d_in[8];
    float* out = (float*)d_out;

    void* encp = 0;
    cudaDriverEntryPointQueryResult qres;
    cudaGetDriverEntryPoint("cuTensorMapEncodeTiled", &encp, cudaEnableDefault, &qres);
    TMEncFn enc = (TMEncFn)encp;

    void *pxh, *pxl, *pwh, *pwl, *pkh, *pkl, *pvh, *pvl, *pch, *pcl;
    cudaGetSymbolAddress(&pxh, g_xh);  cudaGetSymbolAddress(&pxl, g_xl);
    cudaGetSymbolAddress(&pwh, g_wh);  cudaGetSymbolAddress(&pwl, g_wl);
    cudaGetSymbolAddress(&pkh, g_kh);  cudaGetSymbolAddress(&pkl, g_kl);
    cudaGetSymbolAddress(&pvh, g_vth); cudaGetSymbolAddress(&pvl, g_vtl);
    cudaGetSymbolAddress(&pch, g_ctxh); cudaGetSymbolAddress(&pcl, g_ctxl);

    CUtensorMap mxh, mxl, mwh, mwl, mkh, mkl, mvh, mvl, mch, mcl;
    make2d(enc, &mxh, pxh, DM, SEQ, 64, 128);
    make2d(enc, &mxl, pxl, DM, SEQ, 64, 128);
    make2d(enc, &mwh, pwh, DM, 4 * DM, 64, 128);
    make2d(enc, &mwl, pwl, DM, 4 * DM, 64, 128);
    make2d(enc, &mkh, pkh, DM, SEQ, 64, 128);
    make2d(enc, &mkl, pkl, DM, SEQ, 64, 128);
    make2d(enc, &mvh, pvh, SEQ, DM, 64, 64);
    make2d(enc, &mvl, pvl, SEQ, DM, 64, 64);
    make2d(enc, &mch, pch, DM, SEQ, 64, 128);
    make2d(enc, &mcl, pcl, DM, SEQ, 64, 128);

    cudaFuncSetAttribute(qkv_tc, cudaFuncAttributeMaxDynamicSharedMemorySize, GEMM_SMEM);
    cudaFuncSetAttribute(out_tc, cudaFuncAttributeMaxDynamicSharedMemorySize, GEMM_SMEM);
    cudaFuncSetAttribute(attn_tc, cudaFuncAttributeMaxDynamicSharedMemorySize, ATT_SMEM);

    prep_split<<<(PREP_TOT + 255) / 256, 256>>>(x, Wq, Wk, Wv, Wo);
    qkv_tc<<<dim3(DM / 128, SEQ / 128, 3), 256, GEMM_SMEM>>>(mxh, mxl, mwh, mwl, bq, bk, bv);
    attn_tc<<<dim3(SEQ / 256, NH), ATH, ATT_SMEM>>>(mkh, mkl, mvh, mvl);
    out_tc<<<dim3(DM / 128, SEQ / 128), 256, GEMM_SMEM>>>(mch, mcl, mwh, mwl, bo, out);
}